// round 11
// baseline (speedup 1.0000x reference)
#include <cuda_runtime.h>
#include <cuda_bf16.h>
#include <math.h>
#include <stdint.h>

#define NN 4096
#define CC 512
#define HH 128
#define KTOP 3

#define NEG_INF (__int_as_float(0xff800000))

// ---------------- static scratch ----------------
__device__ float g_big[(size_t)NN * NN];
__device__ float g_nc[(size_t)NN * CC];
__device__ float g_hidden1[CC * HH];
__device__ float g_hiddenB[CC * HH];
__device__ float g_tmp[NN * HH];
__device__ float g_tmp2[NN * HH];
__device__ float g_h[NN * HH];
__device__ float g_hidden2[NN * HH];
__device__ float g_colsum[CC];
__device__ float g_valid1[CC];
__device__ float g_normx[NN];
__device__ float g_normB[CC];
__device__ float g_normh[NN];
__device__ float g_diag[NN];
__device__ float g_norm2[NN];
__device__ float g_valid2[NN];
__device__ float g_colsum2[NN];
__device__ float g_cval[(size_t)NN * 128 * 3];
__device__ int   g_cidx[(size_t)NN * 128 * 3];

__device__ __nv_bfloat16 g_xA3[(size_t)NN * 3 * HH];
__device__ __nv_bfloat16 g_xB3[(size_t)NN * 3 * HH];
__device__ __nv_bfloat16 g_hA3[(size_t)NN * 3 * HH];
__device__ __nv_bfloat16 g_hB3[(size_t)NN * 3 * HH];
__device__ __nv_bfloat16 g_h1A3[(size_t)CC * 3 * HH];
__device__ __nv_bfloat16 g_hBB3[(size_t)CC * 3 * HH];
__device__ __nv_bfloat16 g_hBT3[(size_t)HH * 3 * CC];
__device__ __nv_bfloat16 g_h2B3[(size_t)NN * 3 * HH];
__device__ __nv_bfloat16 g_h2T3[(size_t)HH * 3 * NN];
__device__ __nv_bfloat16 g_c2sA3[(size_t)NN * 3 * CC];
__device__ __nv_bfloat16 g_probsA3[(size_t)NN * 3 * NN];   // aliased as pT_A3 [CC,3NN]
__device__ __nv_bfloat16 g_cmT2[(size_t)CC * 2 * NN];
__device__ __nv_bfloat16 g_xvT2[(size_t)HH * 2 * NN];
__device__ __nv_bfloat16 g_xT3[(size_t)HH * 3 * NN];

enum { EP_NONE = 0, EP_COS = 3, EP_ATOM = 6, EP_TOP3 = 7 };

struct EpiParams {
    int mode;
    const float* normA;
    const float* normB;
    const float* validf;
    float* cval;
    int* cidx;
};

__device__ __forceinline__ void ins3(float v, int j, float& b0, float& b1, float& b2,
                                     int& j0, int& j1, int& j2) {
    if (v > b0) { b2 = b1; j2 = j1; b1 = b0; j1 = j0; b0 = v; j0 = j; }
    else if (v > b1) { b2 = b1; j2 = j1; b1 = v; j1 = j; }
    else if (v > b2) { b2 = v; j2 = j; }
}

// ---------------- mma.sync bf16 GEMM (4 warps, 64x64 warp tile, 3-stage) ----------------
#define SMEM_ROW 80
#define STAGE_BYTES (128 * SMEM_ROW)
#define MMA_SMEM (3 * 2 * STAGE_BYTES)

__device__ __forceinline__ void mma16816(float* c, const uint32_t* a, const uint32_t* b) {
    asm volatile(
        "mma.sync.aligned.m16n8k16.row.col.f32.bf16.bf16.f32 "
        "{%0,%1,%2,%3}, {%4,%5,%6,%7}, {%8,%9}, {%0,%1,%2,%3};"
        : "+f"(c[0]), "+f"(c[1]), "+f"(c[2]), "+f"(c[3])
        : "r"(a[0]), "r"(a[1]), "r"(a[2]), "r"(a[3]), "r"(b[0]), "r"(b[1]));
}

__device__ __forceinline__ void cp_async16(uint32_t smem_addr, const void* gptr) {
    asm volatile("cp.async.cg.shared.global [%0], [%1], 16;" :: "r"(smem_addr), "l"(gptr));
}

__device__ __forceinline__ void ldmatrix_x4(uint32_t* r, uint32_t addr) {
    asm volatile("ldmatrix.sync.aligned.m8n8.x4.shared.b16 {%0,%1,%2,%3}, [%4];"
                 : "=r"(r[0]), "=r"(r[1]), "=r"(r[2]), "=r"(r[3]) : "r"(addr));
}

__global__ void __launch_bounds__(128)
mma_gemm(const __nv_bfloat16* __restrict__ A, const __nv_bfloat16* __restrict__ B,
         float* __restrict__ C, int M, int Nn, int Ktot, int kchunk, EpiParams ep) {
    extern __shared__ __align__(16) char smem_[];

    const int tid = threadIdx.x;
    const int lane = tid & 31;
    const int wid = tid >> 5;                 // 0..3
    const int warp_m = (wid >> 1) * 64;
    const int warp_n = (wid & 1) * 64;
    const int m0 = blockIdx.y * 128;
    const int n0 = blockIdx.x * 128;
    const int kbase = blockIdx.z * kchunk;
    const int niter = kchunk >> 5;            // BK = 32 bf16 = 64B

    const char* Ag = (const char*)(A + (size_t)m0 * Ktot + kbase);
    const char* Bg = (const char*)(B + (size_t)n0 * Ktot + kbase);
    const size_t rowb = (size_t)Ktot * 2;

    uint32_t sb = (uint32_t)__cvta_generic_to_shared(smem_);

    float acc[4][8][4];
#pragma unroll
    for (int i = 0; i < 4; i++)
#pragma unroll
        for (int j = 0; j < 8; j++)
#pragma unroll
            for (int q = 0; q < 4; q++) acc[i][j][q] = 0.0f;

    const int lj = lane >> 3;
    const int lr = lane & 7;
    const uint32_t a_row_off = (uint32_t)(warp_m + (lj & 1) * 8 + lr) * SMEM_ROW +
                               (uint32_t)(lj >> 1) * 16;
    const uint32_t b_row_off = (uint32_t)(warp_n + (lj >> 1) * 8 + lr) * SMEM_ROW +
                               (uint32_t)(lj & 1) * 16;

#define LOAD_TILE(s, it) do { \
    uint32_t sA = sb + (uint32_t)(s) * (2 * STAGE_BYTES); \
    uint32_t sB = sA + STAGE_BYTES; \
    size_t gk = (size_t)(it) * 64; \
    _Pragma("unroll") \
    for (int l = 0; l < 4; l++) { \
        int id = tid + l * 128; \
        int row = id >> 2, cc = id & 3; \
        uint32_t so = (uint32_t)row * SMEM_ROW + (uint32_t)cc * 16; \
        size_t go = (size_t)row * rowb + gk + (size_t)cc * 16; \
        cp_async16(sA + so, Ag + go); \
        cp_async16(sB + so, Bg + go); \
    } \
    asm volatile("cp.async.commit_group;"); \
} while (0)

    LOAD_TILE(0, 0);
    if (niter > 1) LOAD_TILE(1, 1);

    for (int it = 0; it < niter; it++) {
        int s = it % 3;
        if (it + 1 < niter) asm volatile("cp.async.wait_group 1;");
        else asm volatile("cp.async.wait_group 0;");
        __syncthreads();

        uint32_t abase = sb + (uint32_t)s * (2 * STAGE_BYTES) + a_row_off;
        uint32_t bbase = sb + (uint32_t)s * (2 * STAGE_BYTES) + STAGE_BYTES + b_row_off;
#pragma unroll
        for (int ks = 0; ks < 32; ks += 16) {
            uint32_t a[4][4], b[8][2];
#pragma unroll
            for (int mi = 0; mi < 4; mi++)
                ldmatrix_x4(a[mi], abase + mi * 16 * SMEM_ROW + ks * 2);
#pragma unroll
            for (int p = 0; p < 4; p++) {
                uint32_t t[4];
                ldmatrix_x4(t, bbase + p * 16 * SMEM_ROW + ks * 2);
                b[p * 2][0] = t[0]; b[p * 2][1] = t[1];
                b[p * 2 + 1][0] = t[2]; b[p * 2 + 1][1] = t[3];
            }
#pragma unroll
            for (int mi = 0; mi < 4; mi++)
#pragma unroll
                for (int ni = 0; ni < 8; ni++) mma16816(acc[mi][ni], a[mi], b[ni]);
        }
        if (it + 2 < niter) LOAD_TILE((it + 2) % 3, it + 2);
    }

    if (ep.mode == EP_TOP3) {
#pragma unroll
        for (int mi = 0; mi < 4; mi++) {
#pragma unroll
            for (int half = 0; half < 2; half++) {
                int m = m0 + warp_m + mi * 16 + (lane >> 2) + half * 8;
                float na = ep.normA[m];
#pragma unroll
                for (int cpart = 0; cpart < 2; cpart++) {
                    float b0 = NEG_INF, b1 = NEG_INF, b2 = NEG_INF;
                    int j0 = 0, j1 = 0, j2 = 0;
#pragma unroll
                    for (int nq = 0; nq < 4; nq++) {
                        int ni = cpart * 4 + nq;
#pragma unroll
                        for (int q = 0; q < 2; q++) {
                            int c = n0 + warp_n + ni * 8 + (lane & 3) * 2 + q;
                            float v = acc[mi][ni][half * 2 + q];
                            float den = na * ep.normB[c];
                            v = v / (den == 0.0f ? 1.0f : den);
                            if (c == m) v = NEG_INF;
                            ins3(v, c, b0, b1, b2, j0, j1, j2);
                        }
                    }
#pragma unroll
                    for (int msk = 1; msk <= 2; msk <<= 1) {
                        float o0 = __shfl_xor_sync(0xffffffff, b0, msk);
                        int p0 = __shfl_xor_sync(0xffffffff, j0, msk);
                        float o1 = __shfl_xor_sync(0xffffffff, b1, msk);
                        int p1 = __shfl_xor_sync(0xffffffff, j1, msk);
                        float o2 = __shfl_xor_sync(0xffffffff, b2, msk);
                        int p2 = __shfl_xor_sync(0xffffffff, j2, msk);
                        ins3(o0, p0, b0, b1, b2, j0, j1, j2);
                        ins3(o1, p1, b0, b1, b2, j0, j1, j2);
                        ins3(o2, p2, b0, b1, b2, j0, j1, j2);
                    }
                    if ((lane & 3) == 0) {
                        int chunk = blockIdx.x * 4 + (warp_n >> 5) + cpart;
                        size_t off = ((size_t)m * 128 + chunk) * 3;
                        ep.cval[off] = b0; ep.cval[off + 1] = b1; ep.cval[off + 2] = b2;
                        ep.cidx[off] = j0; ep.cidx[off + 1] = j1; ep.cidx[off + 2] = j2;
                    }
                }
            }
        }
        return;
    }

#pragma unroll
    for (int mi = 0; mi < 4; mi++) {
        int r0 = m0 + warp_m + mi * 16 + (lane >> 2);
#pragma unroll
        for (int ni = 0; ni < 8; ni++) {
            int c = n0 + warp_n + ni * 8 + (lane & 3) * 2;
#pragma unroll
            for (int half = 0; half < 2; half++) {
                int m = r0 + half * 8;
                float v0 = acc[mi][ni][half * 2];
                float v1 = acc[mi][ni][half * 2 + 1];
                size_t o = (size_t)m * Nn + c;
                if (ep.mode == EP_COS) {
                    float na = ep.normA[m];
                    float d0 = na * ep.normB[c];
                    float d1 = na * ep.normB[c + 1];
                    v0 = v0 / (d0 == 0.0f ? 1.0f : d0);
                    v1 = v1 / (d1 == 0.0f ? 1.0f : d1);
                    if (ep.validf) {
                        if (ep.validf[c] == 0.0f) v0 = NEG_INF;
                        if (ep.validf[c + 1] == 0.0f) v1 = NEG_INF;
                    }
                    *(float2*)&C[o] = make_float2(v0, v1);
                } else if (ep.mode == EP_ATOM) {
                    atomicAdd(&C[o], v0);
                    atomicAdd(&C[o + 1], v1);
                } else {
                    *(float2*)&C[o] = make_float2(v0, v1);
                }
            }
        }
    }
}

// ---------------- transpose kernels ----------------
__global__ void transpose_split3_kernel(const float* __restrict__ X,
                                        __nv_bfloat16* __restrict__ Y, int K) {
    __shared__ float tile[32][33];
    int k0 = blockIdx.x * 32, h0 = blockIdx.y * 32;
    int tx = threadIdx.x, ty = threadIdx.y;
    for (int r = ty; r < 32; r += 8)
        tile[r][tx] = X[(size_t)(k0 + r) * HH + h0 + tx];
    __syncthreads();
    for (int r = ty; r < 32; r += 8) {
        int hcol = h0 + r;
        int k = k0 + tx;
        float v = tile[tx][r];
        __nv_bfloat16 h = __float2bfloat16(v);
        __nv_bfloat16 l = __float2bfloat16(v - __bfloat162float(h));
        size_t base = (size_t)hcol * 3 * K + k;
        Y[base] = h;
        Y[base + K] = l;
        Y[base + 2 * K] = h;
    }
}

// x -> xT3 ([h,l,h]) AND xvT2 (mv-weighted, [h,l]) in one pass
__global__ void xT_kernel(const float* __restrict__ X, const float* __restrict__ mv,
                          __nv_bfloat16* __restrict__ T3, __nv_bfloat16* __restrict__ V2) {
    __shared__ float tile[32][33];
    int k0 = blockIdx.x * 32, h0 = blockIdx.y * 32;
    int tx = threadIdx.x, ty = threadIdx.y;
    for (int r = ty; r < 32; r += 8)
        tile[r][tx] = X[(size_t)(k0 + r) * HH + h0 + tx];
    __syncthreads();
    float mvk = mv[k0 + tx];
    for (int r = ty; r < 32; r += 8) {
        int hcol = h0 + r;
        int k = k0 + tx;
        float v = tile[tx][r];
        __nv_bfloat16 h = __float2bfloat16(v);
        __nv_bfloat16 l = __float2bfloat16(v - __bfloat162float(h));
        size_t base = (size_t)hcol * 3 * NN + k;
        T3[base] = h;
        T3[base + NN] = l;
        T3[base + 2 * NN] = h;
        float w = v * mvk;
        __nv_bfloat16 hw = __float2bfloat16(w);
        __nv_bfloat16 lw = __float2bfloat16(w - __bfloat162float(hw));
        size_t base2 = (size_t)hcol * 2 * NN + k;
        V2[base2] = hw;
        V2[base2 + NN] = lw;
    }
}

// cm transpose (duplicated bf16, exact) + column sums (mv-weighted) fused
__global__ void cm_transpose_kernel(const float* __restrict__ cm, const float* __restrict__ mv,
                                    __nv_bfloat16* __restrict__ Y, float* __restrict__ colsum) {
    __shared__ float tile[32][33];
    int k0 = blockIdx.x * 32, c0 = blockIdx.y * 32;
    int tx = threadIdx.x, ty = threadIdx.y;
    for (int r = ty; r < 32; r += 8)
        tile[r][tx] = cm[(size_t)(k0 + r) * CC + c0 + tx];
    __syncthreads();
    float mvk = mv[k0 + tx];
    for (int r = ty; r < 32; r += 8) {
        int c = c0 + r;
        int k = k0 + tx;
        float fv = tile[tx][r];
        __nv_bfloat16 v = __float2bfloat16(fv);
        size_t base = (size_t)c * 2 * NN + k;
        Y[base] = v;
        Y[base + NN] = v;
        float s = fv * mvk;
#pragma unroll
        for (int o = 16; o > 0; o >>= 1) s += __shfl_xor_sync(0xffffffffu, s, o);
        if (tx == 0) atomicAdd(&colsum[c], s);
    }
}

// ---------------- fused tail kernels ----------------
__device__ __forceinline__ void stage_mm(const float* __restrict__ As,
                                         const float* __restrict__ W, float* Ws,
                                         int tid, float acc[2][8]) {
    const int tx = tid & 15, ty = tid >> 4;
#pragma unroll
    for (int i = 0; i < 2; i++)
#pragma unroll
        for (int j = 0; j < 8; j++) acc[i][j] = 0.0f;
    for (int kc = 0; kc < 128; kc += 32) {
        __syncthreads();
#pragma unroll
        for (int l = 0; l < 16; l++) {
            int id = tid + l * 256;
            int n = id >> 5, k = id & 31;
            Ws[k * 132 + n] = W[n * 128 + kc + k];
        }
        __syncthreads();
#pragma unroll
        for (int k = 0; k < 32; k++) {
            float a0 = As[(ty * 2) * 132 + kc + k];
            float a1 = As[(ty * 2 + 1) * 132 + kc + k];
            const float* wr = &Ws[k * 132 + tx * 8];
            float4 w0 = *(const float4*)wr;
            float4 w1 = *(const float4*)(wr + 4);
            float wv[8] = {w0.x, w0.y, w0.z, w0.w, w1.x, w1.y, w1.z, w1.w};
#pragma unroll
            for (int j = 0; j < 8; j++) {
                acc[0][j] = fmaf(a0, wv[j], acc[0][j]);
                acc[1][j] = fmaf(a1, wv[j], acc[1][j]);
            }
        }
    }
}

__global__ void __launch_bounds__(256) ps_tail_kernel(
    const float* __restrict__ tmp, const float* __restrict__ x,
    const float* __restrict__ W1, const float* __restrict__ b1,
    const float* __restrict__ W2, const float* __restrict__ b2,
    const float* __restrict__ W3, const float* __restrict__ b3,
    const float* __restrict__ Wout, float* __restrict__ h, float* __restrict__ y) {
    extern __shared__ float sm[];
    float* As = sm;
    float* Ps = sm + 32 * 132;
    float* Ws = sm + 2 * 32 * 132;
    int tid = threadIdx.x;
    int m0 = blockIdx.x * 32;
    const int tx = tid & 15, ty = tid >> 4;
#pragma unroll
    for (int l = 0; l < 4; l++) {
        int id = tid + l * 256;
        int m = id >> 5, c4 = id & 31;
        *(float4*)&As[m * 132 + c4 * 4] = *(const float4*)&tmp[(size_t)(m0 + m) * 128 + c4 * 4];
    }
    float acc[2][8];
    stage_mm(As, W1, Ws, tid, acc);
#pragma unroll
    for (int i = 0; i < 2; i++)
#pragma unroll
        for (int j = 0; j < 8; j++)
            Ps[(ty * 2 + i) * 132 + tx * 8 + j] = acc[i][j] + b1[tx * 8 + j];
    stage_mm(Ps, W2, Ws, tid, acc);
#pragma unroll
    for (int i = 0; i < 2; i++) {
        int m = m0 + ty * 2 + i;
#pragma unroll
        for (int j = 0; j < 8; j++) {
            int n = tx * 8 + j;
            h[(size_t)m * 128 + n] = x[(size_t)m * 128 + n] - (acc[i][j] + b2[n]);
        }
    }
    stage_mm(Ps, W3, Ws, tid, acc);
    float d0 = 0.0f, d1 = 0.0f;
#pragma unroll
    for (int j = 0; j < 8; j++) {
        int n = tx * 8 + j;
        float z0 = acc[0][j] + b3[n]; z0 = z0 > 0.0f ? z0 : 0.01f * z0;
        float z1 = acc[1][j] + b3[n]; z1 = z1 > 0.0f ? z1 : 0.01f * z1;
        d0 = fmaf(z0, Wout[n], d0);
        d1 = fmaf(z1, Wout[n], d1);
    }
#pragma unroll
    for (int o = 1; o < 16; o <<= 1) {
        d0 += __shfl_xor_sync(0xffffffff, d0, o);
        d1 += __shfl_xor_sync(0xffffffff, d1, o);
    }
    if (tx == 0) {
        atomicAdd(&y[m0 + ty * 2], d0);
        atomicAdd(&y[m0 + ty * 2 + 1], d1);
    }
}

__global__ void __launch_bounds__(256) hs_tail_kernel(
    const float* __restrict__ tmp2, const float* __restrict__ h,
    const float* __restrict__ W1, const float* __restrict__ b1,
    const float* __restrict__ W2, const float* __restrict__ b2,
    const float* __restrict__ W3, const float* __restrict__ b3,
    const float* __restrict__ W4, const float* __restrict__ b4,
    const float* __restrict__ Wout, float* __restrict__ y) {
    extern __shared__ float sm[];
    float* As = sm;
    float* Hs = sm + 32 * 132;
    float* Is = sm + 2 * 32 * 132;
    float* Ws = sm + 3 * 32 * 132;
    int tid = threadIdx.x;
    int m0 = blockIdx.x * 32;
    const int tx = tid & 15, ty = tid >> 4;
#pragma unroll
    for (int l = 0; l < 4; l++) {
        int id = tid + l * 256;
        int m = id >> 5, c4 = id & 31;
        *(float4*)&As[m * 132 + c4 * 4] = *(const float4*)&tmp2[(size_t)(m0 + m) * 128 + c4 * 4];
    }
    float acc[2][8];
    stage_mm(As, W1, Ws, tid, acc);
#pragma unroll
    for (int i = 0; i < 2; i++)
#pragma unroll
        for (int j = 0; j < 8; j++)
            Hs[(ty * 2 + i) * 132 + tx * 8 + j] = acc[i][j] + b1[tx * 8 + j];
    stage_mm(Hs, W2, Ws, tid, acc);
#pragma unroll
    for (int i = 0; i < 2; i++) {
        int m = m0 + ty * 2 + i;
#pragma unroll
        for (int j = 0; j < 8; j++) {
            int n = tx * 8 + j;
            Is[(ty * 2 + i) * 132 + n] = h[(size_t)m * 128 + n] - (acc[i][j] + b2[n]);
        }
    }
    float d0 = 0.0f, d1 = 0.0f;
    stage_mm(Hs, W3, Ws, tid, acc);
#pragma unroll
    for (int j = 0; j < 8; j++) {
        int n = tx * 8 + j;
        float z0 = acc[0][j] + b3[n]; z0 = z0 > 0.0f ? z0 : 0.01f * z0;
        float z1 = acc[1][j] + b3[n]; z1 = z1 > 0.0f ? z1 : 0.01f * z1;
        d0 = fmaf(z0, Wout[n], d0);
        d1 = fmaf(z1, Wout[n], d1);
    }
    stage_mm(Is, W4, Ws, tid, acc);
#pragma unroll
    for (int j = 0; j < 8; j++) {
        int n = tx * 8 + j;
        float z0 = acc[0][j] + b4[n]; z0 = z0 > 0.0f ? z0 : 0.01f * z0;
        float z1 = acc[1][j] + b4[n]; z1 = z1 > 0.0f ? z1 : 0.01f * z1;
        d0 = fmaf(z0, Wout[n], d0);
        d1 = fmaf(z1, Wout[n], d1);
    }
#pragma unroll
    for (int o = 1; o < 16; o <<= 1) {
        d0 += __shfl_xor_sync(0xffffffff, d0, o);
        d1 += __shfl_xor_sync(0xffffffff, d1, o);
    }
    if (tx == 0) {
        atomicAdd(&y[m0 + ty * 2], d0);
        atomicAdd(&y[m0 + ty * 2 + 1], d1);
    }
}

// ---------------- fused small kernels ----------------
__global__ void zero_all_kernel(float* h2, float* h1, float* hB, float* cs, float* cs2,
                                float* tmp, float* tmp2, float* y, const float* bout) {
    int i = blockIdx.x * blockDim.x + threadIdx.x;
    h2[i] = 0.0f;
    tmp[i] = 0.0f;
    tmp2[i] = 0.0f;
    if (i < CC * HH) { h1[i] = 0.0f; hB[i] = 0.0f; }
    if (i < CC) cs[i] = 0.0f;
    if (i < NN) { cs2[i] = 0.0f; y[i] = bout[0]; }
}

__global__ void xprep_kernel(const float* __restrict__ X, float* __restrict__ norm,
                             __nv_bfloat16* __restrict__ A3, __nv_bfloat16* __restrict__ B3) {
    int m = blockIdx.x, t = threadIdx.x;
    float v = X[(size_t)m * HH + t];
    __shared__ float sh[128];
    sh[t] = v * v;
    __syncthreads();
    for (int o = 64; o > 0; o >>= 1) {
        if (t < o) sh[t] += sh[t + o];
        __syncthreads();
    }
    if (t == 0) norm[m] = sqrtf(sh[0]);
    __nv_bfloat16 h = __float2bfloat16(v);
    __nv_bfloat16 l = __float2bfloat16(v - __bfloat162float(h));
    size_t base = (size_t)m * 3 * HH + t;
    A3[base] = h; A3[base + HH] = h; A3[base + 2 * HH] = l;
    B3[base] = h; B3[base + HH] = l; B3[base + 2 * HH] = h;
}

__global__ void hidden1post_kernel(float* __restrict__ X, const float* __restrict__ colsum,
                                   float* __restrict__ validf, __nv_bfloat16* __restrict__ A3) {
    int m = blockIdx.x, t = threadIdx.x;
    float sc = 1.0f / (colsum[m] + 1.0f);
    float v = X[(size_t)m * HH + t] * sc;
    X[(size_t)m * HH + t] = v;
    __shared__ float sh[128];
    sh[t] = v;
    __syncthreads();
    for (int o = 64; o > 0; o >>= 1) {
        if (t < o) sh[t] += sh[t + o];
        __syncthreads();
    }
    if (t == 0) validf[m] = (sh[0] != 0.0f) ? 1.0f : 0.0f;
    __nv_bfloat16 h = __float2bfloat16(v);
    __nv_bfloat16 l = __float2bfloat16(v - __bfloat162float(h));
    size_t base = (size_t)m * 3 * HH + t;
    A3[base] = h; A3[base + HH] = h; A3[base + 2 * HH] = l;
}

__global__ void hiddenBpost_kernel(float* __restrict__ X, const float* __restrict__ validf,
                                   float* __restrict__ norm, __nv_bfloat16* __restrict__ B3) {
    int m = blockIdx.x, t = threadIdx.x;
    float v = X[(size_t)m * HH + t] * validf[m];
    X[(size_t)m * HH + t] = v;
    __shared__ float sh[128];
    sh[t] = v * v;
    __syncthreads();
    for (int o = 64; o > 0; o >>= 1) {
        if (t < o) sh[t] += sh[t + o];
        __syncthreads();
    }
    if (t == 0) norm[m] = sqrtf(sh[0]);
    __nv_bfloat16 h = __float2bfloat16(v);
    __nv_bfloat16 l = __float2bfloat16(v - __bfloat162float(h));
    size_t base = (size_t)m * 3 * HH + t;
    B3[base] = h; B3[base + HH] = l; B3[base + 2 * HH] = h;
}

__global__ void hpost_kernel(const float* __restrict__ X, float* __restrict__ norm,
                             float* __restrict__ diag, __nv_bfloat16* __restrict__ A3,
                             __nv_bfloat16* __restrict__ B3) {
    int m = blockIdx.x, t = threadIdx.x;
    float v = X[(size_t)m * HH + t];
    __shared__ float sh[128];
    sh[t] = v * v;
    __syncthreads();
    for (int o = 64; o > 0; o >>= 1) {
        if (t < o) sh[t] += sh[t + o];
        __syncthreads();
    }
    if (t == 0) {
        float ss = sh[0];
        float n = sqrtf(ss);
        norm[m] = n;
        float den = n * n;
        diag[m] = (den == 0.0f) ? 0.0f : ss / den;
    }
    __nv_bfloat16 h = __float2bfloat16(v);
    __nv_bfloat16 l = __float2bfloat16(v - __bfloat162float(h));
    size_t base = (size_t)m * 3 * HH + t;
    A3[base] = h; A3[base + HH] = h; A3[base + 2 * HH] = l;
    B3[base] = h; B3[base + HH] = l; B3[base + 2 * HH] = h;
}

__global__ void softmax_split3_kernel(const float* __restrict__ buf,
                                      __nv_bfloat16* __restrict__ out3, int L) {
    int r = blockIdx.x;
    const float* row = buf + (size_t)r * L;
    __nv_bfloat16* orow = out3 + (size_t)r * 3 * L;
    int t = threadIdx.x;
    int V = L >> 8;
    float v[16];
    float mx = NEG_INF;
    for (int u = 0; u < V; u++) {
        v[u] = row[t + (u << 8)];
        mx = fmaxf(mx, v[u]);
    }
    __shared__ float sh[256];
    sh[t] = mx;
    __syncthreads();
    for (int o = 128; o > 0; o >>= 1) {
        if (t < o) sh[t] = fmaxf(sh[t], sh[t + o]);
        __syncthreads();
    }
    mx = sh[0];
    __syncthreads();
    float s = 0.0f;
    for (int u = 0; u < V; u++) {
        v[u] = __expf(v[u] - mx);
        s += v[u];
    }
    sh[t] = s;
    __syncthreads();
    for (int o = 128; o > 0; o >>= 1) {
        if (t < o) sh[t] += sh[t + o];
        __syncthreads();
    }
    float inv = 1.0f / sh[0];
    for (int u = 0; u < V; u++) {
        float p = v[u] * inv;
        __nv_bfloat16 h = __float2bfloat16(p);
        __nv_bfloat16 l = __float2bfloat16(p - __bfloat162float(h));
        int c = t + (u << 8);
        orow[c] = h;
        orow[c + L] = h;
        orow[c + 2 * L] = l;
    }
}

__global__ void top3_reduce_scatter(const float* __restrict__ cval, const int* __restrict__ cidx,
                                    const float* __restrict__ h, float* __restrict__ hidden2,
                                    float* __restrict__ colsum2) {
    int i = blockIdx.x, t = threadIdx.x;
    size_t off = ((size_t)i * 128 + t) * 3;
    __shared__ float sv[384];
    __shared__ int si[384];
    __shared__ float bv[KTOP];
    __shared__ int bi[KTOP];
    sv[t] = cval[off]; sv[128 + t] = cval[off + 1]; sv[256 + t] = cval[off + 2];
    si[t] = cidx[off]; si[128 + t] = cidx[off + 1]; si[256 + t] = cidx[off + 2];
    __syncthreads();
    if (t == 0) {
        float a0 = NEG_INF, a1 = NEG_INF, a2 = NEG_INF;
        int j0 = 0, j1 = 0, j2 = 0;
        for (int q = 0; q < 384; q++) ins3(sv[q], si[q], a0, a1, a2, j0, j1, j2);
        ins3(0.0f, i, a0, a1, a2, j0, j1, j2);
        bv[0] = a0; bv[1] = a1; bv[2] = a2;
        bi[0] = j0; bi[1] = j1; bi[2] = j2;
    }
    __syncthreads();
    float hv = h[(size_t)i * HH + t];
#pragma unroll
    for (int k = 0; k < KTOP; k++) {
        int j = bi[k];
        float v = bv[k];
        atomicAdd(&hidden2[(size_t)j * HH + t], v * hv);
        if (t == 0) atomicAdd(&colsum2[j], v);
    }
}

__global__ void diag_valid_kernel(const float* __restrict__ colsum2, const float* __restrict__ diag,
                                  const float* __restrict__ h, float* __restrict__ hidden2,
                                  float* __restrict__ valid2f, float* __restrict__ norm2,
                                  __nv_bfloat16* __restrict__ B3) {
    int j = blockIdx.x;
    int t = threadIdx.x;
    float dterm = (colsum2[j] != 0.0f) ? diag[j] : 0.0f;
    float v = hidden2[(size_t)j * HH + t] + dterm * h[(size_t)j * HH + t];
    __shared__ float shs[128];
    __shared__ float shq[128];
    shs[t] = v;
    shq[t] = v * v;
    __syncthreads();
    for (int o = 64; o > 0; o >>= 1) {
        if (t < o) { shs[t] += shs[t + o]; shq[t] += shq[t + o]; }
        __syncthreads();
    }
    float valid = (shs[0] != 0.0f) ? 1.0f : 0.0f;
    v *= valid;
    hidden2[(size_t)j * HH + t] = v;
    if (t == 0) {
        valid2f[j] = valid;
        norm2[j] = valid * sqrtf(shq[0]);
    }
    __nv_bfloat16 hh = __float2bfloat16(v);
    __nv_bfloat16 l = __float2bfloat16(v - __bfloat162float(hh));
    size_t base = (size_t)j * 3 * HH + t;
    B3[base] = hh; B3[base + HH] = l; B3[base + 2 * HH] = hh;
}

// ---------------- host orchestration ----------------
static EpiParams ep_make(int mode) {
    EpiParams e;
    e.mode = mode;
    e.normA = nullptr; e.normB = nullptr; e.validf = nullptr;
    e.cval = nullptr; e.cidx = nullptr;
    return e;
}

static void launch_mma(const __nv_bfloat16* A, const __nv_bfloat16* B, float* C,
                       int M, int Nn, int Ktot, int splits, const EpiParams& ep) {
    dim3 grid(Nn / 128, M / 128, splits), block(128);
    mma_gemm<<<grid, block, MMA_SMEM>>>(A, B, C, M, Nn, Ktot, Ktot / splits, ep);
}

#define PS_SMEM (3 * 32 * 132 * 4)
#define HS_SMEM (4 * 32 * 132 * 4)

#define SYM(p, s) do { void* _tmp; cudaGetSymbolAddress(&_tmp, s); p = (float*)_tmp; } while (0)
#define SYMB(p, s) do { void* _tmp; cudaGetSymbolAddress(&_tmp, s); p = (__nv_bfloat16*)_tmp; } while (0)

extern "C" void kernel_launch(void* const* d_in, const int* in_sizes, int n_in,
                              void* d_out, int out_size) {
    const float* x = (const float*)d_in[0];
    const float* cm = (const float*)d_in[1];
    const float* mv = (const float*)d_in[2];
    const float* W_ps = (const float*)d_in[3];
    const float* b_ps = (const float*)d_in[4];
    const float* W_psf = (const float*)d_in[5];
    const float* b_psf = (const float*)d_in[6];
    const float* W_psb = (const float*)d_in[7];
    const float* b_psb = (const float*)d_in[8];
    const float* W_hs = (const float*)d_in[9];
    const float* b_hs = (const float*)d_in[10];
    const float* W_hsf = (const float*)d_in[11];
    const float* b_hsf = (const float*)d_in[12];
    const float* W_hsb = (const float*)d_in[13];
    const float* b_hsb = (const float*)d_in[14];
    const float* W_in = (const float*)d_in[15];
    const float* b_in = (const float*)d_in[16];
    const float* W_out = (const float*)d_in[17];
    const float* b_out = (const float*)d_in[18];
    float* y = (float*)d_out;

    cudaFuncSetAttribute(ps_tail_kernel, cudaFuncAttributeMaxDynamicSharedMemorySize, PS_SMEM);
    cudaFuncSetAttribute(hs_tail_kernel, cudaFuncAttributeMaxDynamicSharedMemorySize, HS_SMEM);
    cudaFuncSetAttribute(mma_gemm, cudaFuncAttributeMaxDynamicSharedMemorySize, MMA_SMEM);

    float *p_big, *p_nc, *p_hidden1, *p_hiddenB, *p_tmp, *p_tmp2, *p_h, *p_hidden2,
        *p_colsum, *p_valid1, *p_normx, *p_normB, *p_normh, *p_diag, *p_norm2, *p_valid2,
        *p_colsum2, *p_cval;
    int* p_cidx;
    __nv_bfloat16 *p_xA3, *p_xB3, *p_hA3, *p_hB3, *p_h1A3, *p_hBB3, *p_hBT3, *p_h2B3,
        *p_h2T3, *p_c2sA3, *p_probsA3, *p_cmT2, *p_xvT2, *p_xT3;
    SYM(p_big, g_big); SYM(p_nc, g_nc); SYM(p_hidden1, g_hidden1); SYM(p_hiddenB, g_hiddenB);
    SYM(p_tmp, g_tmp); SYM(p_tmp2, g_tmp2); SYM(p_h, g_h); SYM(p_hidden2, g_hidden2);
    SYM(p_colsum, g_colsum); SYM(p_valid1, g_valid1); SYM(p_normx, g_normx);
    SYM(p_normB, g_normB); SYM(p_normh, g_normh); SYM(p_diag, g_diag); SYM(p_norm2, g_norm2);
    SYM(p_valid2, g_valid2); SYM(p_colsum2, g_colsum2); SYM(p_cval, g_cval);
    { void* t; cudaGetSymbolAddress(&t, g_cidx); p_cidx = (int*)t; }
    SYMB(p_xA3, g_xA3); SYMB(p_xB3, g_xB3); SYMB(p_hA3, g_hA3); SYMB(p_hB3, g_hB3);
    SYMB(p_h1A3, g_h1A3); SYMB(p_hBB3, g_hBB3); SYMB(p_hBT3, g_hBT3); SYMB(p_h2B3, g_h2B3);
    SYMB(p_h2T3, g_h2T3); SYMB(p_c2sA3, g_c2sA3); SYMB(p_probsA3, g_probsA3);
    SYMB(p_cmT2, g_cmT2); SYMB(p_xvT2, g_xvT2); SYMB(p_xT3, g_xT3);
    __nv_bfloat16* p_pT3 = p_probsA3;

    zero_all_kernel<<<NN * HH / 256, 256>>>(p_hidden2, p_hidden1, p_hiddenB, p_colsum,
                                            p_colsum2, p_tmp, p_tmp2, y, b_out);
    xprep_kernel<<<NN, 128>>>(x, p_normx, p_xA3, p_xB3);

    // ---- ps branch ----
    {
        dim3 grid(NN / 32, CC / 32), block(32, 8);
        cm_transpose_kernel<<<grid, block>>>(cm, mv, p_cmT2, p_colsum);
    }
    {
        dim3 grid(NN / 32, HH / 32), block(32, 8);
        xT_kernel<<<grid, block>>>(x, mv, p_xT3, p_xvT2);
    }
    launch_mma(p_cmT2, p_xvT2, p_hidden1, CC, HH, 2 * NN, 32, ep_make(EP_ATOM));
    hidden1post_kernel<<<CC, 128>>>(p_hidden1, p_colsum, p_valid1, p_h1A3);
    launch_mma(p_h1A3, p_xB3, p_nc, CC, NN, 3 * HH, 1, ep_make(EP_NONE));
    softmax_split3_kernel<<<CC, 256>>>(p_nc, p_pT3, NN);
    launch_mma(p_pT3, p_xT3, p_hiddenB, CC, HH, 3 * NN, 32, ep_make(EP_ATOM));
    hiddenBpost_kernel<<<CC, 128>>>(p_hiddenB, p_valid1, p_normB, p_hBB3);
    {
        dim3 grid(CC / 32, HH / 32), block(32, 8);
        transpose_split3_kernel<<<grid, block>>>(p_hiddenB, p_hBT3, CC);
    }
    {
        EpiParams e = ep_make(EP_COS);
        e.normA = p_normx; e.normB = p_normB; e.validf = p_valid1;
        launch_mma(p_xA3, p_hBB3, p_nc, NN, CC, 3 * HH, 1, e);
    }
    softmax_split3_kernel<<<NN, 256>>>(p_nc, p_c2sA3, CC);
    launch_mma(p_c2sA3, p_hBT3, p_tmp, NN, HH, 3 * CC, 4, ep_make(EP_ATOM));
    ps_tail_kernel<<<NN / 32, 256, PS_SMEM>>>(p_tmp, x, W_ps, b_ps, W_psb, b_psb,
                                              W_psf, b_psf, W_out, p_h, y);

    // ---- hs branch ----
    hpost_kernel<<<NN, 128>>>(p_h, p_normh, p_diag, p_hA3, p_hB3);
    {
        EpiParams e = ep_make(EP_TOP3);
        e.normA = p_normh; e.normB = p_normh;
        e.cval = p_cval; e.cidx = p_cidx;
        launch_mma(p_hA3, p_hB3, p_big, NN, NN, 3 * HH, 1, e);
    }
    top3_reduce_scatter<<<NN, 128>>>(p_cval, p_cidx, p_h, p_hidden2, p_colsum2);
    diag_valid_kernel<<<NN, 128>>>(p_colsum2, p_diag, p_h, p_hidden2, p_valid2, p_norm2,
                                   p_h2B3);
    {
        dim3 grid(NN / 32, HH / 32), block(32, 8);
        transpose_split3_kernel<<<grid, block>>>(p_hidden2, p_h2T3, NN);
    }
    {
        EpiParams e = ep_make(EP_COS);
        e.normA = p_normh; e.normB = p_norm2; e.validf = p_valid2;
        launch_mma(p_hA3, p_h2B3, p_big, NN, NN, 3 * HH, 1, e);
    }
    softmax_split3_kernel<<<NN, 256>>>(p_big, p_probsA3, NN);
    launch_mma(p_probsA3, p_h2T3, p_tmp2, NN, HH, 3 * NN, 8, ep_make(EP_ATOM));
    hs_tail_kernel<<<NN / 32, 256, HS_SMEM>>>(p_tmp2, p_h, W_hs, b_hs, W_hsb, b_hsb,
                                              W_hsf, b_hsf, W_in, b_in, W_out, y);
}

// round 12
// speedup vs baseline: 1.1014x; 1.1014x over previous
#include <cuda_runtime.h>
#include <cuda_bf16.h>
#include <math.h>
#include <stdint.h>

#define NN 4096
#define CC 512
#define HH 128
#define KTOP 3

#define NEG_INF (__int_as_float(0xff800000))

// ---------------- static scratch ----------------
__device__ float g_big[(size_t)NN * NN];
__device__ float g_nc[(size_t)NN * CC];
__device__ float g_hidden1[CC * HH];
__device__ float g_hiddenB[CC * HH];
__device__ float g_tmp[NN * HH];
__device__ float g_tmp2[NN * HH];
__device__ float g_h[NN * HH];
__device__ float g_hidden2[NN * HH];
__device__ float g_colsum[CC];
__device__ float g_valid1[CC];
__device__ float g_normx[NN];
__device__ float g_normB[CC];
__device__ float g_normh[NN];
__device__ float g_diag[NN];
__device__ float g_norm2[NN];
__device__ float g_valid2[NN];
__device__ float g_colsum2[NN];
__device__ float g_cval[(size_t)NN * 128 * 3];
__device__ int   g_cidx[(size_t)NN * 128 * 3];

__device__ __nv_bfloat16 g_xA3[(size_t)NN * 3 * HH];
__device__ __nv_bfloat16 g_xB3[(size_t)NN * 3 * HH];
__device__ __nv_bfloat16 g_hA3[(size_t)NN * 3 * HH];
__device__ __nv_bfloat16 g_hB3[(size_t)NN * 3 * HH];
__device__ __nv_bfloat16 g_h1A3[(size_t)CC * 3 * HH];
__device__ __nv_bfloat16 g_hBB3[(size_t)CC * 3 * HH];
__device__ __nv_bfloat16 g_hBT3[(size_t)HH * 3 * CC];
__device__ __nv_bfloat16 g_h2B3[(size_t)NN * 3 * HH];
__device__ __nv_bfloat16 g_h2T3[(size_t)HH * 3 * NN];
__device__ __nv_bfloat16 g_c2sA3[(size_t)NN * 3 * CC];
__device__ __nv_bfloat16 g_probsA3[(size_t)NN * 3 * NN];   // aliased as pT_A3 [CC,3NN]
__device__ __nv_bfloat16 g_cmT2[(size_t)CC * 2 * NN];
__device__ __nv_bfloat16 g_xvT2[(size_t)HH * 2 * NN];
__device__ __nv_bfloat16 g_xT3[(size_t)HH * 3 * NN];

enum { EP_NONE = 0, EP_COS = 3, EP_ATOM = 6, EP_TOP3 = 7 };

struct EpiParams {
    int mode;
    const float* normA;
    const float* normB;
    const float* validf;
    float* cval;
    int* cidx;
};

__device__ __forceinline__ void ins3(float v, int j, float& b0, float& b1, float& b2,
                                     int& j0, int& j1, int& j2) {
    if (v > b0) { b2 = b1; j2 = j1; b1 = b0; j1 = j0; b0 = v; j0 = j; }
    else if (v > b1) { b2 = b1; j2 = j1; b1 = v; j1 = j; }
    else if (v > b2) { b2 = v; j2 = j; }
}

// ---------------- mma.sync bf16 GEMM (R10 config: 8 warps, 64x32 warp tile, 2-stage) ----
#define SMEM_ROW 80

__device__ __forceinline__ void mma16816(float* c, const uint32_t* a, const uint32_t* b) {
    asm volatile(
        "mma.sync.aligned.m16n8k16.row.col.f32.bf16.bf16.f32 "
        "{%0,%1,%2,%3}, {%4,%5,%6,%7}, {%8,%9}, {%0,%1,%2,%3};"
        : "+f"(c[0]), "+f"(c[1]), "+f"(c[2]), "+f"(c[3])
        : "r"(a[0]), "r"(a[1]), "r"(a[2]), "r"(a[3]), "r"(b[0]), "r"(b[1]));
}

__device__ __forceinline__ void cp_async16(uint32_t smem_addr, const void* gptr) {
    asm volatile("cp.async.cg.shared.global [%0], [%1], 16;" :: "r"(smem_addr), "l"(gptr));
}

__device__ __forceinline__ void ldmatrix_x4(uint32_t* r, uint32_t addr) {
    asm volatile("ldmatrix.sync.aligned.m8n8.x4.shared.b16 {%0,%1,%2,%3}, [%4];"
                 : "=r"(r[0]), "=r"(r[1]), "=r"(r[2]), "=r"(r[3]) : "r"(addr));
}

__global__ void __launch_bounds__(256)
mma_gemm(const __nv_bfloat16* __restrict__ A, const __nv_bfloat16* __restrict__ B,
         float* __restrict__ C, int M, int Nn, int Ktot, int kchunk, EpiParams ep) {
    __shared__ __align__(16) char As_[2][128 * SMEM_ROW];
    __shared__ __align__(16) char Bs_[2][128 * SMEM_ROW];

    const int tid = threadIdx.x;
    const int lane = tid & 31;
    const int wid = tid >> 5;
    const int warp_m = (wid >> 2) * 64;
    const int warp_n = (wid & 3) * 32;
    const int m0 = blockIdx.y * 128;
    const int n0 = blockIdx.x * 128;
    const int kbase = blockIdx.z * kchunk;
    const int niter = kchunk >> 5;

    const char* Ag = (const char*)(A + (size_t)m0 * Ktot + kbase);
    const char* Bg = (const char*)(B + (size_t)n0 * Ktot + kbase);
    const size_t rowb = (size_t)Ktot * 2;

    uint32_t asb = (uint32_t)__cvta_generic_to_shared(&As_[0][0]);
    uint32_t bsb = (uint32_t)__cvta_generic_to_shared(&Bs_[0][0]);

    float acc[4][4][4];
#pragma unroll
    for (int i = 0; i < 4; i++)
#pragma unroll
        for (int j = 0; j < 4; j++)
#pragma unroll
            for (int q = 0; q < 4; q++) acc[i][j][q] = 0.0f;

    const int lm0 = tid >> 2;
    const int lc = tid & 3;

    const int lj = lane >> 3;
    const int lr = lane & 7;
    const uint32_t a_row_off = (uint32_t)(warp_m + (lj & 1) * 8 + lr) * SMEM_ROW +
                               (uint32_t)(lj >> 1) * 16;
    const uint32_t b_row_off = (uint32_t)(warp_n + (lj >> 1) * 8 + lr) * SMEM_ROW +
                               (uint32_t)(lj & 1) * 16;

#define LOAD_TILE(s, it) do { \
    size_t goff = (size_t)(it) * 64 + lc * 16; \
    uint32_t soff = (uint32_t)((s) * 128 * SMEM_ROW + lc * 16); \
    cp_async16(asb + soff + lm0 * SMEM_ROW, Ag + (size_t)lm0 * rowb + goff); \
    cp_async16(asb + soff + (lm0 + 64) * SMEM_ROW, Ag + (size_t)(lm0 + 64) * rowb + goff); \
    cp_async16(bsb + soff + lm0 * SMEM_ROW, Bg + (size_t)lm0 * rowb + goff); \
    cp_async16(bsb + soff + (lm0 + 64) * SMEM_ROW, Bg + (size_t)(lm0 + 64) * rowb + goff); \
    asm volatile("cp.async.commit_group;"); \
} while (0)

    LOAD_TILE(0, 0);

    for (int it = 0; it < niter; it++) {
        int s = it & 1;
        if (it + 1 < niter) {
            LOAD_TILE(s ^ 1, it + 1);
            asm volatile("cp.async.wait_group 1;");
        } else {
            asm volatile("cp.async.wait_group 0;");
        }
        __syncthreads();

        uint32_t abase = asb + (uint32_t)s * (128 * SMEM_ROW) + a_row_off;
        uint32_t bbase = bsb + (uint32_t)s * (128 * SMEM_ROW) + b_row_off;
#pragma unroll
        for (int ks = 0; ks < 32; ks += 16) {
            uint32_t a[4][4], b[4][2];
#pragma unroll
            for (int mi = 0; mi < 4; mi++)
                ldmatrix_x4(a[mi], abase + mi * 16 * SMEM_ROW + ks * 2);
#pragma unroll
            for (int p = 0; p < 2; p++) {
                uint32_t t[4];
                ldmatrix_x4(t, bbase + p * 16 * SMEM_ROW + ks * 2);
                b[p * 2][0] = t[0]; b[p * 2][1] = t[1];
                b[p * 2 + 1][0] = t[2]; b[p * 2 + 1][1] = t[3];
            }
#pragma unroll
            for (int mi = 0; mi < 4; mi++)
#pragma unroll
                for (int ni = 0; ni < 4; ni++) mma16816(acc[mi][ni], a[mi], b[ni]);
        }
        __syncthreads();
    }

    if (ep.mode == EP_TOP3) {
#pragma unroll
        for (int mi = 0; mi < 4; mi++) {
#pragma unroll
            for (int half = 0; half < 2; half++) {
                int m = m0 + warp_m + mi * 16 + (lane >> 2) + half * 8;
                float na = ep.normA[m];
                float b0 = NEG_INF, b1 = NEG_INF, b2 = NEG_INF;
                int j0 = 0, j1 = 0, j2 = 0;
#pragma unroll
                for (int ni = 0; ni < 4; ni++) {
#pragma unroll
                    for (int q = 0; q < 2; q++) {
                        int c = n0 + warp_n + ni * 8 + (lane & 3) * 2 + q;
                        float v = acc[mi][ni][half * 2 + q];
                        float den = na * ep.normB[c];
                        v = v / (den == 0.0f ? 1.0f : den);
                        if (c == m) v = NEG_INF;
                        ins3(v, c, b0, b1, b2, j0, j1, j2);
                    }
                }
#pragma unroll
                for (int msk = 1; msk <= 2; msk <<= 1) {
                    float o0 = __shfl_xor_sync(0xffffffff, b0, msk);
                    int p0 = __shfl_xor_sync(0xffffffff, j0, msk);
                    float o1 = __shfl_xor_sync(0xffffffff, b1, msk);
                    int p1 = __shfl_xor_sync(0xffffffff, j1, msk);
                    float o2 = __shfl_xor_sync(0xffffffff, b2, msk);
                    int p2 = __shfl_xor_sync(0xffffffff, j2, msk);
                    ins3(o0, p0, b0, b1, b2, j0, j1, j2);
                    ins3(o1, p1, b0, b1, b2, j0, j1, j2);
                    ins3(o2, p2, b0, b1, b2, j0, j1, j2);
                }
                if ((lane & 3) == 0) {
                    int chunk = blockIdx.x * 4 + (warp_n >> 5);
                    size_t off = ((size_t)m * 128 + chunk) * 3;
                    ep.cval[off] = b0; ep.cval[off + 1] = b1; ep.cval[off + 2] = b2;
                    ep.cidx[off] = j0; ep.cidx[off + 1] = j1; ep.cidx[off + 2] = j2;
                }
            }
        }
        return;
    }

#pragma unroll
    for (int mi = 0; mi < 4; mi++) {
        int r0 = m0 + warp_m + mi * 16 + (lane >> 2);
#pragma unroll
        for (int ni = 0; ni < 4; ni++) {
            int c = n0 + warp_n + ni * 8 + (lane & 3) * 2;
#pragma unroll
            for (int half = 0; half < 2; half++) {
                int m = r0 + half * 8;
                float v0 = acc[mi][ni][half * 2];
                float v1 = acc[mi][ni][half * 2 + 1];
                size_t o = (size_t)m * Nn + c;
                if (ep.mode == EP_COS) {
                    float na = ep.normA[m];
                    float d0 = na * ep.normB[c];
                    float d1 = na * ep.normB[c + 1];
                    v0 = v0 / (d0 == 0.0f ? 1.0f : d0);
                    v1 = v1 / (d1 == 0.0f ? 1.0f : d1);
                    if (ep.validf) {
                        if (ep.validf[c] == 0.0f) v0 = NEG_INF;
                        if (ep.validf[c + 1] == 0.0f) v1 = NEG_INF;
                    }
                    *(float2*)&C[o] = make_float2(v0, v1);
                } else if (ep.mode == EP_ATOM) {
                    atomicAdd(&C[o], v0);
                    atomicAdd(&C[o + 1], v1);
                } else {
                    *(float2*)&C[o] = make_float2(v0, v1);
                }
            }
        }
    }
}

// ---------------- transpose kernels ----------------
__global__ void transpose_split3_kernel(const float* __restrict__ X,
                                        __nv_bfloat16* __restrict__ Y, int K) {
    __shared__ float tile[32][33];
    int k0 = blockIdx.x * 32, h0 = blockIdx.y * 32;
    int tx = threadIdx.x, ty = threadIdx.y;
    for (int r = ty; r < 32; r += 8)
        tile[r][tx] = X[(size_t)(k0 + r) * HH + h0 + tx];
    __syncthreads();
    for (int r = ty; r < 32; r += 8) {
        int hcol = h0 + r;
        int k = k0 + tx;
        float v = tile[tx][r];
        __nv_bfloat16 h = __float2bfloat16(v);
        __nv_bfloat16 l = __float2bfloat16(v - __bfloat162float(h));
        size_t base = (size_t)hcol * 3 * K + k;
        Y[base] = h;
        Y[base + K] = l;
        Y[base + 2 * K] = h;
    }
}

// x -> xT3 ([h,l,h]) AND xvT2 (mv-weighted, [h,l]) in one pass
__global__ void xT_kernel(const float* __restrict__ X, const float* __restrict__ mv,
                          __nv_bfloat16* __restrict__ T3, __nv_bfloat16* __restrict__ V2) {
    __shared__ float tile[32][33];
    int k0 = blockIdx.x * 32, h0 = blockIdx.y * 32;
    int tx = threadIdx.x, ty = threadIdx.y;
    for (int r = ty; r < 32; r += 8)
        tile[r][tx] = X[(size_t)(k0 + r) * HH + h0 + tx];
    __syncthreads();
    float mvk = mv[k0 + tx];
    for (int r = ty; r < 32; r += 8) {
        int hcol = h0 + r;
        int k = k0 + tx;
        float v = tile[tx][r];
        __nv_bfloat16 h = __float2bfloat16(v);
        __nv_bfloat16 l = __float2bfloat16(v - __bfloat162float(h));
        size_t base = (size_t)hcol * 3 * NN + k;
        T3[base] = h;
        T3[base + NN] = l;
        T3[base + 2 * NN] = h;
        float w = v * mvk;
        __nv_bfloat16 hw = __float2bfloat16(w);
        __nv_bfloat16 lw = __float2bfloat16(w - __bfloat162float(hw));
        size_t base2 = (size_t)hcol * 2 * NN + k;
        V2[base2] = hw;
        V2[base2 + NN] = lw;
    }
}

// cm transpose (duplicated bf16, exact) + column sums (mv-weighted) fused
__global__ void cm_transpose_kernel(const float* __restrict__ cm, const float* __restrict__ mv,
                                    __nv_bfloat16* __restrict__ Y, float* __restrict__ colsum) {
    __shared__ float tile[32][33];
    int k0 = blockIdx.x * 32, c0 = blockIdx.y * 32;
    int tx = threadIdx.x, ty = threadIdx.y;
    for (int r = ty; r < 32; r += 8)
        tile[r][tx] = cm[(size_t)(k0 + r) * CC + c0 + tx];
    __syncthreads();
    float mvk = mv[k0 + tx];
    for (int r = ty; r < 32; r += 8) {
        int c = c0 + r;
        int k = k0 + tx;
        float fv = tile[tx][r];
        __nv_bfloat16 v = __float2bfloat16(fv);
        size_t base = (size_t)c * 2 * NN + k;
        Y[base] = v;
        Y[base + NN] = v;
        float s = fv * mvk;
#pragma unroll
        for (int o = 16; o > 0; o >>= 1) s += __shfl_xor_sync(0xffffffffu, s, o);
        if (tx == 0) atomicAdd(&colsum[c], s);
    }
}

// ---------------- fused tail kernels ----------------
__device__ __forceinline__ void stage_mm(const float* __restrict__ As,
                                         const float* __restrict__ W, float* Ws,
                                         int tid, float acc[2][8]) {
    const int tx = tid & 15, ty = tid >> 4;
#pragma unroll
    for (int i = 0; i < 2; i++)
#pragma unroll
        for (int j = 0; j < 8; j++) acc[i][j] = 0.0f;
    for (int kc = 0; kc < 128; kc += 32) {
        __syncthreads();
#pragma unroll
        for (int l = 0; l < 16; l++) {
            int id = tid + l * 256;
            int n = id >> 5, k = id & 31;
            Ws[k * 132 + n] = W[n * 128 + kc + k];
        }
        __syncthreads();
#pragma unroll
        for (int k = 0; k < 32; k++) {
            float a0 = As[(ty * 2) * 132 + kc + k];
            float a1 = As[(ty * 2 + 1) * 132 + kc + k];
            const float* wr = &Ws[k * 132 + tx * 8];
            float4 w0 = *(const float4*)wr;
            float4 w1 = *(const float4*)(wr + 4);
            float wv[8] = {w0.x, w0.y, w0.z, w0.w, w1.x, w1.y, w1.z, w1.w};
#pragma unroll
            for (int j = 0; j < 8; j++) {
                acc[0][j] = fmaf(a0, wv[j], acc[0][j]);
                acc[1][j] = fmaf(a1, wv[j], acc[1][j]);
            }
        }
    }
}

__global__ void __launch_bounds__(256) ps_tail_kernel(
    const float* __restrict__ tmp, const float* __restrict__ x,
    const float* __restrict__ W1, const float* __restrict__ b1,
    const float* __restrict__ W2, const float* __restrict__ b2,
    const float* __restrict__ W3, const float* __restrict__ b3,
    const float* __restrict__ Wout, float* __restrict__ h, float* __restrict__ y) {
    extern __shared__ float sm[];
    float* As = sm;
    float* Ps = sm + 32 * 132;
    float* Ws = sm + 2 * 32 * 132;
    int tid = threadIdx.x;
    int m0 = blockIdx.x * 32;
    const int tx = tid & 15, ty = tid >> 4;
#pragma unroll
    for (int l = 0; l < 4; l++) {
        int id = tid + l * 256;
        int m = id >> 5, c4 = id & 31;
        *(float4*)&As[m * 132 + c4 * 4] = *(const float4*)&tmp[(size_t)(m0 + m) * 128 + c4 * 4];
    }
    float acc[2][8];
    stage_mm(As, W1, Ws, tid, acc);
#pragma unroll
    for (int i = 0; i < 2; i++)
#pragma unroll
        for (int j = 0; j < 8; j++)
            Ps[(ty * 2 + i) * 132 + tx * 8 + j] = acc[i][j] + b1[tx * 8 + j];
    stage_mm(Ps, W2, Ws, tid, acc);
#pragma unroll
    for (int i = 0; i < 2; i++) {
        int m = m0 + ty * 2 + i;
#pragma unroll
        for (int j = 0; j < 8; j++) {
            int n = tx * 8 + j;
            h[(size_t)m * 128 + n] = x[(size_t)m * 128 + n] - (acc[i][j] + b2[n]);
        }
    }
    stage_mm(Ps, W3, Ws, tid, acc);
    float d0 = 0.0f, d1 = 0.0f;
#pragma unroll
    for (int j = 0; j < 8; j++) {
        int n = tx * 8 + j;
        float z0 = acc[0][j] + b3[n]; z0 = z0 > 0.0f ? z0 : 0.01f * z0;
        float z1 = acc[1][j] + b3[n]; z1 = z1 > 0.0f ? z1 : 0.01f * z1;
        d0 = fmaf(z0, Wout[n], d0);
        d1 = fmaf(z1, Wout[n], d1);
    }
#pragma unroll
    for (int o = 1; o < 16; o <<= 1) {
        d0 += __shfl_xor_sync(0xffffffff, d0, o);
        d1 += __shfl_xor_sync(0xffffffff, d1, o);
    }
    if (tx == 0) {
        atomicAdd(&y[m0 + ty * 2], d0);
        atomicAdd(&y[m0 + ty * 2 + 1], d1);
    }
}

__global__ void __launch_bounds__(256) hs_tail_kernel(
    const float* __restrict__ tmp2, const float* __restrict__ h,
    const float* __restrict__ W1, const float* __restrict__ b1,
    const float* __restrict__ W2, const float* __restrict__ b2,
    const float* __restrict__ W3, const float* __restrict__ b3,
    const float* __restrict__ W4, const float* __restrict__ b4,
    const float* __restrict__ Wout, float* __restrict__ y) {
    extern __shared__ float sm[];
    float* As = sm;
    float* Hs = sm + 32 * 132;
    float* Is = sm + 2 * 32 * 132;
    float* Ws = sm + 3 * 32 * 132;
    int tid = threadIdx.x;
    int m0 = blockIdx.x * 32;
    const int tx = tid & 15, ty = tid >> 4;
#pragma unroll
    for (int l = 0; l < 4; l++) {
        int id = tid + l * 256;
        int m = id >> 5, c4 = id & 31;
        *(float4*)&As[m * 132 + c4 * 4] = *(const float4*)&tmp2[(size_t)(m0 + m) * 128 + c4 * 4];
    }
    float acc[2][8];
    stage_mm(As, W1, Ws, tid, acc);
#pragma unroll
    for (int i = 0; i < 2; i++)
#pragma unroll
        for (int j = 0; j < 8; j++)
            Hs[(ty * 2 + i) * 132 + tx * 8 + j] = acc[i][j] + b1[tx * 8 + j];
    stage_mm(Hs, W2, Ws, tid, acc);
#pragma unroll
    for (int i = 0; i < 2; i++) {
        int m = m0 + ty * 2 + i;
#pragma unroll
        for (int j = 0; j < 8; j++) {
            int n = tx * 8 + j;
            Is[(ty * 2 + i) * 132 + n] = h[(size_t)m * 128 + n] - (acc[i][j] + b2[n]);
        }
    }
    float d0 = 0.0f, d1 = 0.0f;
    stage_mm(Hs, W3, Ws, tid, acc);
#pragma unroll
    for (int j = 0; j < 8; j++) {
        int n = tx * 8 + j;
        float z0 = acc[0][j] + b3[n]; z0 = z0 > 0.0f ? z0 : 0.01f * z0;
        float z1 = acc[1][j] + b3[n]; z1 = z1 > 0.0f ? z1 : 0.01f * z1;
        d0 = fmaf(z0, Wout[n], d0);
        d1 = fmaf(z1, Wout[n], d1);
    }
    stage_mm(Is, W4, Ws, tid, acc);
#pragma unroll
    for (int j = 0; j < 8; j++) {
        int n = tx * 8 + j;
        float z0 = acc[0][j] + b4[n]; z0 = z0 > 0.0f ? z0 : 0.01f * z0;
        float z1 = acc[1][j] + b4[n]; z1 = z1 > 0.0f ? z1 : 0.01f * z1;
        d0 = fmaf(z0, Wout[n], d0);
        d1 = fmaf(z1, Wout[n], d1);
    }
#pragma unroll
    for (int o = 1; o < 16; o <<= 1) {
        d0 += __shfl_xor_sync(0xffffffff, d0, o);
        d1 += __shfl_xor_sync(0xffffffff, d1, o);
    }
    if (tx == 0) {
        atomicAdd(&y[m0 + ty * 2], d0);
        atomicAdd(&y[m0 + ty * 2 + 1], d1);
    }
}

// ---------------- fused small kernels ----------------
__global__ void zero_all_kernel(float* h2, float* h1, float* hB, float* cs, float* cs2,
                                float* tmp, float* tmp2, float* y, const float* bout) {
    int i = blockIdx.x * blockDim.x + threadIdx.x;
    h2[i] = 0.0f;
    tmp[i] = 0.0f;
    tmp2[i] = 0.0f;
    if (i < CC * HH) { h1[i] = 0.0f; hB[i] = 0.0f; }
    if (i < CC) cs[i] = 0.0f;
    if (i < NN) { cs2[i] = 0.0f; y[i] = bout[0]; }
}

__global__ void xprep_kernel(const float* __restrict__ X, float* __restrict__ norm,
                             __nv_bfloat16* __restrict__ A3, __nv_bfloat16* __restrict__ B3) {
    int m = blockIdx.x, t = threadIdx.x;
    float v = X[(size_t)m * HH + t];
    __shared__ float sh[128];
    sh[t] = v * v;
    __syncthreads();
    for (int o = 64; o > 0; o >>= 1) {
        if (t < o) sh[t] += sh[t + o];
        __syncthreads();
    }
    if (t == 0) norm[m] = sqrtf(sh[0]);
    __nv_bfloat16 h = __float2bfloat16(v);
    __nv_bfloat16 l = __float2bfloat16(v - __bfloat162float(h));
    size_t base = (size_t)m * 3 * HH + t;
    A3[base] = h; A3[base + HH] = h; A3[base + 2 * HH] = l;
    B3[base] = h; B3[base + HH] = l; B3[base + 2 * HH] = h;
}

__global__ void hidden1post_kernel(float* __restrict__ X, const float* __restrict__ colsum,
                                   float* __restrict__ validf, __nv_bfloat16* __restrict__ A3) {
    int m = blockIdx.x, t = threadIdx.x;
    float sc = 1.0f / (colsum[m] + 1.0f);
    float v = X[(size_t)m * HH + t] * sc;
    X[(size_t)m * HH + t] = v;
    __shared__ float sh[128];
    sh[t] = v;
    __syncthreads();
    for (int o = 64; o > 0; o >>= 1) {
        if (t < o) sh[t] += sh[t + o];
        __syncthreads();
    }
    if (t == 0) validf[m] = (sh[0] != 0.0f) ? 1.0f : 0.0f;
    __nv_bfloat16 h = __float2bfloat16(v);
    __nv_bfloat16 l = __float2bfloat16(v - __bfloat162float(h));
    size_t base = (size_t)m * 3 * HH + t;
    A3[base] = h; A3[base + HH] = h; A3[base + 2 * HH] = l;
}

__global__ void hiddenBpost_kernel(float* __restrict__ X, const float* __restrict__ validf,
                                   float* __restrict__ norm, __nv_bfloat16* __restrict__ B3) {
    int m = blockIdx.x, t = threadIdx.x;
    float v = X[(size_t)m * HH + t] * validf[m];
    X[(size_t)m * HH + t] = v;
    __shared__ float sh[128];
    sh[t] = v * v;
    __syncthreads();
    for (int o = 64; o > 0; o >>= 1) {
        if (t < o) sh[t] += sh[t + o];
        __syncthreads();
    }
    if (t == 0) norm[m] = sqrtf(sh[0]);
    __nv_bfloat16 h = __float2bfloat16(v);
    __nv_bfloat16 l = __float2bfloat16(v - __bfloat162float(h));
    size_t base = (size_t)m * 3 * HH + t;
    B3[base] = h; B3[base + HH] = l; B3[base + 2 * HH] = h;
}

__global__ void hpost_kernel(const float* __restrict__ X, float* __restrict__ norm,
                             float* __restrict__ diag, __nv_bfloat16* __restrict__ A3,
                             __nv_bfloat16* __restrict__ B3) {
    int m = blockIdx.x, t = threadIdx.x;
    float v = X[(size_t)m * HH + t];
    __shared__ float sh[128];
    sh[t] = v * v;
    __syncthreads();
    for (int o = 64; o > 0; o >>= 1) {
        if (t < o) sh[t] += sh[t + o];
        __syncthreads();
    }
    if (t == 0) {
        float ss = sh[0];
        float n = sqrtf(ss);
        norm[m] = n;
        float den = n * n;
        diag[m] = (den == 0.0f) ? 0.0f : ss / den;
    }
    __nv_bfloat16 h = __float2bfloat16(v);
    __nv_bfloat16 l = __float2bfloat16(v - __bfloat162float(h));
    size_t base = (size_t)m * 3 * HH + t;
    A3[base] = h; A3[base + HH] = h; A3[base + 2 * HH] = l;
    B3[base] = h; B3[base + HH] = l; B3[base + 2 * HH] = h;
}

__global__ void softmax_split3_kernel(const float* __restrict__ buf,
                                      __nv_bfloat16* __restrict__ out3, int L) {
    int r = blockIdx.x;
    const float* row = buf + (size_t)r * L;
    __nv_bfloat16* orow = out3 + (size_t)r * 3 * L;
    int t = threadIdx.x;
    int V = L >> 8;
    float v[16];
    float mx = NEG_INF;
    for (int u = 0; u < V; u++) {
        v[u] = row[t + (u << 8)];
        mx = fmaxf(mx, v[u]);
    }
    __shared__ float sh[256];
    sh[t] = mx;
    __syncthreads();
    for (int o = 128; o > 0; o >>= 1) {
        if (t < o) sh[t] = fmaxf(sh[t], sh[t + o]);
        __syncthreads();
    }
    mx = sh[0];
    __syncthreads();
    float s = 0.0f;
    for (int u = 0; u < V; u++) {
        v[u] = __expf(v[u] - mx);
        s += v[u];
    }
    sh[t] = s;
    __syncthreads();
    for (int o = 128; o > 0; o >>= 1) {
        if (t < o) sh[t] += sh[t + o];
        __syncthreads();
    }
    float inv = 1.0f / sh[0];
    for (int u = 0; u < V; u++) {
        float p = v[u] * inv;
        __nv_bfloat16 h = __float2bfloat16(p);
        __nv_bfloat16 l = __float2bfloat16(p - __bfloat162float(h));
        int c = t + (u << 8);
        orow[c] = h;
        orow[c + L] = h;
        orow[c + 2 * L] = l;
    }
}

__global__ void top3_reduce_scatter(const float* __restrict__ cval, const int* __restrict__ cidx,
                                    const float* __restrict__ h, float* __restrict__ hidden2,
                                    float* __restrict__ colsum2) {
    int i = blockIdx.x, t = threadIdx.x;
    size_t off = ((size_t)i * 128 + t) * 3;
    __shared__ float sv[384];
    __shared__ int si[384];
    __shared__ float bv[KTOP];
    __shared__ int bi[KTOP];
    sv[t] = cval[off]; sv[128 + t] = cval[off + 1]; sv[256 + t] = cval[off + 2];
    si[t] = cidx[off]; si[128 + t] = cidx[off + 1]; si[256 + t] = cidx[off + 2];
    __syncthreads();
    if (t == 0) {
        float a0 = NEG_INF, a1 = NEG_INF, a2 = NEG_INF;
        int j0 = 0, j1 = 0, j2 = 0;
        for (int q = 0; q < 384; q++) ins3(sv[q], si[q], a0, a1, a2, j0, j1, j2);
        ins3(0.0f, i, a0, a1, a2, j0, j1, j2);
        bv[0] = a0; bv[1] = a1; bv[2] = a2;
        bi[0] = j0; bi[1] = j1; bi[2] = j2;
    }
    __syncthreads();
    float hv = h[(size_t)i * HH + t];
#pragma unroll
    for (int k = 0; k < KTOP; k++) {
        int j = bi[k];
        float v = bv[k];
        atomicAdd(&hidden2[(size_t)j * HH + t], v * hv);
        if (t == 0) atomicAdd(&colsum2[j], v);
    }
}

__global__ void diag_valid_kernel(const float* __restrict__ colsum2, const float* __restrict__ diag,
                                  const float* __restrict__ h, float* __restrict__ hidden2,
                                  float* __restrict__ valid2f, float* __restrict__ norm2,
                                  __nv_bfloat16* __restrict__ B3) {
    int j = blockIdx.x;
    int t = threadIdx.x;
    float dterm = (colsum2[j] != 0.0f) ? diag[j] : 0.0f;
    float v = hidden2[(size_t)j * HH + t] + dterm * h[(size_t)j * HH + t];
    __shared__ float shs[128];
    __shared__ float shq[128];
    shs[t] = v;
    shq[t] = v * v;
    __syncthreads();
    for (int o = 64; o > 0; o >>= 1) {
        if (t < o) { shs[t] += shs[t + o]; shq[t] += shq[t + o]; }
        __syncthreads();
    }
    float valid = (shs[0] != 0.0f) ? 1.0f : 0.0f;
    v *= valid;
    hidden2[(size_t)j * HH + t] = v;
    if (t == 0) {
        valid2f[j] = valid;
        norm2[j] = valid * sqrtf(shq[0]);
    }
    __nv_bfloat16 hh = __float2bfloat16(v);
    __nv_bfloat16 l = __float2bfloat16(v - __bfloat162float(hh));
    size_t base = (size_t)j * 3 * HH + t;
    B3[base] = hh; B3[base + HH] = l; B3[base + 2 * HH] = hh;
}

// ---------------- host orchestration ----------------
static EpiParams ep_make(int mode) {
    EpiParams e;
    e.mode = mode;
    e.normA = nullptr; e.normB = nullptr; e.validf = nullptr;
    e.cval = nullptr; e.cidx = nullptr;
    return e;
}

static void launch_mma(const __nv_bfloat16* A, const __nv_bfloat16* B, float* C,
                       int M, int Nn, int Ktot, int splits, const EpiParams& ep) {
    dim3 grid(Nn / 128, M / 128, splits), block(256);
    mma_gemm<<<grid, block>>>(A, B, C, M, Nn, Ktot, Ktot / splits, ep);
}

#define PS_SMEM (3 * 32 * 132 * 4)
#define HS_SMEM (4 * 32 * 132 * 4)

#define SYM(p, s) do { void* _tmp; cudaGetSymbolAddress(&_tmp, s); p = (float*)_tmp; } while (0)
#define SYMB(p, s) do { void* _tmp; cudaGetSymbolAddress(&_tmp, s); p = (__nv_bfloat16*)_tmp; } while (0)

extern "C" void kernel_launch(void* const* d_in, const int* in_sizes, int n_in,
                              void* d_out, int out_size) {
    const float* x = (const float*)d_in[0];
    const float* cm = (const float*)d_in[1];
    const float* mv = (const float*)d_in[2];
    const float* W_ps = (const float*)d_in[3];
    const float* b_ps = (const float*)d_in[4];
    const float* W_psf = (const float*)d_in[5];
    const float* b_psf = (const float*)d_in[6];
    const float* W_psb = (const float*)d_in[7];
    const float* b_psb = (const float*)d_in[8];
    const float* W_hs = (const float*)d_in[9];
    const float* b_hs = (const float*)d_in[10];
    const float* W_hsf = (const float*)d_in[11];
    const float* b_hsf = (const float*)d_in[12];
    const float* W_hsb = (const float*)d_in[13];
    const float* b_hsb = (const float*)d_in[14];
    const float* W_in = (const float*)d_in[15];
    const float* b_in = (const float*)d_in[16];
    const float* W_out = (const float*)d_in[17];
    const float* b_out = (const float*)d_in[18];
    float* y = (float*)d_out;

    cudaFuncSetAttribute(ps_tail_kernel, cudaFuncAttributeMaxDynamicSharedMemorySize, PS_SMEM);
    cudaFuncSetAttribute(hs_tail_kernel, cudaFuncAttributeMaxDynamicSharedMemorySize, HS_SMEM);

    float *p_big, *p_nc, *p_hidden1, *p_hiddenB, *p_tmp, *p_tmp2, *p_h, *p_hidden2,
        *p_colsum, *p_valid1, *p_normx, *p_normB, *p_normh, *p_diag, *p_norm2, *p_valid2,
        *p_colsum2, *p_cval;
    int* p_cidx;
    __nv_bfloat16 *p_xA3, *p_xB3, *p_hA3, *p_hB3, *p_h1A3, *p_hBB3, *p_hBT3, *p_h2B3,
        *p_h2T3, *p_c2sA3, *p_probsA3, *p_cmT2, *p_xvT2, *p_xT3;
    SYM(p_big, g_big); SYM(p_nc, g_nc); SYM(p_hidden1, g_hidden1); SYM(p_hiddenB, g_hiddenB);
    SYM(p_tmp, g_tmp); SYM(p_tmp2, g_tmp2); SYM(p_h, g_h); SYM(p_hidden2, g_hidden2);
    SYM(p_colsum, g_colsum); SYM(p_valid1, g_valid1); SYM(p_normx, g_normx);
    SYM(p_normB, g_normB); SYM(p_normh, g_normh); SYM(p_diag, g_diag); SYM(p_norm2, g_norm2);
    SYM(p_valid2, g_valid2); SYM(p_colsum2, g_colsum2); SYM(p_cval, g_cval);
    { void* t; cudaGetSymbolAddress(&t, g_cidx); p_cidx = (int*)t; }
    SYMB(p_xA3, g_xA3); SYMB(p_xB3, g_xB3); SYMB(p_hA3, g_hA3); SYMB(p_hB3, g_hB3);
    SYMB(p_h1A3, g_h1A3); SYMB(p_hBB3, g_hBB3); SYMB(p_hBT3, g_hBT3); SYMB(p_h2B3, g_h2B3);
    SYMB(p_h2T3, g_h2T3); SYMB(p_c2sA3, g_c2sA3); SYMB(p_probsA3, g_probsA3);
    SYMB(p_cmT2, g_cmT2); SYMB(p_xvT2, g_xvT2); SYMB(p_xT3, g_xT3);
    __nv_bfloat16* p_pT3 = p_probsA3;

    zero_all_kernel<<<NN * HH / 256, 256>>>(p_hidden2, p_hidden1, p_hiddenB, p_colsum,
                                            p_colsum2, p_tmp, p_tmp2, y, b_out);
    xprep_kernel<<<NN, 128>>>(x, p_normx, p_xA3, p_xB3);

    // ---- ps branch ----
    {
        dim3 grid(NN / 32, CC / 32), block(32, 8);
        cm_transpose_kernel<<<grid, block>>>(cm, mv, p_cmT2, p_colsum);
    }
    {
        dim3 grid(NN / 32, HH / 32), block(32, 8);
        xT_kernel<<<grid, block>>>(x, mv, p_xT3, p_xvT2);
    }
    launch_mma(p_cmT2, p_xvT2, p_hidden1, CC, HH, 2 * NN, 32, ep_make(EP_ATOM));
    hidden1post_kernel<<<CC, 128>>>(p_hidden1, p_colsum, p_valid1, p_h1A3);
    launch_mma(p_h1A3, p_xB3, p_nc, CC, NN, 3 * HH, 1, ep_make(EP_NONE));
    softmax_split3_kernel<<<CC, 256>>>(p_nc, p_pT3, NN);
    launch_mma(p_pT3, p_xT3, p_hiddenB, CC, HH, 3 * NN, 32, ep_make(EP_ATOM));
    hiddenBpost_kernel<<<CC, 128>>>(p_hiddenB, p_valid1, p_normB, p_hBB3);
    {
        dim3 grid(CC / 32, HH / 32), block(32, 8);
        transpose_split3_kernel<<<grid, block>>>(p_hiddenB, p_hBT3, CC);
    }
    {
        EpiParams e = ep_make(EP_COS);
        e.normA = p_normx; e.normB = p_normB; e.validf = p_valid1;
        launch_mma(p_xA3, p_hBB3, p_nc, NN, CC, 3 * HH, 1, e);
    }
    softmax_split3_kernel<<<NN, 256>>>(p_nc, p_c2sA3, CC);
    launch_mma(p_c2sA3, p_hBT3, p_tmp, NN, HH, 3 * CC, 4, ep_make(EP_ATOM));
    ps_tail_kernel<<<NN / 32, 256, PS_SMEM>>>(p_tmp, x, W_ps, b_ps, W_psb, b_psb,
                                              W_psf, b_psf, W_out, p_h, y);

    // ---- hs branch ----
    hpost_kernel<<<NN, 128>>>(p_h, p_normh, p_diag, p_hA3, p_hB3);
    {
        EpiParams e = ep_make(EP_TOP3);
        e.normA = p_normh; e.normB = p_normh;
        e.cval = p_cval; e.cidx = p_cidx;
        launch_mma(p_hA3, p_hB3, p_big, NN, NN, 3 * HH, 1, e);
    }
    top3_reduce_scatter<<<NN, 128>>>(p_cval, p_cidx, p_h, p_hidden2, p_colsum2);
    diag_valid_kernel<<<NN, 128>>>(p_colsum2, p_diag, p_h, p_hidden2, p_valid2, p_norm2,
                                   p_h2B3);
    {
        dim3 grid(NN / 32, HH / 32), block(32, 8);
        transpose_split3_kernel<<<grid, block>>>(p_hidden2, p_h2T3, NN);
    }
    {
        EpiParams e = ep_make(EP_COS);
        e.normA = p_normh; e.normB = p_norm2; e.validf = p_valid2;
        launch_mma(p_hA3, p_h2B3, p_big, NN, NN, 3 * HH, 1, e);
    }
    softmax_split3_kernel<<<NN, 256>>>(p_big, p_probsA3, NN);
    launch_mma(p_probsA3, p_h2T3, p_tmp2, NN, HH, 3 * NN, 8, ep_make(EP_ATOM));
    hs_tail_kernel<<<NN / 32, 256, HS_SMEM>>>(p_tmp2, p_h, W_hs, b_hs, W_hsb, b_hsb,
                                              W_hsf, b_hsf, W_in, b_in, W_out, y);
}

// round 13
// speedup vs baseline: 1.1346x; 1.0301x over previous
#include <cuda_runtime.h>
#include <cuda_bf16.h>
#include <math.h>
#include <stdint.h>

#define NN 4096
#define CC 512
#define HH 128
#define KTOP 3

#define NEG_INF (__int_as_float(0xff800000))

// ---------------- static scratch ----------------
__device__ float g_big[(size_t)NN * NN];
__device__ float g_nc[(size_t)NN * CC];
__device__ float g_hidden1[CC * HH];
__device__ float g_hiddenB[CC * HH];
__device__ float g_tmp[NN * HH];
__device__ float g_tmp2[NN * HH];
__device__ float g_h[NN * HH];
__device__ float g_hidden2[NN * HH];
__device__ float g_colsum[CC];
__device__ float g_valid1[CC];
__device__ float g_normx[NN];
__device__ float g_normB[CC];
__device__ float g_normh[NN];
__device__ float g_diag[NN];
__device__ float g_norm2[NN];
__device__ float g_valid2[NN];
__device__ float g_colsum2[NN];
__device__ float g_rowsC[NN];
__device__ float g_rowsN[NN];
__device__ float g_cval[(size_t)NN * 128 * 3];
__device__ int   g_cidx[(size_t)NN * 128 * 3];

__device__ __nv_bfloat16 g_xA3[(size_t)NN * 3 * HH];
__device__ __nv_bfloat16 g_xB3[(size_t)NN * 3 * HH];
__device__ __nv_bfloat16 g_hA3[(size_t)NN * 3 * HH];
__device__ __nv_bfloat16 g_hB3[(size_t)NN * 3 * HH];
__device__ __nv_bfloat16 g_h1A3[(size_t)CC * 3 * HH];
__device__ __nv_bfloat16 g_hBB3[(size_t)CC * 3 * HH];
__device__ __nv_bfloat16 g_hBT3[(size_t)HH * 3 * CC];
__device__ __nv_bfloat16 g_h2B3[(size_t)NN * 3 * HH];
__device__ __nv_bfloat16 g_h2T3[(size_t)HH * 3 * NN];
__device__ __nv_bfloat16 g_c2sA3[(size_t)NN * 3 * CC];
__device__ __nv_bfloat16 g_probsA3[(size_t)NN * 3 * NN];   // aliased as pT_A3 [CC,3NN]
__device__ __nv_bfloat16 g_cmT2[(size_t)CC * 2 * NN];
__device__ __nv_bfloat16 g_xvT2[(size_t)HH * 2 * NN];
__device__ __nv_bfloat16 g_xT3[(size_t)HH * 3 * NN];

enum { EP_NONE = 0, EP_COS = 3, EP_ATOM = 6, EP_TOP3 = 7, EP_EXP3 = 8 };

struct EpiParams {
    int mode;
    const float* normA;
    const float* normB;
    const float* validf;
    float* cval;
    int* cidx;
    __nv_bfloat16* out3;
    float* rowsum;
};

__device__ __forceinline__ void ins3(float v, int j, float& b0, float& b1, float& b2,
                                     int& j0, int& j1, int& j2) {
    if (v > b0) { b2 = b1; j2 = j1; b1 = b0; j1 = j0; b0 = v; j0 = j; }
    else if (v > b1) { b2 = b1; j2 = j1; b1 = v; j1 = j; }
    else if (v > b2) { b2 = v; j2 = j; }
}

// ---------------- mma.sync bf16 GEMM (8 warps, 64x32 warp tile, 2-stage) ----------------
#define SMEM_ROW 80

__device__ __forceinline__ void mma16816(float* c, const uint32_t* a, const uint32_t* b) {
    asm volatile(
        "mma.sync.aligned.m16n8k16.row.col.f32.bf16.bf16.f32 "
        "{%0,%1,%2,%3}, {%4,%5,%6,%7}, {%8,%9}, {%0,%1,%2,%3};"
        : "+f"(c[0]), "+f"(c[1]), "+f"(c[2]), "+f"(c[3])
        : "r"(a[0]), "r"(a[1]), "r"(a[2]), "r"(a[3]), "r"(b[0]), "r"(b[1]));
}

__device__ __forceinline__ void cp_async16(uint32_t smem_addr, const void* gptr) {
    asm volatile("cp.async.cg.shared.global [%0], [%1], 16;" :: "r"(smem_addr), "l"(gptr));
}

__device__ __forceinline__ void ldmatrix_x4(uint32_t* r, uint32_t addr) {
    asm volatile("ldmatrix.sync.aligned.m8n8.x4.shared.b16 {%0,%1,%2,%3}, [%4];"
                 : "=r"(r[0]), "=r"(r[1]), "=r"(r[2]), "=r"(r[3]) : "r"(addr));
}

__global__ void __launch_bounds__(256)
mma_gemm(const __nv_bfloat16* __restrict__ A, const __nv_bfloat16* __restrict__ B,
         float* __restrict__ C, int M, int Nn, int Ktot, int kchunk, EpiParams ep) {
    __shared__ __align__(16) char As_[2][128 * SMEM_ROW];
    __shared__ __align__(16) char Bs_[2][128 * SMEM_ROW];

    const int tid = threadIdx.x;
    const int lane = tid & 31;
    const int wid = tid >> 5;
    const int warp_m = (wid >> 2) * 64;
    const int warp_n = (wid & 3) * 32;
    const int m0 = blockIdx.y * 128;
    const int n0 = blockIdx.x * 128;
    const int kbase = blockIdx.z * kchunk;
    const int niter = kchunk >> 5;

    const char* Ag = (const char*)(A + (size_t)m0 * Ktot + kbase);
    const char* Bg = (const char*)(B + (size_t)n0 * Ktot + kbase);
    const size_t rowb = (size_t)Ktot * 2;

    uint32_t asb = (uint32_t)__cvta_generic_to_shared(&As_[0][0]);
    uint32_t bsb = (uint32_t)__cvta_generic_to_shared(&Bs_[0][0]);

    float acc[4][4][4];
#pragma unroll
    for (int i = 0; i < 4; i++)
#pragma unroll
        for (int j = 0; j < 4; j++)
#pragma unroll
            for (int q = 0; q < 4; q++) acc[i][j][q] = 0.0f;

    const int lm0 = tid >> 2;
    const int lc = tid & 3;

    const int lj = lane >> 3;
    const int lr = lane & 7;
    const uint32_t a_row_off = (uint32_t)(warp_m + (lj & 1) * 8 + lr) * SMEM_ROW +
                               (uint32_t)(lj >> 1) * 16;
    const uint32_t b_row_off = (uint32_t)(warp_n + (lj >> 1) * 8 + lr) * SMEM_ROW +
                               (uint32_t)(lj & 1) * 16;

#define LOAD_TILE(s, it) do { \
    size_t goff = (size_t)(it) * 64 + lc * 16; \
    uint32_t soff = (uint32_t)((s) * 128 * SMEM_ROW + lc * 16); \
    cp_async16(asb + soff + lm0 * SMEM_ROW, Ag + (size_t)lm0 * rowb + goff); \
    cp_async16(asb + soff + (lm0 + 64) * SMEM_ROW, Ag + (size_t)(lm0 + 64) * rowb + goff); \
    cp_async16(bsb + soff + lm0 * SMEM_ROW, Bg + (size_t)lm0 * rowb + goff); \
    cp_async16(bsb + soff + (lm0 + 64) * SMEM_ROW, Bg + (size_t)(lm0 + 64) * rowb + goff); \
    asm volatile("cp.async.commit_group;"); \
} while (0)

    LOAD_TILE(0, 0);

    for (int it = 0; it < niter; it++) {
        int s = it & 1;
        if (it + 1 < niter) {
            LOAD_TILE(s ^ 1, it + 1);
            asm volatile("cp.async.wait_group 1;");
        } else {
            asm volatile("cp.async.wait_group 0;");
        }
        __syncthreads();

        uint32_t abase = asb + (uint32_t)s * (128 * SMEM_ROW) + a_row_off;
        uint32_t bbase = bsb + (uint32_t)s * (128 * SMEM_ROW) + b_row_off;
#pragma unroll
        for (int ks = 0; ks < 32; ks += 16) {
            uint32_t a[4][4], b[4][2];
#pragma unroll
            for (int mi = 0; mi < 4; mi++)
                ldmatrix_x4(a[mi], abase + mi * 16 * SMEM_ROW + ks * 2);
#pragma unroll
            for (int p = 0; p < 2; p++) {
                uint32_t t[4];
                ldmatrix_x4(t, bbase + p * 16 * SMEM_ROW + ks * 2);
                b[p * 2][0] = t[0]; b[p * 2][1] = t[1];
                b[p * 2 + 1][0] = t[2]; b[p * 2 + 1][1] = t[3];
            }
#pragma unroll
            for (int mi = 0; mi < 4; mi++)
#pragma unroll
                for (int ni = 0; ni < 4; ni++) mma16816(acc[mi][ni], a[mi], b[ni]);
        }
        __syncthreads();
    }

    if (ep.mode == EP_TOP3) {
#pragma unroll
        for (int mi = 0; mi < 4; mi++) {
#pragma unroll
            for (int half = 0; half < 2; half++) {
                int m = m0 + warp_m + mi * 16 + (lane >> 2) + half * 8;
                float na = ep.normA[m];
                float b0 = NEG_INF, b1 = NEG_INF, b2 = NEG_INF;
                int j0 = 0, j1 = 0, j2 = 0;
#pragma unroll
                for (int ni = 0; ni < 4; ni++) {
#pragma unroll
                    for (int q = 0; q < 2; q++) {
                        int c = n0 + warp_n + ni * 8 + (lane & 3) * 2 + q;
                        float v = acc[mi][ni][half * 2 + q];
                        float den = na * ep.normB[c];
                        v = v / (den == 0.0f ? 1.0f : den);
                        if (c == m) v = NEG_INF;
                        ins3(v, c, b0, b1, b2, j0, j1, j2);
                    }
                }
#pragma unroll
                for (int msk = 1; msk <= 2; msk <<= 1) {
                    float o0 = __shfl_xor_sync(0xffffffff, b0, msk);
                    int p0 = __shfl_xor_sync(0xffffffff, j0, msk);
                    float o1 = __shfl_xor_sync(0xffffffff, b1, msk);
                    int p1 = __shfl_xor_sync(0xffffffff, j1, msk);
                    float o2 = __shfl_xor_sync(0xffffffff, b2, msk);
                    int p2 = __shfl_xor_sync(0xffffffff, j2, msk);
                    ins3(o0, p0, b0, b1, b2, j0, j1, j2);
                    ins3(o1, p1, b0, b1, b2, j0, j1, j2);
                    ins3(o2, p2, b0, b1, b2, j0, j1, j2);
                }
                if ((lane & 3) == 0) {
                    int chunk = blockIdx.x * 4 + (warp_n >> 5);
                    size_t off = ((size_t)m * 128 + chunk) * 3;
                    ep.cval[off] = b0; ep.cval[off + 1] = b1; ep.cval[off + 2] = b2;
                    ep.cidx[off] = j0; ep.cidx[off + 1] = j1; ep.cidx[off + 2] = j2;
                }
            }
        }
        return;
    }

    if (ep.mode == EP_EXP3) {
#pragma unroll
        for (int mi = 0; mi < 4; mi++) {
#pragma unroll
            for (int half = 0; half < 2; half++) {
                int m = m0 + warp_m + mi * 16 + (lane >> 2) + half * 8;
                float na = ep.normA[m];
                float rs = 0.0f;
#pragma unroll
                for (int ni = 0; ni < 4; ni++) {
                    int c = n0 + warp_n + ni * 8 + (lane & 3) * 2;
                    float v0 = acc[mi][ni][half * 2];
                    float v1 = acc[mi][ni][half * 2 + 1];
                    float d0 = na * ep.normB[c];
                    float d1 = na * ep.normB[c + 1];
                    v0 = v0 / (d0 == 0.0f ? 1.0f : d0);
                    v1 = v1 / (d1 == 0.0f ? 1.0f : d1);
                    float e0 = (ep.validf && ep.validf[c] == 0.0f) ? 0.0f : __expf(v0);
                    float e1 = (ep.validf && ep.validf[c + 1] == 0.0f) ? 0.0f : __expf(v1);
                    rs += e0 + e1;
                    __nv_bfloat16 h0 = __float2bfloat16(e0);
                    __nv_bfloat16 h1 = __float2bfloat16(e1);
                    __nv_bfloat16 l0 = __float2bfloat16(e0 - __bfloat162float(h0));
                    __nv_bfloat16 l1 = __float2bfloat16(e1 - __bfloat162float(h1));
                    __nv_bfloat162 hv; hv.x = h0; hv.y = h1;
                    __nv_bfloat162 lv; lv.x = l0; lv.y = l1;
                    size_t base = (size_t)m * 3 * Nn + c;
                    *(__nv_bfloat162*)&ep.out3[base] = hv;
                    *(__nv_bfloat162*)&ep.out3[base + Nn] = hv;
                    *(__nv_bfloat162*)&ep.out3[base + 2 * Nn] = lv;
                }
                rs += __shfl_xor_sync(0xffffffffu, rs, 1);
                rs += __shfl_xor_sync(0xffffffffu, rs, 2);
                if ((lane & 3) == 0) atomicAdd(&ep.rowsum[m], rs);
            }
        }
        return;
    }

#pragma unroll
    for (int mi = 0; mi < 4; mi++) {
        int r0 = m0 + warp_m + mi * 16 + (lane >> 2);
#pragma unroll
        for (int ni = 0; ni < 4; ni++) {
            int c = n0 + warp_n + ni * 8 + (lane & 3) * 2;
#pragma unroll
            for (int half = 0; half < 2; half++) {
                int m = r0 + half * 8;
                float v0 = acc[mi][ni][half * 2];
                float v1 = acc[mi][ni][half * 2 + 1];
                size_t o = (size_t)m * Nn + c;
                if (ep.mode == EP_COS) {
                    float na = ep.normA[m];
                    float d0 = na * ep.normB[c];
                    float d1 = na * ep.normB[c + 1];
                    v0 = v0 / (d0 == 0.0f ? 1.0f : d0);
                    v1 = v1 / (d1 == 0.0f ? 1.0f : d1);
                    if (ep.validf) {
                        if (ep.validf[c] == 0.0f) v0 = NEG_INF;
                        if (ep.validf[c + 1] == 0.0f) v1 = NEG_INF;
                    }
                    *(float2*)&C[o] = make_float2(v0, v1);
                } else if (ep.mode == EP_ATOM) {
                    atomicAdd(&C[o], v0);
                    atomicAdd(&C[o + 1], v1);
                } else {
                    *(float2*)&C[o] = make_float2(v0, v1);
                }
            }
        }
    }
}

// ---------------- transpose kernels ----------------
__global__ void transpose_split3_kernel(const float* __restrict__ X,
                                        __nv_bfloat16* __restrict__ Y, int K) {
    __shared__ float tile[32][33];
    int k0 = blockIdx.x * 32, h0 = blockIdx.y * 32;
    int tx = threadIdx.x, ty = threadIdx.y;
    for (int r = ty; r < 32; r += 8)
        tile[r][tx] = X[(size_t)(k0 + r) * HH + h0 + tx];
    __syncthreads();
    for (int r = ty; r < 32; r += 8) {
        int hcol = h0 + r;
        int k = k0 + tx;
        float v = tile[tx][r];
        __nv_bfloat16 h = __float2bfloat16(v);
        __nv_bfloat16 l = __float2bfloat16(v - __bfloat162float(h));
        size_t base = (size_t)hcol * 3 * K + k;
        Y[base] = h;
        Y[base + K] = l;
        Y[base + 2 * K] = h;
    }
}

// x -> xT3 ([h,l,h]) AND xvT2 (mv-weighted, [h,l]) in one pass
__global__ void xT_kernel(const float* __restrict__ X, const float* __restrict__ mv,
                          __nv_bfloat16* __restrict__ T3, __nv_bfloat16* __restrict__ V2) {
    __shared__ float tile[32][33];
    int k0 = blockIdx.x * 32, h0 = blockIdx.y * 32;
    int tx = threadIdx.x, ty = threadIdx.y;
    for (int r = ty; r < 32; r += 8)
        tile[r][tx] = X[(size_t)(k0 + r) * HH + h0 + tx];
    __syncthreads();
    float mvk = mv[k0 + tx];
    for (int r = ty; r < 32; r += 8) {
        int hcol = h0 + r;
        int k = k0 + tx;
        float v = tile[tx][r];
        __nv_bfloat16 h = __float2bfloat16(v);
        __nv_bfloat16 l = __float2bfloat16(v - __bfloat162float(h));
        size_t base = (size_t)hcol * 3 * NN + k;
        T3[base] = h;
        T3[base + NN] = l;
        T3[base + 2 * NN] = h;
        float w = v * mvk;
        __nv_bfloat16 hw = __float2bfloat16(w);
        __nv_bfloat16 lw = __float2bfloat16(w - __bfloat162float(hw));
        size_t base2 = (size_t)hcol * 2 * NN + k;
        V2[base2] = hw;
        V2[base2 + NN] = lw;
    }
}

// cm transpose (duplicated bf16, exact) + column sums (mv-weighted) fused
__global__ void cm_transpose_kernel(const float* __restrict__ cm, const float* __restrict__ mv,
                                    __nv_bfloat16* __restrict__ Y, float* __restrict__ colsum) {
    __shared__ float tile[32][33];
    int k0 = blockIdx.x * 32, c0 = blockIdx.y * 32;
    int tx = threadIdx.x, ty = threadIdx.y;
    for (int r = ty; r < 32; r += 8)
        tile[r][tx] = cm[(size_t)(k0 + r) * CC + c0 + tx];
    __syncthreads();
    float mvk = mv[k0 + tx];
    for (int r = ty; r < 32; r += 8) {
        int c = c0 + r;
        int k = k0 + tx;
        float fv = tile[tx][r];
        __nv_bfloat16 v = __float2bfloat16(fv);
        size_t base = (size_t)c * 2 * NN + k;
        Y[base] = v;
        Y[base + NN] = v;
        float s = fv * mvk;
#pragma unroll
        for (int o = 16; o > 0; o >>= 1) s += __shfl_xor_sync(0xffffffffu, s, o);
        if (tx == 0) atomicAdd(&colsum[c], s);
    }
}

// ---------------- fused tail kernels ----------------
__device__ __forceinline__ void stage_mm(const float* __restrict__ As,
                                         const float* __restrict__ W, float* Ws,
                                         int tid, float acc[2][8]) {
    const int tx = tid & 15, ty = tid >> 4;
#pragma unroll
    for (int i = 0; i < 2; i++)
#pragma unroll
        for (int j = 0; j < 8; j++) acc[i][j] = 0.0f;
    for (int kc = 0; kc < 128; kc += 32) {
        __syncthreads();
#pragma unroll
        for (int l = 0; l < 16; l++) {
            int id = tid + l * 256;
            int n = id >> 5, k = id & 31;
            Ws[k * 132 + n] = W[n * 128 + kc + k];
        }
        __syncthreads();
#pragma unroll
        for (int k = 0; k < 32; k++) {
            float a0 = As[(ty * 2) * 132 + kc + k];
            float a1 = As[(ty * 2 + 1) * 132 + kc + k];
            const float* wr = &Ws[k * 132 + tx * 8];
            float4 w0 = *(const float4*)wr;
            float4 w1 = *(const float4*)(wr + 4);
            float wv[8] = {w0.x, w0.y, w0.z, w0.w, w1.x, w1.y, w1.z, w1.w};
#pragma unroll
            for (int j = 0; j < 8; j++) {
                acc[0][j] = fmaf(a0, wv[j], acc[0][j]);
                acc[1][j] = fmaf(a1, wv[j], acc[1][j]);
            }
        }
    }
}

__global__ void __launch_bounds__(256) ps_tail_kernel(
    const float* __restrict__ tmp, const float* __restrict__ rowsum,
    const float* __restrict__ x,
    const float* __restrict__ W1, const float* __restrict__ b1,
    const float* __restrict__ W2, const float* __restrict__ b2,
    const float* __restrict__ W3, const float* __restrict__ b3,
    const float* __restrict__ Wout, float* __restrict__ h, float* __restrict__ y) {
    extern __shared__ float sm[];
    float* As = sm;
    float* Ps = sm + 32 * 132;
    float* Ws = sm + 2 * 32 * 132;
    int tid = threadIdx.x;
    int m0 = blockIdx.x * 32;
    const int tx = tid & 15, ty = tid >> 4;
#pragma unroll
    for (int l = 0; l < 4; l++) {
        int id = tid + l * 256;
        int m = id >> 5, c4 = id & 31;
        float inv = 1.0f / rowsum[m0 + m];
        float4 v = *(const float4*)&tmp[(size_t)(m0 + m) * 128 + c4 * 4];
        v.x *= inv; v.y *= inv; v.z *= inv; v.w *= inv;
        *(float4*)&As[m * 132 + c4 * 4] = v;
    }
    float acc[2][8];
    stage_mm(As, W1, Ws, tid, acc);
#pragma unroll
    for (int i = 0; i < 2; i++)
#pragma unroll
        for (int j = 0; j < 8; j++)
            Ps[(ty * 2 + i) * 132 + tx * 8 + j] = acc[i][j] + b1[tx * 8 + j];
    stage_mm(Ps, W2, Ws, tid, acc);
#pragma unroll
    for (int i = 0; i < 2; i++) {
        int m = m0 + ty * 2 + i;
#pragma unroll
        for (int j = 0; j < 8; j++) {
            int n = tx * 8 + j;
            h[(size_t)m * 128 + n] = x[(size_t)m * 128 + n] - (acc[i][j] + b2[n]);
        }
    }
    stage_mm(Ps, W3, Ws, tid, acc);
    float d0 = 0.0f, d1 = 0.0f;
#pragma unroll
    for (int j = 0; j < 8; j++) {
        int n = tx * 8 + j;
        float z0 = acc[0][j] + b3[n]; z0 = z0 > 0.0f ? z0 : 0.01f * z0;
        float z1 = acc[1][j] + b3[n]; z1 = z1 > 0.0f ? z1 : 0.01f * z1;
        d0 = fmaf(z0, Wout[n], d0);
        d1 = fmaf(z1, Wout[n], d1);
    }
#pragma unroll
    for (int o = 1; o < 16; o <<= 1) {
        d0 += __shfl_xor_sync(0xffffffff, d0, o);
        d1 += __shfl_xor_sync(0xffffffff, d1, o);
    }
    if (tx == 0) {
        atomicAdd(&y[m0 + ty * 2], d0);
        atomicAdd(&y[m0 + ty * 2 + 1], d1);
    }
}

__global__ void __launch_bounds__(256) hs_tail_kernel(
    const float* __restrict__ tmp2, const float* __restrict__ rowsum,
    const float* __restrict__ h,
    const float* __restrict__ W1, const float* __restrict__ b1,
    const float* __restrict__ W2, const float* __restrict__ b2,
    const float* __restrict__ W3, const float* __restrict__ b3,
    const float* __restrict__ W4, const float* __restrict__ b4,
    const float* __restrict__ Wout, float* __restrict__ y) {
    extern __shared__ float sm[];
    float* As = sm;
    float* Hs = sm + 32 * 132;
    float* Is = sm + 2 * 32 * 132;
    float* Ws = sm + 3 * 32 * 132;
    int tid = threadIdx.x;
    int m0 = blockIdx.x * 32;
    const int tx = tid & 15, ty = tid >> 4;
#pragma unroll
    for (int l = 0; l < 4; l++) {
        int id = tid + l * 256;
        int m = id >> 5, c4 = id & 31;
        float inv = 1.0f / rowsum[m0 + m];
        float4 v = *(const float4*)&tmp2[(size_t)(m0 + m) * 128 + c4 * 4];
        v.x *= inv; v.y *= inv; v.z *= inv; v.w *= inv;
        *(float4*)&As[m * 132 + c4 * 4] = v;
    }
    float acc[2][8];
    stage_mm(As, W1, Ws, tid, acc);
#pragma unroll
    for (int i = 0; i < 2; i++)
#pragma unroll
        for (int j = 0; j < 8; j++)
            Hs[(ty * 2 + i) * 132 + tx * 8 + j] = acc[i][j] + b1[tx * 8 + j];
    stage_mm(Hs, W2, Ws, tid, acc);
#pragma unroll
    for (int i = 0; i < 2; i++) {
        int m = m0 + ty * 2 + i;
#pragma unroll
        for (int j = 0; j < 8; j++) {
            int n = tx * 8 + j;
            Is[(ty * 2 + i) * 132 + n] = h[(size_t)m * 128 + n] - (acc[i][j] + b2[n]);
        }
    }
    float d0 = 0.0f, d1 = 0.0f;
    stage_mm(Hs, W3, Ws, tid, acc);
#pragma unroll
    for (int j = 0; j < 8; j++) {
        int n = tx * 8 + j;
        float z0 = acc[0][j] + b3[n]; z0 = z0 > 0.0f ? z0 : 0.01f * z0;
        float z1 = acc[1][j] + b3[n]; z1 = z1 > 0.0f ? z1 : 0.01f * z1;
        d0 = fmaf(z0, Wout[n], d0);
        d1 = fmaf(z1, Wout[n], d1);
    }
    stage_mm(Is, W4, Ws, tid, acc);
#pragma unroll
    for (int j = 0; j < 8; j++) {
        int n = tx * 8 + j;
        float z0 = acc[0][j] + b4[n]; z0 = z0 > 0.0f ? z0 : 0.01f * z0;
        float z1 = acc[1][j] + b4[n]; z1 = z1 > 0.0f ? z1 : 0.01f * z1;
        d0 = fmaf(z0, Wout[n], d0);
        d1 = fmaf(z1, Wout[n], d1);
    }
#pragma unroll
    for (int o = 1; o < 16; o <<= 1) {
        d0 += __shfl_xor_sync(0xffffffff, d0, o);
        d1 += __shfl_xor_sync(0xffffffff, d1, o);
    }
    if (tx == 0) {
        atomicAdd(&y[m0 + ty * 2], d0);
        atomicAdd(&y[m0 + ty * 2 + 1], d1);
    }
}

// ---------------- fused small kernels ----------------
__global__ void zero_all_kernel(float* h2, float* h1, float* hB, float* cs, float* cs2,
                                float* tmp, float* tmp2, float* rsC, float* rsN,
                                float* y, const float* bout) {
    int i = blockIdx.x * blockDim.x + threadIdx.x;
    h2[i] = 0.0f;
    tmp[i] = 0.0f;
    tmp2[i] = 0.0f;
    if (i < CC * HH) { h1[i] = 0.0f; hB[i] = 0.0f; }
    if (i < CC) cs[i] = 0.0f;
    if (i < NN) { cs2[i] = 0.0f; rsC[i] = 0.0f; rsN[i] = 0.0f; y[i] = bout[0]; }
}

__global__ void xprep_kernel(const float* __restrict__ X, float* __restrict__ norm,
                             __nv_bfloat16* __restrict__ A3, __nv_bfloat16* __restrict__ B3) {
    int m = blockIdx.x, t = threadIdx.x;
    float v = X[(size_t)m * HH + t];
    __shared__ float sh[128];
    sh[t] = v * v;
    __syncthreads();
    for (int o = 64; o > 0; o >>= 1) {
        if (t < o) sh[t] += sh[t + o];
        __syncthreads();
    }
    if (t == 0) norm[m] = sqrtf(sh[0]);
    __nv_bfloat16 h = __float2bfloat16(v);
    __nv_bfloat16 l = __float2bfloat16(v - __bfloat162float(h));
    size_t base = (size_t)m * 3 * HH + t;
    A3[base] = h; A3[base + HH] = h; A3[base + 2 * HH] = l;
    B3[base] = h; B3[base + HH] = l; B3[base + 2 * HH] = h;
}

__global__ void hidden1post_kernel(float* __restrict__ X, const float* __restrict__ colsum,
                                   float* __restrict__ validf, __nv_bfloat16* __restrict__ A3) {
    int m = blockIdx.x, t = threadIdx.x;
    float sc = 1.0f / (colsum[m] + 1.0f);
    float v = X[(size_t)m * HH + t] * sc;
    X[(size_t)m * HH + t] = v;
    __shared__ float sh[128];
    sh[t] = v;
    __syncthreads();
    for (int o = 64; o > 0; o >>= 1) {
        if (t < o) sh[t] += sh[t + o];
        __syncthreads();
    }
    if (t == 0) validf[m] = (sh[0] != 0.0f) ? 1.0f : 0.0f;
    __nv_bfloat16 h = __float2bfloat16(v);
    __nv_bfloat16 l = __float2bfloat16(v - __bfloat162float(h));
    size_t base = (size_t)m * 3 * HH + t;
    A3[base] = h; A3[base + HH] = h; A3[base + 2 * HH] = l;
}

__global__ void hiddenBpost_kernel(float* __restrict__ X, const float* __restrict__ validf,
                                   float* __restrict__ norm, __nv_bfloat16* __restrict__ B3) {
    int m = blockIdx.x, t = threadIdx.x;
    float v = X[(size_t)m * HH + t] * validf[m];
    X[(size_t)m * HH + t] = v;
    __shared__ float sh[128];
    sh[t] = v * v;
    __syncthreads();
    for (int o = 64; o > 0; o >>= 1) {
        if (t < o) sh[t] += sh[t + o];
        __syncthreads();
    }
    if (t == 0) norm[m] = sqrtf(sh[0]);
    __nv_bfloat16 h = __float2bfloat16(v);
    __nv_bfloat16 l = __float2bfloat16(v - __bfloat162float(h));
    size_t base = (size_t)m * 3 * HH + t;
    B3[base] = h; B3[base + HH] = l; B3[base + 2 * HH] = h;
}

__global__ void hpost_kernel(const float* __restrict__ X, float* __restrict__ norm,
                             float* __restrict__ diag, __nv_bfloat16* __restrict__ A3,
                             __nv_bfloat16* __restrict__ B3) {
    int m = blockIdx.x, t = threadIdx.x;
    float v = X[(size_t)m * HH + t];
    __shared__ float sh[128];
    sh[t] = v * v;
    __syncthreads();
    for (int o = 64; o > 0; o >>= 1) {
        if (t < o) sh[t] += sh[t + o];
        __syncthreads();
    }
    if (t == 0) {
        float ss = sh[0];
        float n = sqrtf(ss);
        norm[m] = n;
        float den = n * n;
        diag[m] = (den == 0.0f) ? 0.0f : ss / den;
    }
    __nv_bfloat16 h = __float2bfloat16(v);
    __nv_bfloat16 l = __float2bfloat16(v - __bfloat162float(h));
    size_t base = (size_t)m * 3 * HH + t;
    A3[base] = h; A3[base + HH] = h; A3[base + 2 * HH] = l;
    B3[base] = h; B3[base + HH] = l; B3[base + 2 * HH] = h;
}

// softmax (unbounded logits) writing bf16 split-3 A-pattern directly
__global__ void softmax_split3_kernel(const float* __restrict__ buf,
                                      __nv_bfloat16* __restrict__ out3, int L) {
    int r = blockIdx.x;
    const float* row = buf + (size_t)r * L;
    __nv_bfloat16* orow = out3 + (size_t)r * 3 * L;
    int t = threadIdx.x;
    int V = L >> 8;
    float v[16];
    float mx = NEG_INF;
    for (int u = 0; u < V; u++) {
        v[u] = row[t + (u << 8)];
        mx = fmaxf(mx, v[u]);
    }
    __shared__ float sh[256];
    sh[t] = mx;
    __syncthreads();
    for (int o = 128; o > 0; o >>= 1) {
        if (t < o) sh[t] = fmaxf(sh[t], sh[t + o]);
        __syncthreads();
    }
    mx = sh[0];
    __syncthreads();
    float s = 0.0f;
    for (int u = 0; u < V; u++) {
        v[u] = __expf(v[u] - mx);
        s += v[u];
    }
    sh[t] = s;
    __syncthreads();
    for (int o = 128; o > 0; o >>= 1) {
        if (t < o) sh[t] += sh[t + o];
        __syncthreads();
    }
    float inv = 1.0f / sh[0];
    for (int u = 0; u < V; u++) {
        float p = v[u] * inv;
        __nv_bfloat16 h = __float2bfloat16(p);
        __nv_bfloat16 l = __float2bfloat16(p - __bfloat162float(h));
        int c = t + (u << 8);
        orow[c] = h;
        orow[c + L] = h;
        orow[c + 2 * L] = l;
    }
}

__global__ void top3_reduce_scatter(const float* __restrict__ cval, const int* __restrict__ cidx,
                                    const float* __restrict__ h, float* __restrict__ hidden2,
                                    float* __restrict__ colsum2) {
    int i = blockIdx.x, t = threadIdx.x;
    size_t off = ((size_t)i * 128 + t) * 3;
    __shared__ float sv[384];
    __shared__ int si[384];
    __shared__ float bv[KTOP];
    __shared__ int bi[KTOP];
    sv[t] = cval[off]; sv[128 + t] = cval[off + 1]; sv[256 + t] = cval[off + 2];
    si[t] = cidx[off]; si[128 + t] = cidx[off + 1]; si[256 + t] = cidx[off + 2];
    __syncthreads();
    if (t == 0) {
        float a0 = NEG_INF, a1 = NEG_INF, a2 = NEG_INF;
        int j0 = 0, j1 = 0, j2 = 0;
        for (int q = 0; q < 384; q++) ins3(sv[q], si[q], a0, a1, a2, j0, j1, j2);
        ins3(0.0f, i, a0, a1, a2, j0, j1, j2);
        bv[0] = a0; bv[1] = a1; bv[2] = a2;
        bi[0] = j0; bi[1] = j1; bi[2] = j2;
    }
    __syncthreads();
    float hv = h[(size_t)i * HH + t];
#pragma unroll
    for (int k = 0; k < KTOP; k++) {
        int j = bi[k];
        float v = bv[k];
        atomicAdd(&hidden2[(size_t)j * HH + t], v * hv);
        if (t == 0) atomicAdd(&colsum2[j], v);
    }
}

__global__ void diag_valid_kernel(const float* __restrict__ colsum2, const float* __restrict__ diag,
                                  const float* __restrict__ h, float* __restrict__ hidden2,
                                  float* __restrict__ valid2f, float* __restrict__ norm2,
                                  __nv_bfloat16* __restrict__ B3) {
    int j = blockIdx.x;
    int t = threadIdx.x;
    float dterm = (colsum2[j] != 0.0f) ? diag[j] : 0.0f;
    float v = hidden2[(size_t)j * HH + t] + dterm * h[(size_t)j * HH + t];
    __shared__ float shs[128];
    __shared__ float shq[128];
    shs[t] = v;
    shq[t] = v * v;
    __syncthreads();
    for (int o = 64; o > 0; o >>= 1) {
        if (t < o) { shs[t] += shs[t + o]; shq[t] += shq[t + o]; }
        __syncthreads();
    }
    float valid = (shs[0] != 0.0f) ? 1.0f : 0.0f;
    v *= valid;
    hidden2[(size_t)j * HH + t] = v;
    if (t == 0) {
        valid2f[j] = valid;
        norm2[j] = valid * sqrtf(shq[0]);
    }
    __nv_bfloat16 hh = __float2bfloat16(v);
    __nv_bfloat16 l = __float2bfloat16(v - __bfloat162float(hh));
    size_t base = (size_t)j * 3 * HH + t;
    B3[base] = hh; B3[base + HH] = l; B3[base + 2 * HH] = hh;
}

// ---------------- host orchestration ----------------
static EpiParams ep_make(int mode) {
    EpiParams e;
    e.mode = mode;
    e.normA = nullptr; e.normB = nullptr; e.validf = nullptr;
    e.cval = nullptr; e.cidx = nullptr;
    e.out3 = nullptr; e.rowsum = nullptr;
    return e;
}

static void launch_mma(const __nv_bfloat16* A, const __nv_bfloat16* B, float* C,
                       int M, int Nn, int Ktot, int splits, const EpiParams& ep) {
    dim3 grid(Nn / 128, M / 128, splits), block(256);
    mma_gemm<<<grid, block>>>(A, B, C, M, Nn, Ktot, Ktot / splits, ep);
}

#define PS_SMEM (3 * 32 * 132 * 4)
#define HS_SMEM (4 * 32 * 132 * 4)

#define SYM(p, s) do { void* _tmp; cudaGetSymbolAddress(&_tmp, s); p = (float*)_tmp; } while (0)
#define SYMB(p, s) do { void* _tmp; cudaGetSymbolAddress(&_tmp, s); p = (__nv_bfloat16*)_tmp; } while (0)

extern "C" void kernel_launch(void* const* d_in, const int* in_sizes, int n_in,
                              void* d_out, int out_size) {
    const float* x = (const float*)d_in[0];
    const float* cm = (const float*)d_in[1];
    const float* mv = (const float*)d_in[2];
    const float* W_ps = (const float*)d_in[3];
    const float* b_ps = (const float*)d_in[4];
    const float* W_psf = (const float*)d_in[5];
    const float* b_psf = (const float*)d_in[6];
    const float* W_psb = (const float*)d_in[7];
    const float* b_psb = (const float*)d_in[8];
    const float* W_hs = (const float*)d_in[9];
    const float* b_hs = (const float*)d_in[10];
    const float* W_hsf = (const float*)d_in[11];
    const float* b_hsf = (const float*)d_in[12];
    const float* W_hsb = (const float*)d_in[13];
    const float* b_hsb = (const float*)d_in[14];
    const float* W_in = (const float*)d_in[15];
    const float* b_in = (const float*)d_in[16];
    const float* W_out = (const float*)d_in[17];
    const float* b_out = (const float*)d_in[18];
    float* y = (float*)d_out;

    cudaFuncSetAttribute(ps_tail_kernel, cudaFuncAttributeMaxDynamicSharedMemorySize, PS_SMEM);
    cudaFuncSetAttribute(hs_tail_kernel, cudaFuncAttributeMaxDynamicSharedMemorySize, HS_SMEM);

    float *p_big, *p_nc, *p_hidden1, *p_hiddenB, *p_tmp, *p_tmp2, *p_h, *p_hidden2,
        *p_colsum, *p_valid1, *p_normx, *p_normB, *p_normh, *p_diag, *p_norm2, *p_valid2,
        *p_colsum2, *p_rowsC, *p_rowsN, *p_cval;
    int* p_cidx;
    __nv_bfloat16 *p_xA3, *p_xB3, *p_hA3, *p_hB3, *p_h1A3, *p_hBB3, *p_hBT3, *p_h2B3,
        *p_h2T3, *p_c2sA3, *p_probsA3, *p_cmT2, *p_xvT2, *p_xT3;
    SYM(p_big, g_big); SYM(p_nc, g_nc); SYM(p_hidden1, g_hidden1); SYM(p_hiddenB, g_hiddenB);
    SYM(p_tmp, g_tmp); SYM(p_tmp2, g_tmp2); SYM(p_h, g_h); SYM(p_hidden2, g_hidden2);
    SYM(p_colsum, g_colsum); SYM(p_valid1, g_valid1); SYM(p_normx, g_normx);
    SYM(p_normB, g_normB); SYM(p_normh, g_normh); SYM(p_diag, g_diag); SYM(p_norm2, g_norm2);
    SYM(p_valid2, g_valid2); SYM(p_colsum2, g_colsum2); SYM(p_rowsC, g_rowsC);
    SYM(p_rowsN, g_rowsN); SYM(p_cval, g_cval);
    { void* t; cudaGetSymbolAddress(&t, g_cidx); p_cidx = (int*)t; }
    SYMB(p_xA3, g_xA3); SYMB(p_xB3, g_xB3); SYMB(p_hA3, g_hA3); SYMB(p_hB3, g_hB3);
    SYMB(p_h1A3, g_h1A3); SYMB(p_hBB3, g_hBB3); SYMB(p_hBT3, g_hBT3); SYMB(p_h2B3, g_h2B3);
    SYMB(p_h2T3, g_h2T3); SYMB(p_c2sA3, g_c2sA3); SYMB(p_probsA3, g_probsA3);
    SYMB(p_cmT2, g_cmT2); SYMB(p_xvT2, g_xvT2); SYMB(p_xT3, g_xT3);
    __nv_bfloat16* p_pT3 = p_probsA3;

    zero_all_kernel<<<NN * HH / 256, 256>>>(p_hidden2, p_hidden1, p_hiddenB, p_colsum,
                                            p_colsum2, p_tmp, p_tmp2, p_rowsC, p_rowsN,
                                            y, b_out);
    xprep_kernel<<<NN, 128>>>(x, p_normx, p_xA3, p_xB3);

    // ---- ps branch ----
    {
        dim3 grid(NN / 32, CC / 32), block(32, 8);
        cm_transpose_kernel<<<grid, block>>>(cm, mv, p_cmT2, p_colsum);
    }
    {
        dim3 grid(NN / 32, HH / 32), block(32, 8);
        xT_kernel<<<grid, block>>>(x, mv, p_xT3, p_xvT2);
    }
    launch_mma(p_cmT2, p_xvT2, p_hidden1, CC, HH, 2 * NN, 32, ep_make(EP_ATOM));
    hidden1post_kernel<<<CC, 128>>>(p_hidden1, p_colsum, p_valid1, p_h1A3);
    launch_mma(p_h1A3, p_xB3, p_nc, CC, NN, 3 * HH, 1, ep_make(EP_NONE));
    softmax_split3_kernel<<<CC, 256>>>(p_nc, p_pT3, NN);
    launch_mma(p_pT3, p_xT3, p_hiddenB, CC, HH, 3 * NN, 32, ep_make(EP_ATOM));
    hiddenBpost_kernel<<<CC, 128>>>(p_hiddenB, p_valid1, p_normB, p_hBB3);
    {
        dim3 grid(CC / 32, HH / 32), block(32, 8);
        transpose_split3_kernel<<<grid, block>>>(p_hiddenB, p_hBT3, CC);
    }
    // cos(x,hiddenB) -> exp(cos) bf16 split3 + rowsums (softmax fused)
    {
        EpiParams e = ep_make(EP_EXP3);
        e.normA = p_normx; e.normB = p_normB; e.validf = p_valid1;
        e.out3 = p_c2sA3; e.rowsum = p_rowsC;
        launch_mma(p_xA3, p_hBB3, p_big, NN, CC, 3 * HH, 1, e);
    }
    launch_mma(p_c2sA3, p_hBT3, p_tmp, NN, HH, 3 * CC, 4, ep_make(EP_ATOM));
    ps_tail_kernel<<<NN / 32, 256, PS_SMEM>>>(p_tmp, p_rowsC, x, W_ps, b_ps, W_psb, b_psb,
                                              W_psf, b_psf, W_out, p_h, y);

    // ---- hs branch ----
    hpost_kernel<<<NN, 128>>>(p_h, p_normh, p_diag, p_hA3, p_hB3);
    {
        EpiParams e = ep_make(EP_TOP3);
        e.normA = p_normh; e.normB = p_normh;
        e.cval = p_cval; e.cidx = p_cidx;
        launch_mma(p_hA3, p_hB3, p_big, NN, NN, 3 * HH, 1, e);
    }
    top3_reduce_scatter<<<NN, 128>>>(p_cval, p_cidx, p_h, p_hidden2, p_colsum2);
    diag_valid_kernel<<<NN, 128>>>(p_colsum2, p_diag, p_h, p_hidden2, p_valid2, p_norm2,
                                   p_h2B3);
    {
        dim3 grid(NN / 32, HH / 32), block(32, 8);
        transpose_split3_kernel<<<grid, block>>>(p_hidden2, p_h2T3, NN);
    }
    // cos(h,hidden2) -> exp(cos) bf16 split3 + rowsums (softmax fused)
    {
        EpiParams e = ep_make(EP_EXP3);
        e.normA = p_normh; e.normB = p_norm2; e.validf = p_valid2;
        e.out3 = p_probsA3; e.rowsum = p_rowsN;
        launch_mma(p_hA3, p_h2B3, p_big, NN, NN, 3 * HH, 1, e);
    }
    launch_mma(p_probsA3, p_h2T3, p_tmp2, NN, HH, 3 * NN, 8, ep_make(EP_ATOM));
    hs_tail_kernel<<<NN / 32, 256, HS_SMEM>>>(p_tmp2, p_rowsN, p_h, W_hs, b_hs, W_hsb, b_hsb,
                                              W_hsf, b_hsf, W_in, b_in, W_out, y);
}

// round 14
// speedup vs baseline: 1.1478x; 1.0116x over previous
#include <cuda_runtime.h>
#include <cuda_bf16.h>
#include <math.h>
#include <stdint.h>

#define NN 4096
#define CC 512
#define HH 128
#define KTOP 3

#define NEG_INF (__int_as_float(0xff800000))

// ---------------- static scratch ----------------
__device__ float g_big[(size_t)NN * NN];
__device__ float g_nc[(size_t)NN * CC];
__device__ float g_hidden1[CC * HH];
__device__ float g_hiddenB[CC * HH];
__device__ float g_tmp[NN * HH];
__device__ float g_tmp2[NN * HH];
__device__ float g_h[NN * HH];
__device__ float g_hidden2[NN * HH];
__device__ float g_colsum[CC];
__device__ float g_valid1[CC];
__device__ float g_normx[NN];
__device__ float g_normB[CC];
__device__ float g_normh[NN];
__device__ float g_diag[NN];
__device__ float g_norm2[NN];
__device__ float g_valid2[NN];
__device__ float g_colsum2[NN];
__device__ float g_rowsC[NN];
__device__ float g_rowsN[NN];
__device__ float g_cval[(size_t)NN * 128 * 3];
__device__ int   g_cidx[(size_t)NN * 128 * 3];

__device__ __nv_bfloat16 g_xA3[(size_t)NN * 3 * HH];
__device__ __nv_bfloat16 g_xB3[(size_t)NN * 3 * HH];
__device__ __nv_bfloat16 g_hA3[(size_t)NN * 3 * HH];
__device__ __nv_bfloat16 g_hB3[(size_t)NN * 3 * HH];
__device__ __nv_bfloat16 g_h1A3[(size_t)CC * 3 * HH];
__device__ __nv_bfloat16 g_hBB3[(size_t)CC * 3 * HH];
__device__ __nv_bfloat16 g_hBT3[(size_t)HH * 3 * CC];
__device__ __nv_bfloat16 g_h2B3[(size_t)NN * 3 * HH];
__device__ __nv_bfloat16 g_h2T3[(size_t)HH * 3 * NN];
__device__ __nv_bfloat16 g_c2sA2[(size_t)NN * 2 * CC];      // [h,l] split-2 (amap)
__device__ __nv_bfloat16 g_probsA2[(size_t)NN * 2 * NN];    // [h,l]; also pT2 [CC,2NN]
__device__ __nv_bfloat16 g_cmT2[(size_t)CC * 2 * NN];
__device__ __nv_bfloat16 g_xvT2[(size_t)HH * 2 * NN];
__device__ __nv_bfloat16 g_xT3[(size_t)HH * 3 * NN];

enum { EP_NONE = 0, EP_COS = 3, EP_ATOM = 6, EP_TOP3 = 7, EP_EXP3 = 8 };

struct EpiParams {
    int mode;
    const float* normA;
    const float* normB;
    const float* validf;
    float* cval;
    int* cidx;
    __nv_bfloat16* out3;
    float* rowsum;
};

__device__ __forceinline__ void ins3(float v, int j, float& b0, float& b1, float& b2,
                                     int& j0, int& j1, int& j2) {
    if (v > b0) { b2 = b1; j2 = j1; b1 = b0; j1 = j0; b0 = v; j0 = j; }
    else if (v > b1) { b2 = b1; j2 = j1; b1 = v; j1 = j; }
    else if (v > b2) { b2 = v; j2 = j; }
}

// ---------------- mma.sync bf16 GEMM (8 warps, 64x32 warp tile, 2-stage) ----------------
// amapL (elements): when nonzero, A is stored as [h,l] with physical row 2*amapL,
// but logical Ktot = 3*amapL: logical k in [0,L) and [L,2L) both map to segment 0,
// [2L,3L) maps to segment 1. Equivalent to the [h,h,l] A-pattern without duplication.
#define SMEM_ROW 80

__device__ __forceinline__ void mma16816(float* c, const uint32_t* a, const uint32_t* b) {
    asm volatile(
        "mma.sync.aligned.m16n8k16.row.col.f32.bf16.bf16.f32 "
        "{%0,%1,%2,%3}, {%4,%5,%6,%7}, {%8,%9}, {%0,%1,%2,%3};"
        : "+f"(c[0]), "+f"(c[1]), "+f"(c[2]), "+f"(c[3])
        : "r"(a[0]), "r"(a[1]), "r"(a[2]), "r"(a[3]), "r"(b[0]), "r"(b[1]));
}

__device__ __forceinline__ void cp_async16(uint32_t smem_addr, const void* gptr) {
    asm volatile("cp.async.cg.shared.global [%0], [%1], 16;" :: "r"(smem_addr), "l"(gptr));
}

__device__ __forceinline__ void ldmatrix_x4(uint32_t* r, uint32_t addr) {
    asm volatile("ldmatrix.sync.aligned.m8n8.x4.shared.b16 {%0,%1,%2,%3}, [%4];"
                 : "=r"(r[0]), "=r"(r[1]), "=r"(r[2]), "=r"(r[3]) : "r"(addr));
}

__global__ void __launch_bounds__(256)
mma_gemm(const __nv_bfloat16* __restrict__ A, const __nv_bfloat16* __restrict__ B,
         float* __restrict__ C, int M, int Nn, int Ktot, int kchunk, int amapL,
         EpiParams ep) {
    __shared__ __align__(16) char As_[2][128 * SMEM_ROW];
    __shared__ __align__(16) char Bs_[2][128 * SMEM_ROW];

    const int tid = threadIdx.x;
    const int lane = tid & 31;
    const int wid = tid >> 5;
    const int warp_m = (wid >> 2) * 64;
    const int warp_n = (wid & 3) * 32;
    const int m0 = blockIdx.y * 128;
    const int n0 = blockIdx.x * 128;
    const int kbase = blockIdx.z * kchunk;
    const int niter = kchunk >> 5;

    const size_t rowbA = (size_t)(amapL ? 2 * amapL : Ktot) * 2;
    const size_t rowbB = (size_t)Ktot * 2;
    const char* Ag = (const char*)A + (size_t)m0 * rowbA;
    const char* Bg = (const char*)(B + (size_t)n0 * Ktot + kbase);
    const uint32_t Lb = (uint32_t)amapL * 2;   // segment byte length

    uint32_t asb = (uint32_t)__cvta_generic_to_shared(&As_[0][0]);
    uint32_t bsb = (uint32_t)__cvta_generic_to_shared(&Bs_[0][0]);

    float acc[4][4][4];
#pragma unroll
    for (int i = 0; i < 4; i++)
#pragma unroll
        for (int j = 0; j < 4; j++)
#pragma unroll
            for (int q = 0; q < 4; q++) acc[i][j][q] = 0.0f;

    const int lm0 = tid >> 2;
    const int lc = tid & 3;

    const int lj = lane >> 3;
    const int lr = lane & 7;
    const uint32_t a_row_off = (uint32_t)(warp_m + (lj & 1) * 8 + lr) * SMEM_ROW +
                               (uint32_t)(lj >> 1) * 16;
    const uint32_t b_row_off = (uint32_t)(warp_n + (lj >> 1) * 8 + lr) * SMEM_ROW +
                               (uint32_t)(lj & 1) * 16;

#define LOAD_TILE(s, it) do { \
    uint32_t lkB = (uint32_t)kbase * 2 + (uint32_t)(it) * 64; \
    uint32_t pkB = (amapL && lkB >= Lb) ? lkB - Lb : lkB; \
    uint32_t soff = (uint32_t)((s) * 128 * SMEM_ROW + lc * 16); \
    cp_async16(asb + soff + lm0 * SMEM_ROW, \
               Ag + (size_t)lm0 * rowbA + pkB + lc * 16); \
    cp_async16(asb + soff + (lm0 + 64) * SMEM_ROW, \
               Ag + (size_t)(lm0 + 64) * rowbA + pkB + lc * 16); \
    size_t goffB = (size_t)(it) * 64 + lc * 16; \
    cp_async16(bsb + soff + lm0 * SMEM_ROW, Bg + (size_t)lm0 * rowbB + goffB); \
    cp_async16(bsb + soff + (lm0 + 64) * SMEM_ROW, Bg + (size_t)(lm0 + 64) * rowbB + goffB); \
    asm volatile("cp.async.commit_group;"); \
} while (0)

    LOAD_TILE(0, 0);

    for (int it = 0; it < niter; it++) {
        int s = it & 1;
        if (it + 1 < niter) {
            LOAD_TILE(s ^ 1, it + 1);
            asm volatile("cp.async.wait_group 1;");
        } else {
            asm volatile("cp.async.wait_group 0;");
        }
        __syncthreads();

        uint32_t abase = asb + (uint32_t)s * (128 * SMEM_ROW) + a_row_off;
        uint32_t bbase = bsb + (uint32_t)s * (128 * SMEM_ROW) + b_row_off;
#pragma unroll
        for (int ks = 0; ks < 32; ks += 16) {
            uint32_t a[4][4], b[4][2];
#pragma unroll
            for (int mi = 0; mi < 4; mi++)
                ldmatrix_x4(a[mi], abase + mi * 16 * SMEM_ROW + ks * 2);
#pragma unroll
            for (int p = 0; p < 2; p++) {
                uint32_t t[4];
                ldmatrix_x4(t, bbase + p * 16 * SMEM_ROW + ks * 2);
                b[p * 2][0] = t[0]; b[p * 2][1] = t[1];
                b[p * 2 + 1][0] = t[2]; b[p * 2 + 1][1] = t[3];
            }
#pragma unroll
            for (int mi = 0; mi < 4; mi++)
#pragma unroll
                for (int ni = 0; ni < 4; ni++) mma16816(acc[mi][ni], a[mi], b[ni]);
        }
        __syncthreads();
    }

    if (ep.mode == EP_TOP3) {
#pragma unroll
        for (int mi = 0; mi < 4; mi++) {
#pragma unroll
            for (int half = 0; half < 2; half++) {
                int m = m0 + warp_m + mi * 16 + (lane >> 2) + half * 8;
                float na = ep.normA[m];
                float b0 = NEG_INF, b1 = NEG_INF, b2 = NEG_INF;
                int j0 = 0, j1 = 0, j2 = 0;
#pragma unroll
                for (int ni = 0; ni < 4; ni++) {
#pragma unroll
                    for (int q = 0; q < 2; q++) {
                        int c = n0 + warp_n + ni * 8 + (lane & 3) * 2 + q;
                        float v = acc[mi][ni][half * 2 + q];
                        float den = na * ep.normB[c];
                        v = v / (den == 0.0f ? 1.0f : den);
                        if (c == m) v = NEG_INF;
                        ins3(v, c, b0, b1, b2, j0, j1, j2);
                    }
                }
#pragma unroll
                for (int msk = 1; msk <= 2; msk <<= 1) {
                    float o0 = __shfl_xor_sync(0xffffffff, b0, msk);
                    int p0 = __shfl_xor_sync(0xffffffff, j0, msk);
                    float o1 = __shfl_xor_sync(0xffffffff, b1, msk);
                    int p1 = __shfl_xor_sync(0xffffffff, j1, msk);
                    float o2 = __shfl_xor_sync(0xffffffff, b2, msk);
                    int p2 = __shfl_xor_sync(0xffffffff, j2, msk);
                    ins3(o0, p0, b0, b1, b2, j0, j1, j2);
                    ins3(o1, p1, b0, b1, b2, j0, j1, j2);
                    ins3(o2, p2, b0, b1, b2, j0, j1, j2);
                }
                if ((lane & 3) == 0) {
                    int chunk = blockIdx.x * 4 + (warp_n >> 5);
                    size_t off = ((size_t)m * 128 + chunk) * 3;
                    ep.cval[off] = b0; ep.cval[off + 1] = b1; ep.cval[off + 2] = b2;
                    ep.cidx[off] = j0; ep.cidx[off + 1] = j1; ep.cidx[off + 2] = j2;
                }
            }
        }
        return;
    }

    if (ep.mode == EP_EXP3) {
        // write exp(cos) as [h,l] split-2 (consumed via amap) + rowsums
#pragma unroll
        for (int mi = 0; mi < 4; mi++) {
#pragma unroll
            for (int half = 0; half < 2; half++) {
                int m = m0 + warp_m + mi * 16 + (lane >> 2) + half * 8;
                float na = ep.normA[m];
                float rs = 0.0f;
#pragma unroll
                for (int ni = 0; ni < 4; ni++) {
                    int c = n0 + warp_n + ni * 8 + (lane & 3) * 2;
                    float v0 = acc[mi][ni][half * 2];
                    float v1 = acc[mi][ni][half * 2 + 1];
                    float d0 = na * ep.normB[c];
                    float d1 = na * ep.normB[c + 1];
                    v0 = v0 / (d0 == 0.0f ? 1.0f : d0);
                    v1 = v1 / (d1 == 0.0f ? 1.0f : d1);
                    float e0 = (ep.validf && ep.validf[c] == 0.0f) ? 0.0f : __expf(v0);
                    float e1 = (ep.validf && ep.validf[c + 1] == 0.0f) ? 0.0f : __expf(v1);
                    rs += e0 + e1;
                    __nv_bfloat16 h0 = __float2bfloat16(e0);
                    __nv_bfloat16 h1 = __float2bfloat16(e1);
                    __nv_bfloat16 l0 = __float2bfloat16(e0 - __bfloat162float(h0));
                    __nv_bfloat16 l1 = __float2bfloat16(e1 - __bfloat162float(h1));
                    __nv_bfloat162 hv; hv.x = h0; hv.y = h1;
                    __nv_bfloat162 lv; lv.x = l0; lv.y = l1;
                    size_t base = (size_t)m * 2 * Nn + c;
                    *(__nv_bfloat162*)&ep.out3[base] = hv;
                    *(__nv_bfloat162*)&ep.out3[base + Nn] = lv;
                }
                rs += __shfl_xor_sync(0xffffffffu, rs, 1);
                rs += __shfl_xor_sync(0xffffffffu, rs, 2);
                if ((lane & 3) == 0) atomicAdd(&ep.rowsum[m], rs);
            }
        }
        return;
    }

#pragma unroll
    for (int mi = 0; mi < 4; mi++) {
        int r0 = m0 + warp_m + mi * 16 + (lane >> 2);
#pragma unroll
        for (int ni = 0; ni < 4; ni++) {
            int c = n0 + warp_n + ni * 8 + (lane & 3) * 2;
#pragma unroll
            for (int half = 0; half < 2; half++) {
                int m = r0 + half * 8;
                float v0 = acc[mi][ni][half * 2];
                float v1 = acc[mi][ni][half * 2 + 1];
                size_t o = (size_t)m * Nn + c;
                if (ep.mode == EP_COS) {
                    float na = ep.normA[m];
                    float d0 = na * ep.normB[c];
                    float d1 = na * ep.normB[c + 1];
                    v0 = v0 / (d0 == 0.0f ? 1.0f : d0);
                    v1 = v1 / (d1 == 0.0f ? 1.0f : d1);
                    if (ep.validf) {
                        if (ep.validf[c] == 0.0f) v0 = NEG_INF;
                        if (ep.validf[c + 1] == 0.0f) v1 = NEG_INF;
                    }
                    *(float2*)&C[o] = make_float2(v0, v1);
                } else if (ep.mode == EP_ATOM) {
                    atomicAdd(&C[o], v0);
                    atomicAdd(&C[o + 1], v1);
                } else {
                    *(float2*)&C[o] = make_float2(v0, v1);
                }
            }
        }
    }
}

// ---------------- transpose kernels ----------------
__global__ void transpose_split3_kernel(const float* __restrict__ X,
                                        __nv_bfloat16* __restrict__ Y, int K) {
    __shared__ float tile[32][33];
    int k0 = blockIdx.x * 32, h0 = blockIdx.y * 32;
    int tx = threadIdx.x, ty = threadIdx.y;
    for (int r = ty; r < 32; r += 8)
        tile[r][tx] = X[(size_t)(k0 + r) * HH + h0 + tx];
    __syncthreads();
    for (int r = ty; r < 32; r += 8) {
        int hcol = h0 + r;
        int k = k0 + tx;
        float v = tile[tx][r];
        __nv_bfloat16 h = __float2bfloat16(v);
        __nv_bfloat16 l = __float2bfloat16(v - __bfloat162float(h));
        size_t base = (size_t)hcol * 3 * K + k;
        Y[base] = h;
        Y[base + K] = l;
        Y[base + 2 * K] = h;
    }
}

__global__ void xT_kernel(const float* __restrict__ X, const float* __restrict__ mv,
                          __nv_bfloat16* __restrict__ T3, __nv_bfloat16* __restrict__ V2) {
    __shared__ float tile[32][33];
    int k0 = blockIdx.x * 32, h0 = blockIdx.y * 32;
    int tx = threadIdx.x, ty = threadIdx.y;
    for (int r = ty; r < 32; r += 8)
        tile[r][tx] = X[(size_t)(k0 + r) * HH + h0 + tx];
    __syncthreads();
    float mvk = mv[k0 + tx];
    for (int r = ty; r < 32; r += 8) {
        int hcol = h0 + r;
        int k = k0 + tx;
        float v = tile[tx][r];
        __nv_bfloat16 h = __float2bfloat16(v);
        __nv_bfloat16 l = __float2bfloat16(v - __bfloat162float(h));
        size_t base = (size_t)hcol * 3 * NN + k;
        T3[base] = h;
        T3[base + NN] = l;
        T3[base + 2 * NN] = h;
        float w = v * mvk;
        __nv_bfloat16 hw = __float2bfloat16(w);
        __nv_bfloat16 lw = __float2bfloat16(w - __bfloat162float(hw));
        size_t base2 = (size_t)hcol * 2 * NN + k;
        V2[base2] = hw;
        V2[base2 + NN] = lw;
    }
}

__global__ void cm_transpose_kernel(const float* __restrict__ cm, const float* __restrict__ mv,
                                    __nv_bfloat16* __restrict__ Y, float* __restrict__ colsum) {
    __shared__ float tile[32][33];
    int k0 = blockIdx.x * 32, c0 = blockIdx.y * 32;
    int tx = threadIdx.x, ty = threadIdx.y;
    for (int r = ty; r < 32; r += 8)
        tile[r][tx] = cm[(size_t)(k0 + r) * CC + c0 + tx];
    __syncthreads();
    float mvk = mv[k0 + tx];
    for (int r = ty; r < 32; r += 8) {
        int c = c0 + r;
        int k = k0 + tx;
        float fv = tile[tx][r];
        __nv_bfloat16 v = __float2bfloat16(fv);
        size_t base = (size_t)c * 2 * NN + k;
        Y[base] = v;
        Y[base + NN] = v;
        float s = fv * mvk;
#pragma unroll
        for (int o = 16; o > 0; o >>= 1) s += __shfl_xor_sync(0xffffffffu, s, o);
        if (tx == 0) atomicAdd(&colsum[c], s);
    }
}

// ---------------- fused tail kernels ----------------
__device__ __forceinline__ void stage_mm(const float* __restrict__ As,
                                         const float* __restrict__ W, float* Ws,
                                         int tid, float acc[2][8]) {
    const int tx = tid & 15, ty = tid >> 4;
#pragma unroll
    for (int i = 0; i < 2; i++)
#pragma unroll
        for (int j = 0; j < 8; j++) acc[i][j] = 0.0f;
    for (int kc = 0; kc < 128; kc += 32) {
        __syncthreads();
#pragma unroll
        for (int l = 0; l < 16; l++) {
            int id = tid + l * 256;
            int n = id >> 5, k = id & 31;
            Ws[k * 132 + n] = W[n * 128 + kc + k];
        }
        __syncthreads();
#pragma unroll
        for (int k = 0; k < 32; k++) {
            float a0 = As[(ty * 2) * 132 + kc + k];
            float a1 = As[(ty * 2 + 1) * 132 + kc + k];
            const float* wr = &Ws[k * 132 + tx * 8];
            float4 w0 = *(const float4*)wr;
            float4 w1 = *(const float4*)(wr + 4);
            float wv[8] = {w0.x, w0.y, w0.z, w0.w, w1.x, w1.y, w1.z, w1.w};
#pragma unroll
            for (int j = 0; j < 8; j++) {
                acc[0][j] = fmaf(a0, wv[j], acc[0][j]);
                acc[1][j] = fmaf(a1, wv[j], acc[1][j]);
            }
        }
    }
}

__global__ void __launch_bounds__(256) ps_tail_kernel(
    const float* __restrict__ tmp, const float* __restrict__ rowsum,
    const float* __restrict__ x,
    const float* __restrict__ W1, const float* __restrict__ b1,
    const float* __restrict__ W2, const float* __restrict__ b2,
    const float* __restrict__ W3, const float* __restrict__ b3,
    const float* __restrict__ Wout, float* __restrict__ h, float* __restrict__ y) {
    extern __shared__ float sm[];
    float* As = sm;
    float* Ps = sm + 32 * 132;
    float* Ws = sm + 2 * 32 * 132;
    int tid = threadIdx.x;
    int m0 = blockIdx.x * 32;
    const int tx = tid & 15, ty = tid >> 4;
#pragma unroll
    for (int l = 0; l < 4; l++) {
        int id = tid + l * 256;
        int m = id >> 5, c4 = id & 31;
        float inv = 1.0f / rowsum[m0 + m];
        float4 v = *(const float4*)&tmp[(size_t)(m0 + m) * 128 + c4 * 4];
        v.x *= inv; v.y *= inv; v.z *= inv; v.w *= inv;
        *(float4*)&As[m * 132 + c4 * 4] = v;
    }
    float acc[2][8];
    stage_mm(As, W1, Ws, tid, acc);
#pragma unroll
    for (int i = 0; i < 2; i++)
#pragma unroll
        for (int j = 0; j < 8; j++)
            Ps[(ty * 2 + i) * 132 + tx * 8 + j] = acc[i][j] + b1[tx * 8 + j];
    stage_mm(Ps, W2, Ws, tid, acc);
#pragma unroll
    for (int i = 0; i < 2; i++) {
        int m = m0 + ty * 2 + i;
#pragma unroll
        for (int j = 0; j < 8; j++) {
            int n = tx * 8 + j;
            h[(size_t)m * 128 + n] = x[(size_t)m * 128 + n] - (acc[i][j] + b2[n]);
        }
    }
    stage_mm(Ps, W3, Ws, tid, acc);
    float d0 = 0.0f, d1 = 0.0f;
#pragma unroll
    for (int j = 0; j < 8; j++) {
        int n = tx * 8 + j;
        float z0 = acc[0][j] + b3[n]; z0 = z0 > 0.0f ? z0 : 0.01f * z0;
        float z1 = acc[1][j] + b3[n]; z1 = z1 > 0.0f ? z1 : 0.01f * z1;
        d0 = fmaf(z0, Wout[n], d0);
        d1 = fmaf(z1, Wout[n], d1);
    }
#pragma unroll
    for (int o = 1; o < 16; o <<= 1) {
        d0 += __shfl_xor_sync(0xffffffff, d0, o);
        d1 += __shfl_xor_sync(0xffffffff, d1, o);
    }
    if (tx == 0) {
        atomicAdd(&y[m0 + ty * 2], d0);
        atomicAdd(&y[m0 + ty * 2 + 1], d1);
    }
}

__global__ void __launch_bounds__(256) hs_tail_kernel(
    const float* __restrict__ tmp2, const float* __restrict__ rowsum,
    const float* __restrict__ h,
    const float* __restrict__ W1, const float* __restrict__ b1,
    const float* __restrict__ W2, const float* __restrict__ b2,
    const float* __restrict__ W3, const float* __restrict__ b3,
    const float* __restrict__ W4, const float* __restrict__ b4,
    const float* __restrict__ Wout, float* __restrict__ y) {
    extern __shared__ float sm[];
    float* As = sm;
    float* Hs = sm + 32 * 132;
    float* Is = sm + 2 * 32 * 132;
    float* Ws = sm + 3 * 32 * 132;
    int tid = threadIdx.x;
    int m0 = blockIdx.x * 32;
    const int tx = tid & 15, ty = tid >> 4;
#pragma unroll
    for (int l = 0; l < 4; l++) {
        int id = tid + l * 256;
        int m = id >> 5, c4 = id & 31;
        float inv = 1.0f / rowsum[m0 + m];
        float4 v = *(const float4*)&tmp2[(size_t)(m0 + m) * 128 + c4 * 4];
        v.x *= inv; v.y *= inv; v.z *= inv; v.w *= inv;
        *(float4*)&As[m * 132 + c4 * 4] = v;
    }
    float acc[2][8];
    stage_mm(As, W1, Ws, tid, acc);
#pragma unroll
    for (int i = 0; i < 2; i++)
#pragma unroll
        for (int j = 0; j < 8; j++)
            Hs[(ty * 2 + i) * 132 + tx * 8 + j] = acc[i][j] + b1[tx * 8 + j];
    stage_mm(Hs, W2, Ws, tid, acc);
#pragma unroll
    for (int i = 0; i < 2; i++) {
        int m = m0 + ty * 2 + i;
#pragma unroll
        for (int j = 0; j < 8; j++) {
            int n = tx * 8 + j;
            Is[(ty * 2 + i) * 132 + n] = h[(size_t)m * 128 + n] - (acc[i][j] + b2[n]);
        }
    }
    float d0 = 0.0f, d1 = 0.0f;
    stage_mm(Hs, W3, Ws, tid, acc);
#pragma unroll
    for (int j = 0; j < 8; j++) {
        int n = tx * 8 + j;
        float z0 = acc[0][j] + b3[n]; z0 = z0 > 0.0f ? z0 : 0.01f * z0;
        float z1 = acc[1][j] + b3[n]; z1 = z1 > 0.0f ? z1 : 0.01f * z1;
        d0 = fmaf(z0, Wout[n], d0);
        d1 = fmaf(z1, Wout[n], d1);
    }
    stage_mm(Is, W4, Ws, tid, acc);
#pragma unroll
    for (int j = 0; j < 8; j++) {
        int n = tx * 8 + j;
        float z0 = acc[0][j] + b4[n]; z0 = z0 > 0.0f ? z0 : 0.01f * z0;
        float z1 = acc[1][j] + b4[n]; z1 = z1 > 0.0f ? z1 : 0.01f * z1;
        d0 = fmaf(z0, Wout[n], d0);
        d1 = fmaf(z1, Wout[n], d1);
    }
#pragma unroll
    for (int o = 1; o < 16; o <<= 1) {
        d0 += __shfl_xor_sync(0xffffffff, d0, o);
        d1 += __shfl_xor_sync(0xffffffff, d1, o);
    }
    if (tx == 0) {
        atomicAdd(&y[m0 + ty * 2], d0);
        atomicAdd(&y[m0 + ty * 2 + 1], d1);
    }
}

// ---------------- fused small kernels ----------------
__global__ void zero_all_kernel(float* h2, float* h1, float* hB, float* cs, float* cs2,
                                float* tmp, float* tmp2, float* rsC, float* rsN,
                                float* y, const float* bout) {
    int i = blockIdx.x * blockDim.x + threadIdx.x;
    h2[i] = 0.0f;
    tmp[i] = 0.0f;
    tmp2[i] = 0.0f;
    if (i < CC * HH) { h1[i] = 0.0f; hB[i] = 0.0f; }
    if (i < CC) cs[i] = 0.0f;
    if (i < NN) { cs2[i] = 0.0f; rsC[i] = 0.0f; rsN[i] = 0.0f; y[i] = bout[0]; }
}

__global__ void xprep_kernel(const float* __restrict__ X, float* __restrict__ norm,
                             __nv_bfloat16* __restrict__ A3, __nv_bfloat16* __restrict__ B3) {
    int m = blockIdx.x, t = threadIdx.x;
    float v = X[(size_t)m * HH + t];
    __shared__ float sh[128];
    sh[t] = v * v;
    __syncthreads();
    for (int o = 64; o > 0; o >>= 1) {
        if (t < o) sh[t] += sh[t + o];
        __syncthreads();
    }
    if (t == 0) norm[m] = sqrtf(sh[0]);
    __nv_bfloat16 h = __float2bfloat16(v);
    __nv_bfloat16 l = __float2bfloat16(v - __bfloat162float(h));
    size_t base = (size_t)m * 3 * HH + t;
    A3[base] = h; A3[base + HH] = h; A3[base + 2 * HH] = l;
    B3[base] = h; B3[base + HH] = l; B3[base + 2 * HH] = h;
}

__global__ void hidden1post_kernel(float* __restrict__ X, const float* __restrict__ colsum,
                                   float* __restrict__ validf, __nv_bfloat16* __restrict__ A3) {
    int m = blockIdx.x, t = threadIdx.x;
    float sc = 1.0f / (colsum[m] + 1.0f);
    float v = X[(size_t)m * HH + t] * sc;
    X[(size_t)m * HH + t] = v;
    __shared__ float sh[128];
    sh[t] = v;
    __syncthreads();
    for (int o = 64; o > 0; o >>= 1) {
        if (t < o) sh[t] += sh[t + o];
        __syncthreads();
    }
    if (t == 0) validf[m] = (sh[0] != 0.0f) ? 1.0f : 0.0f;
    __nv_bfloat16 h = __float2bfloat16(v);
    __nv_bfloat16 l = __float2bfloat16(v - __bfloat162float(h));
    size_t base = (size_t)m * 3 * HH + t;
    A3[base] = h; A3[base + HH] = h; A3[base + 2 * HH] = l;
}

__global__ void hiddenBpost_kernel(float* __restrict__ X, const float* __restrict__ validf,
                                   float* __restrict__ norm, __nv_bfloat16* __restrict__ B3) {
    int m = blockIdx.x, t = threadIdx.x;
    float v = X[(size_t)m * HH + t] * validf[m];
    X[(size_t)m * HH + t] = v;
    __shared__ float sh[128];
    sh[t] = v * v;
    __syncthreads();
    for (int o = 64; o > 0; o >>= 1) {
        if (t < o) sh[t] += sh[t + o];
        __syncthreads();
    }
    if (t == 0) norm[m] = sqrtf(sh[0]);
    __nv_bfloat16 h = __float2bfloat16(v);
    __nv_bfloat16 l = __float2bfloat16(v - __bfloat162float(h));
    size_t base = (size_t)m * 3 * HH + t;
    B3[base] = h; B3[base + HH] = l; B3[base + 2 * HH] = h;
}

__global__ void hpost_kernel(const float* __restrict__ X, float* __restrict__ norm,
                             float* __restrict__ diag, __nv_bfloat16* __restrict__ A3,
                             __nv_bfloat16* __restrict__ B3) {
    int m = blockIdx.x, t = threadIdx.x;
    float v = X[(size_t)m * HH + t];
    __shared__ float sh[128];
    sh[t] = v * v;
    __syncthreads();
    for (int o = 64; o > 0; o >>= 1) {
        if (t < o) sh[t] += sh[t + o];
        __syncthreads();
    }
    if (t == 0) {
        float ss = sh[0];
        float n = sqrtf(ss);
        norm[m] = n;
        float den = n * n;
        diag[m] = (den == 0.0f) ? 0.0f : ss / den;
    }
    __nv_bfloat16 h = __float2bfloat16(v);
    __nv_bfloat16 l = __float2bfloat16(v - __bfloat162float(h));
    size_t base = (size_t)m * 3 * HH + t;
    A3[base] = h; A3[base + HH] = h; A3[base + 2 * HH] = l;
    B3[base] = h; B3[base + HH] = l; B3[base + 2 * HH] = h;
}

// softmax (unbounded logits) writing bf16 [h,l] split-2 (consumed via amap)
__global__ void softmax_split2_kernel(const float* __restrict__ buf,
                                      __nv_bfloat16* __restrict__ out2, int L) {
    int r = blockIdx.x;
    const float* row = buf + (size_t)r * L;
    __nv_bfloat16* orow = out2 + (size_t)r * 2 * L;
    int t = threadIdx.x;
    int V = L >> 8;
    float v[16];
    float mx = NEG_INF;
    for (int u = 0; u < V; u++) {
        v[u] = row[t + (u << 8)];
        mx = fmaxf(mx, v[u]);
    }
    __shared__ float sh[256];
    sh[t] = mx;
    __syncthreads();
    for (int o = 128; o > 0; o >>= 1) {
        if (t < o) sh[t] = fmaxf(sh[t], sh[t + o]);
        __syncthreads();
    }
    mx = sh[0];
    __syncthreads();
    float s = 0.0f;
    for (int u = 0; u < V; u++) {
        v[u] = __expf(v[u] - mx);
        s += v[u];
    }
    sh[t] = s;
    __syncthreads();
    for (int o = 128; o > 0; o >>= 1) {
        if (t < o) sh[t] += sh[t + o];
        __syncthreads();
    }
    float inv = 1.0f / sh[0];
    for (int u = 0; u < V; u++) {
        float p = v[u] * inv;
        __nv_bfloat16 h = __float2bfloat16(p);
        __nv_bfloat16 l = __float2bfloat16(p - __bfloat162float(h));
        int c = t + (u << 8);
        orow[c] = h;
        orow[c + L] = l;
    }
}

__global__ void top3_reduce_scatter(const float* __restrict__ cval, const int* __restrict__ cidx,
                                    const float* __restrict__ h, float* __restrict__ hidden2,
                                    float* __restrict__ colsum2) {
    int i = blockIdx.x, t = threadIdx.x;
    size_t off = ((size_t)i * 128 + t) * 3;
    __shared__ float sv[384];
    __shared__ int si[384];
    __shared__ float bv[KTOP];
    __shared__ int bi[KTOP];
    sv[t] = cval[off]; sv[128 + t] = cval[off + 1]; sv[256 + t] = cval[off + 2];
    si[t] = cidx[off]; si[128 + t] = cidx[off + 1]; si[256 + t] = cidx[off + 2];
    __syncthreads();
    if (t == 0) {
        float a0 = NEG_INF, a1 = NEG_INF, a2 = NEG_INF;
        int j0 = 0, j1 = 0, j2 = 0;
        for (int q = 0; q < 384; q++) ins3(sv[q], si[q], a0, a1, a2, j0, j1, j2);
        ins3(0.0f, i, a0, a1, a2, j0, j1, j2);
        bv[0] = a0; bv[1] = a1; bv[2] = a2;
        bi[0] = j0; bi[1] = j1; bi[2] = j2;
    }
    __syncthreads();
    float hv = h[(size_t)i * HH + t];
#pragma unroll
    for (int k = 0; k < KTOP; k++) {
        int j = bi[k];
        float v = bv[k];
        atomicAdd(&hidden2[(size_t)j * HH + t], v * hv);
        if (t == 0) atomicAdd(&colsum2[j], v);
    }
}

__global__ void diag_valid_kernel(const float* __restrict__ colsum2, const float* __restrict__ diag,
                                  const float* __restrict__ h, float* __restrict__ hidden2,
                                  float* __restrict__ valid2f, float* __restrict__ norm2,
                                  __nv_bfloat16* __restrict__ B3) {
    int j = blockIdx.x;
    int t = threadIdx.x;
    float dterm = (colsum2[j] != 0.0f) ? diag[j] : 0.0f;
    float v = hidden2[(size_t)j * HH + t] + dterm * h[(size_t)j * HH + t];
    __shared__ float shs[128];
    __shared__ float shq[128];
    shs[t] = v;
    shq[t] = v * v;
    __syncthreads();
    for (int o = 64; o > 0; o >>= 1) {
        if (t < o) { shs[t] += shs[t + o]; shq[t] += shq[t + o]; }
        __syncthreads();
    }
    float valid = (shs[0] != 0.0f) ? 1.0f : 0.0f;
    v *= valid;
    hidden2[(size_t)j * HH + t] = v;
    if (t == 0) {
        valid2f[j] = valid;
        norm2[j] = valid * sqrtf(shq[0]);
    }
    __nv_bfloat16 hh = __float2bfloat16(v);
    __nv_bfloat16 l = __float2bfloat16(v - __bfloat162float(hh));
    size_t base = (size_t)j * 3 * HH + t;
    B3[base] = hh; B3[base + HH] = l; B3[base + 2 * HH] = hh;
}

// ---------------- host orchestration ----------------
static EpiParams ep_make(int mode) {
    EpiParams e;
    e.mode = mode;
    e.normA = nullptr; e.normB = nullptr; e.validf = nullptr;
    e.cval = nullptr; e.cidx = nullptr;
    e.out3 = nullptr; e.rowsum = nullptr;
    return e;
}

static void launch_mma(const __nv_bfloat16* A, const __nv_bfloat16* B, float* C,
                       int M, int Nn, int Ktot, int splits, int amapL,
                       const EpiParams& ep) {
    dim3 grid(Nn / 128, M / 128, splits), block(256);
    mma_gemm<<<grid, block>>>(A, B, C, M, Nn, Ktot, Ktot / splits, amapL, ep);
}

#define PS_SMEM (3 * 32 * 132 * 4)
#define HS_SMEM (4 * 32 * 132 * 4)

#define SYM(p, s) do { void* _tmp; cudaGetSymbolAddress(&_tmp, s); p = (float*)_tmp; } while (0)
#define SYMB(p, s) do { void* _tmp; cudaGetSymbolAddress(&_tmp, s); p = (__nv_bfloat16*)_tmp; } while (0)

extern "C" void kernel_launch(void* const* d_in, const int* in_sizes, int n_in,
                              void* d_out, int out_size) {
    const float* x = (const float*)d_in[0];
    const float* cm = (const float*)d_in[1];
    const float* mv = (const float*)d_in[2];
    const float* W_ps = (const float*)d_in[3];
    const float* b_ps = (const float*)d_in[4];
    const float* W_psf = (const float*)d_in[5];
    const float* b_psf = (const float*)d_in[6];
    const float* W_psb = (const float*)d_in[7];
    const float* b_psb = (const float*)d_in[8];
    const float* W_hs = (const float*)d_in[9];
    const float* b_hs = (const float*)d_in[10];
    const float* W_hsf = (const float*)d_in[11];
    const float* b_hsf = (const float*)d_in[12];
    const float* W_hsb = (const float*)d_in[13];
    const float* b_hsb = (const float*)d_in[14];
    const float* W_in = (const float*)d_in[15];
    const float* b_in = (const float*)d_in[16];
    const float* W_out = (const float*)d_in[17];
    const float* b_out = (const float*)d_in[18];
    float* y = (float*)d_out;

    cudaFuncSetAttribute(ps_tail_kernel, cudaFuncAttributeMaxDynamicSharedMemorySize, PS_SMEM);
    cudaFuncSetAttribute(hs_tail_kernel, cudaFuncAttributeMaxDynamicSharedMemorySize, HS_SMEM);

    float *p_big, *p_nc, *p_hidden1, *p_hiddenB, *p_tmp, *p_tmp2, *p_h, *p_hidden2,
        *p_colsum, *p_valid1, *p_normx, *p_normB, *p_normh, *p_diag, *p_norm2, *p_valid2,
        *p_colsum2, *p_rowsC, *p_rowsN, *p_cval;
    int* p_cidx;
    __nv_bfloat16 *p_xA3, *p_xB3, *p_hA3, *p_hB3, *p_h1A3, *p_hBB3, *p_hBT3, *p_h2B3,
        *p_h2T3, *p_c2sA2, *p_probsA2, *p_cmT2, *p_xvT2, *p_xT3;
    SYM(p_big, g_big); SYM(p_nc, g_nc); SYM(p_hidden1, g_hidden1); SYM(p_hiddenB, g_hiddenB);
    SYM(p_tmp, g_tmp); SYM(p_tmp2, g_tmp2); SYM(p_h, g_h); SYM(p_hidden2, g_hidden2);
    SYM(p_colsum, g_colsum); SYM(p_valid1, g_valid1); SYM(p_normx, g_normx);
    SYM(p_normB, g_normB); SYM(p_normh, g_normh); SYM(p_diag, g_diag); SYM(p_norm2, g_norm2);
    SYM(p_valid2, g_valid2); SYM(p_colsum2, g_colsum2); SYM(p_rowsC, g_rowsC);
    SYM(p_rowsN, g_rowsN); SYM(p_cval, g_cval);
    { void* t; cudaGetSymbolAddress(&t, g_cidx); p_cidx = (int*)t; }
    SYMB(p_xA3, g_xA3); SYMB(p_xB3, g_xB3); SYMB(p_hA3, g_hA3); SYMB(p_hB3, g_hB3);
    SYMB(p_h1A3, g_h1A3); SYMB(p_hBB3, g_hBB3); SYMB(p_hBT3, g_hBT3); SYMB(p_h2B3, g_h2B3);
    SYMB(p_h2T3, g_h2T3); SYMB(p_c2sA2, g_c2sA2); SYMB(p_probsA2, g_probsA2);
    SYMB(p_cmT2, g_cmT2); SYMB(p_xvT2, g_xvT2); SYMB(p_xT3, g_xT3);
    __nv_bfloat16* p_pT2 = p_probsA2;   // alias [CC, 2*NN] (ps-phase lifetime)

    zero_all_kernel<<<NN * HH / 256, 256>>>(p_hidden2, p_hidden1, p_hiddenB, p_colsum,
                                            p_colsum2, p_tmp, p_tmp2, p_rowsC, p_rowsN,
                                            y, b_out);
    xprep_kernel<<<NN, 128>>>(x, p_normx, p_xA3, p_xB3);

    // ---- ps branch ----
    {
        dim3 grid(NN / 32, CC / 32), block(32, 8);
        cm_transpose_kernel<<<grid, block>>>(cm, mv, p_cmT2, p_colsum);
    }
    {
        dim3 grid(NN / 32, HH / 32), block(32, 8);
        xT_kernel<<<grid, block>>>(x, mv, p_xT3, p_xvT2);
    }
    launch_mma(p_cmT2, p_xvT2, p_hidden1, CC, HH, 2 * NN, 32, 0, ep_make(EP_ATOM));
    hidden1post_kernel<<<CC, 128>>>(p_hidden1, p_colsum, p_valid1, p_h1A3);
    launch_mma(p_h1A3, p_xB3, p_nc, CC, NN, 3 * HH, 1, 0, ep_make(EP_NONE));
    softmax_split2_kernel<<<CC, 256>>>(p_nc, p_pT2, NN);
    launch_mma(p_pT2, p_xT3, p_hiddenB, CC, HH, 3 * NN, 32, NN, ep_make(EP_ATOM));
    hiddenBpost_kernel<<<CC, 128>>>(p_hiddenB, p_valid1, p_normB, p_hBB3);
    {
        dim3 grid(CC / 32, HH / 32), block(32, 8);
        transpose_split3_kernel<<<grid, block>>>(p_hiddenB, p_hBT3, CC);
    }
    // cos(x,hiddenB) -> exp(cos) bf16 [h,l] + rowsums (softmax fused)
    {
        EpiParams e = ep_make(EP_EXP3);
        e.normA = p_normx; e.normB = p_normB; e.validf = p_valid1;
        e.out3 = p_c2sA2; e.rowsum = p_rowsC;
        launch_mma(p_xA3, p_hBB3, p_big, NN, CC, 3 * HH, 1, 0, e);
    }
    launch_mma(p_c2sA2, p_hBT3, p_tmp, NN, HH, 3 * CC, 4, CC, ep_make(EP_ATOM));
    ps_tail_kernel<<<NN / 32, 256, PS_SMEM>>>(p_tmp, p_rowsC, x, W_ps, b_ps, W_psb, b_psb,
                                              W_psf, b_psf, W_out, p_h, y);

    // ---- hs branch ----
    hpost_kernel<<<NN, 128>>>(p_h, p_normh, p_diag, p_hA3, p_hB3);
    {
        EpiParams e = ep_make(EP_TOP3);
        e.normA = p_normh; e.normB = p_normh;
        e.cval = p_cval; e.cidx = p_cidx;
        launch_mma(p_hA3, p_hB3, p_big, NN, NN, 3 * HH, 1, 0, e);
    }
    top3_reduce_scatter<<<NN, 128>>>(p_cval, p_cidx, p_h, p_hidden2, p_colsum2);
    diag_valid_kernel<<<NN, 128>>>(p_colsum2, p_diag, p_h, p_hidden2, p_valid2, p_norm2,
                                   p_h2B3);
    {
        dim3 grid(NN / 32, HH / 32), block(32, 8);
        transpose_split3_kernel<<<grid, block>>>(p_hidden2, p_h2T3, NN);
    }
    // cos(h,hidden2) -> exp(cos) bf16 [h,l] + rowsums (softmax fused)
    {
        EpiParams e = ep_make(EP_EXP3);
        e.normA = p_normh; e.normB = p_norm2; e.validf = p_valid2;
        e.out3 = p_probsA2; e.rowsum = p_rowsN;
        launch_mma(p_hA3, p_h2B3, p_big, NN, NN, 3 * HH, 1, 0, e);
    }
    launch_mma(p_probsA2, p_h2T3, p_tmp2, NN, HH, 3 * NN, 8, NN, ep_make(EP_ATOM));
    hs_tail_kernel<<<NN / 32, 256, HS_SMEM>>>(p_tmp2, p_rowsN, p_h, W_hs, b_hs, W_hsb, b_hsb,
                                              W_hsf, b_hsf, W_in, b_in, W_out, y);
}

// round 15
// speedup vs baseline: 1.1556x; 1.0068x over previous
#include <cuda_runtime.h>
#include <cuda_bf16.h>
#include <math.h>
#include <stdint.h>

#define NN 4096
#define CC 512
#define HH 128
#define KTOP 3

#define NEG_INF (__int_as_float(0xff800000))

// ---------------- static scratch ----------------
__device__ float g_big[(size_t)NN * NN];
__device__ float g_nc[(size_t)NN * CC];
__device__ float g_hidden1[CC * HH];
__device__ float g_hiddenB[CC * HH];
__device__ float g_tmp[NN * HH];
__device__ float g_tmp2[NN * HH];
__device__ float g_h[NN * HH];
__device__ float g_hidden2[NN * HH];
__device__ float g_colsum[CC];
__device__ float g_valid1[CC];
__device__ float g_normx[NN];
__device__ float g_normB[CC];
__device__ float g_normh[NN];
__device__ float g_diag[NN];
__device__ float g_norm2[NN];
__device__ float g_valid2[NN];
__device__ float g_colsum2[NN];
__device__ float g_rowsC[NN];
__device__ float g_rowsN[NN];
__device__ float g_cval[(size_t)NN * 128 * 3];
__device__ int   g_cidx[(size_t)NN * 128 * 3];

// all split operands stored [h,l] (split-2), consumed via A-map [h,h,l] / B-map [h,l,h]
__device__ __nv_bfloat16 g_x2[(size_t)NN * 2 * HH];
__device__ __nv_bfloat16 g_h2b[(size_t)NN * 2 * HH];
__device__ __nv_bfloat16 g_h1b[(size_t)CC * 2 * HH];
__device__ __nv_bfloat16 g_hBb[(size_t)CC * 2 * HH];
__device__ __nv_bfloat16 g_h22b[(size_t)NN * 2 * HH];
__device__ __nv_bfloat16 g_hBT2[(size_t)HH * 2 * CC];
__device__ __nv_bfloat16 g_h2T2[(size_t)HH * 2 * NN];
__device__ __nv_bfloat16 g_xT2[(size_t)HH * 2 * NN];
__device__ __nv_bfloat16 g_xvT2[(size_t)HH * 2 * NN];
__device__ __nv_bfloat16 g_c2sA2[(size_t)NN * 2 * CC];
__device__ __nv_bfloat16 g_probsA2[(size_t)NN * 2 * NN];
__device__ __nv_bfloat16 g_cmT2[(size_t)CC * 2 * NN];

enum { EP_NONE = 0, EP_ATOM = 6, EP_TOP3 = 7, EP_EXP3 = 8 };

struct EpiParams {
    int mode;
    const float* normA;
    const float* normB;
    const float* validf;
    float* cval;
    int* cidx;
    __nv_bfloat16* out3;
    float* rowsum;
};

__device__ __forceinline__ void ins3(float v, int j, float& b0, float& b1, float& b2,
                                     int& j0, int& j1, int& j2) {
    if (v > b0) { b2 = b1; j2 = j1; b1 = b0; j1 = j0; b0 = v; j0 = j; }
    else if (v > b1) { b2 = b1; j2 = j1; b1 = v; j1 = j; }
    else if (v > b2) { b2 = v; j2 = j; }
}

// ---------------- mma.sync bf16 GEMM (8 warps, 64x32 warp tile, 2-stage) ----------------
// mapL  != 0: A stored [h,l] (phys 2L), logical K=3L with pattern [h,h,l]:
//             physk = lk < L ? lk : lk - L
// bmapL != 0: B stored [h,l] (phys 2L), logical K=3L with pattern [h,l,h]:
//             physk = lk < 2L ? lk : lk - 2L
#define SMEM_ROW 80

__device__ __forceinline__ void mma16816(float* c, const uint32_t* a, const uint32_t* b) {
    asm volatile(
        "mma.sync.aligned.m16n8k16.row.col.f32.bf16.bf16.f32 "
        "{%0,%1,%2,%3}, {%4,%5,%6,%7}, {%8,%9}, {%0,%1,%2,%3};"
        : "+f"(c[0]), "+f"(c[1]), "+f"(c[2]), "+f"(c[3])
        : "r"(a[0]), "r"(a[1]), "r"(a[2]), "r"(a[3]), "r"(b[0]), "r"(b[1]));
}

__device__ __forceinline__ void cp_async16(uint32_t smem_addr, const void* gptr) {
    asm volatile("cp.async.cg.shared.global [%0], [%1], 16;" :: "r"(smem_addr), "l"(gptr));
}

__device__ __forceinline__ void ldmatrix_x4(uint32_t* r, uint32_t addr) {
    asm volatile("ldmatrix.sync.aligned.m8n8.x4.shared.b16 {%0,%1,%2,%3}, [%4];"
                 : "=r"(r[0]), "=r"(r[1]), "=r"(r[2]), "=r"(r[3]) : "r"(addr));
}

__global__ void __launch_bounds__(256)
mma_gemm(const __nv_bfloat16* __restrict__ A, const __nv_bfloat16* __restrict__ B,
         float* __restrict__ C, int M, int Nn, int Ktot, int kchunk, int mapL, int bmapL,
         EpiParams ep) {
    __shared__ __align__(16) char As_[2][128 * SMEM_ROW];
    __shared__ __align__(16) char Bs_[2][128 * SMEM_ROW];

    const int tid = threadIdx.x;
    const int lane = tid & 31;
    const int wid = tid >> 5;
    const int warp_m = (wid >> 2) * 64;
    const int warp_n = (wid & 3) * 32;
    const int m0 = blockIdx.y * 128;
    const int n0 = blockIdx.x * 128;
    const int kbase = blockIdx.z * kchunk;
    const int niter = kchunk >> 5;

    const size_t rowbA = (size_t)(mapL ? 2 * mapL : Ktot) * 2;
    const size_t rowbB = (size_t)(bmapL ? 2 * bmapL : Ktot) * 2;
    const char* Ag = (const char*)A + (size_t)m0 * rowbA;
    const char* Bg = (const char*)B + (size_t)n0 * rowbB;
    const uint32_t LbA = (uint32_t)mapL * 2;
    const uint32_t LbB2 = (uint32_t)bmapL * 4;

    uint32_t asb = (uint32_t)__cvta_generic_to_shared(&As_[0][0]);
    uint32_t bsb = (uint32_t)__cvta_generic_to_shared(&Bs_[0][0]);

    float acc[4][4][4];
#pragma unroll
    for (int i = 0; i < 4; i++)
#pragma unroll
        for (int j = 0; j < 4; j++)
#pragma unroll
            for (int q = 0; q < 4; q++) acc[i][j][q] = 0.0f;

    const int lm0 = tid >> 2;
    const int lc = tid & 3;

    const int lj = lane >> 3;
    const int lr = lane & 7;
    const uint32_t a_row_off = (uint32_t)(warp_m + (lj & 1) * 8 + lr) * SMEM_ROW +
                               (uint32_t)(lj >> 1) * 16;
    const uint32_t b_row_off = (uint32_t)(warp_n + (lj >> 1) * 8 + lr) * SMEM_ROW +
                               (uint32_t)(lj & 1) * 16;

#define LOAD_TILE(s, it) do { \
    uint32_t lkB = (uint32_t)kbase * 2 + (uint32_t)(it) * 64; \
    uint32_t pA = (mapL && lkB >= LbA) ? lkB - LbA : lkB; \
    uint32_t pB = (bmapL && lkB >= LbB2) ? lkB - LbB2 : lkB; \
    uint32_t soff = (uint32_t)((s) * 128 * SMEM_ROW + lc * 16); \
    cp_async16(asb + soff + lm0 * SMEM_ROW, \
               Ag + (size_t)lm0 * rowbA + pA + lc * 16); \
    cp_async16(asb + soff + (lm0 + 64) * SMEM_ROW, \
               Ag + (size_t)(lm0 + 64) * rowbA + pA + lc * 16); \
    cp_async16(bsb + soff + lm0 * SMEM_ROW, \
               Bg + (size_t)lm0 * rowbB + pB + lc * 16); \
    cp_async16(bsb + soff + (lm0 + 64) * SMEM_ROW, \
               Bg + (size_t)(lm0 + 64) * rowbB + pB + lc * 16); \
    asm volatile("cp.async.commit_group;"); \
} while (0)

    LOAD_TILE(0, 0);

    for (int it = 0; it < niter; it++) {
        int s = it & 1;
        if (it + 1 < niter) {
            LOAD_TILE(s ^ 1, it + 1);
            asm volatile("cp.async.wait_group 1;");
        } else {
            asm volatile("cp.async.wait_group 0;");
        }
        __syncthreads();

        uint32_t abase = asb + (uint32_t)s * (128 * SMEM_ROW) + a_row_off;
        uint32_t bbase = bsb + (uint32_t)s * (128 * SMEM_ROW) + b_row_off;
#pragma unroll
        for (int ks = 0; ks < 32; ks += 16) {
            uint32_t a[4][4], b[4][2];
#pragma unroll
            for (int mi = 0; mi < 4; mi++)
                ldmatrix_x4(a[mi], abase + mi * 16 * SMEM_ROW + ks * 2);
#pragma unroll
            for (int p = 0; p < 2; p++) {
                uint32_t t[4];
                ldmatrix_x4(t, bbase + p * 16 * SMEM_ROW + ks * 2);
                b[p * 2][0] = t[0]; b[p * 2][1] = t[1];
                b[p * 2 + 1][0] = t[2]; b[p * 2 + 1][1] = t[3];
            }
#pragma unroll
            for (int mi = 0; mi < 4; mi++)
#pragma unroll
                for (int ni = 0; ni < 4; ni++) mma16816(acc[mi][ni], a[mi], b[ni]);
        }
        __syncthreads();
    }

    if (ep.mode == EP_TOP3) {
#pragma unroll
        for (int mi = 0; mi < 4; mi++) {
#pragma unroll
            for (int half = 0; half < 2; half++) {
                int m = m0 + warp_m + mi * 16 + (lane >> 2) + half * 8;
                float na = ep.normA[m];
                float b0 = NEG_INF, b1 = NEG_INF, b2 = NEG_INF;
                int j0 = 0, j1 = 0, j2 = 0;
#pragma unroll
                for (int ni = 0; ni < 4; ni++) {
#pragma unroll
                    for (int q = 0; q < 2; q++) {
                        int c = n0 + warp_n + ni * 8 + (lane & 3) * 2 + q;
                        float v = acc[mi][ni][half * 2 + q];
                        float den = na * ep.normB[c];
                        v = v / (den == 0.0f ? 1.0f : den);
                        if (c == m) v = NEG_INF;
                        ins3(v, c, b0, b1, b2, j0, j1, j2);
                    }
                }
#pragma unroll
                for (int msk = 1; msk <= 2; msk <<= 1) {
                    float o0 = __shfl_xor_sync(0xffffffff, b0, msk);
                    int p0 = __shfl_xor_sync(0xffffffff, j0, msk);
                    float o1 = __shfl_xor_sync(0xffffffff, b1, msk);
                    int p1 = __shfl_xor_sync(0xffffffff, j1, msk);
                    float o2 = __shfl_xor_sync(0xffffffff, b2, msk);
                    int p2 = __shfl_xor_sync(0xffffffff, j2, msk);
                    ins3(o0, p0, b0, b1, b2, j0, j1, j2);
                    ins3(o1, p1, b0, b1, b2, j0, j1, j2);
                    ins3(o2, p2, b0, b1, b2, j0, j1, j2);
                }
                if ((lane & 3) == 0) {
                    int chunk = blockIdx.x * 4 + (warp_n >> 5);
                    size_t off = ((size_t)m * 128 + chunk) * 3;
                    ep.cval[off] = b0; ep.cval[off + 1] = b1; ep.cval[off + 2] = b2;
                    ep.cidx[off] = j0; ep.cidx[off + 1] = j1; ep.cidx[off + 2] = j2;
                }
            }
        }
        return;
    }

    if (ep.mode == EP_EXP3) {
#pragma unroll
        for (int mi = 0; mi < 4; mi++) {
#pragma unroll
            for (int half = 0; half < 2; half++) {
                int m = m0 + warp_m + mi * 16 + (lane >> 2) + half * 8;
                float na = ep.normA[m];
                float rs = 0.0f;
#pragma unroll
                for (int ni = 0; ni < 4; ni++) {
                    int c = n0 + warp_n + ni * 8 + (lane & 3) * 2;
                    float v0 = acc[mi][ni][half * 2];
                    float v1 = acc[mi][ni][half * 2 + 1];
                    float d0 = na * ep.normB[c];
                    float d1 = na * ep.normB[c + 1];
                    v0 = v0 / (d0 == 0.0f ? 1.0f : d0);
                    v1 = v1 / (d1 == 0.0f ? 1.0f : d1);
                    float e0 = (ep.validf && ep.validf[c] == 0.0f) ? 0.0f : __expf(v0);
                    float e1 = (ep.validf && ep.validf[c + 1] == 0.0f) ? 0.0f : __expf(v1);
                    rs += e0 + e1;
                    __nv_bfloat16 h0 = __float2bfloat16(e0);
                    __nv_bfloat16 h1 = __float2bfloat16(e1);
                    __nv_bfloat16 l0 = __float2bfloat16(e0 - __bfloat162float(h0));
                    __nv_bfloat16 l1 = __float2bfloat16(e1 - __bfloat162float(h1));
                    __nv_bfloat162 hv; hv.x = h0; hv.y = h1;
                    __nv_bfloat162 lv; lv.x = l0; lv.y = l1;
                    size_t base = (size_t)m * 2 * Nn + c;
                    *(__nv_bfloat162*)&ep.out3[base] = hv;
                    *(__nv_bfloat162*)&ep.out3[base + Nn] = lv;
                }
                rs += __shfl_xor_sync(0xffffffffu, rs, 1);
                rs += __shfl_xor_sync(0xffffffffu, rs, 2);
                if ((lane & 3) == 0) atomicAdd(&ep.rowsum[m], rs);
            }
        }
        return;
    }

#pragma unroll
    for (int mi = 0; mi < 4; mi++) {
        int r0 = m0 + warp_m + mi * 16 + (lane >> 2);
#pragma unroll
        for (int ni = 0; ni < 4; ni++) {
            int c = n0 + warp_n + ni * 8 + (lane & 3) * 2;
#pragma unroll
            for (int half = 0; half < 2; half++) {
                int m = r0 + half * 8;
                float v0 = acc[mi][ni][half * 2];
                float v1 = acc[mi][ni][half * 2 + 1];
                size_t o = (size_t)m * Nn + c;
                if (ep.mode == EP_ATOM) {
                    atomicAdd(&C[o], v0);
                    atomicAdd(&C[o + 1], v1);
                } else {
                    *(float2*)&C[o] = make_float2(v0, v1);
                }
            }
        }
    }
}

// ---------------- transpose kernels ----------------
// X [K, HH] fp32 -> Y [HH, 2K] bf16 [h,l]
__global__ void transpose_split2_kernel(const float* __restrict__ X,
                                        __nv_bfloat16* __restrict__ Y, int K) {
    __shared__ float tile[32][33];
    int k0 = blockIdx.x * 32, h0 = blockIdx.y * 32;
    int tx = threadIdx.x, ty = threadIdx.y;
    for (int r = ty; r < 32; r += 8)
        tile[r][tx] = X[(size_t)(k0 + r) * HH + h0 + tx];
    __syncthreads();
    for (int r = ty; r < 32; r += 8) {
        int hcol = h0 + r;
        int k = k0 + tx;
        float v = tile[tx][r];
        __nv_bfloat16 h = __float2bfloat16(v);
        __nv_bfloat16 l = __float2bfloat16(v - __bfloat162float(h));
        size_t base = (size_t)hcol * 2 * K + k;
        Y[base] = h;
        Y[base + K] = l;
    }
}

// x -> xT2 [h,l] AND xvT2 (mv-weighted, [h,l]) in one pass
__global__ void xT_kernel(const float* __restrict__ X, const float* __restrict__ mv,
                          __nv_bfloat16* __restrict__ T2, __nv_bfloat16* __restrict__ V2) {
    __shared__ float tile[32][33];
    int k0 = blockIdx.x * 32, h0 = blockIdx.y * 32;
    int tx = threadIdx.x, ty = threadIdx.y;
    for (int r = ty; r < 32; r += 8)
        tile[r][tx] = X[(size_t)(k0 + r) * HH + h0 + tx];
    __syncthreads();
    float mvk = mv[k0 + tx];
    for (int r = ty; r < 32; r += 8) {
        int hcol = h0 + r;
        int k = k0 + tx;
        float v = tile[tx][r];
        __nv_bfloat16 h = __float2bfloat16(v);
        __nv_bfloat16 l = __float2bfloat16(v - __bfloat162float(h));
        size_t base = (size_t)hcol * 2 * NN + k;
        T2[base] = h;
        T2[base + NN] = l;
        float w = v * mvk;
        __nv_bfloat16 hw = __float2bfloat16(w);
        __nv_bfloat16 lw = __float2bfloat16(w - __bfloat162float(hw));
        V2[base] = hw;
        V2[base + NN] = lw;
    }
}

__global__ void cm_transpose_kernel(const float* __restrict__ cm, const float* __restrict__ mv,
                                    __nv_bfloat16* __restrict__ Y, float* __restrict__ colsum) {
    __shared__ float tile[32][33];
    int k0 = blockIdx.x * 32, c0 = blockIdx.y * 32;
    int tx = threadIdx.x, ty = threadIdx.y;
    for (int r = ty; r < 32; r += 8)
        tile[r][tx] = cm[(size_t)(k0 + r) * CC + c0 + tx];
    __syncthreads();
    float mvk = mv[k0 + tx];
    for (int r = ty; r < 32; r += 8) {
        int c = c0 + r;
        int k = k0 + tx;
        float fv = tile[tx][r];
        __nv_bfloat16 v = __float2bfloat16(fv);
        size_t base = (size_t)c * 2 * NN + k;
        Y[base] = v;
        Y[base + NN] = v;
        float s = fv * mvk;
#pragma unroll
        for (int o = 16; o > 0; o >>= 1) s += __shfl_xor_sync(0xffffffffu, s, o);
        if (tx == 0) atomicAdd(&colsum[c], s);
    }
}

// ---------------- fused tail kernels ----------------
__device__ __forceinline__ void stage_mm(const float* __restrict__ As,
                                         const float* __restrict__ W, float* Ws,
                                         int tid, float acc[2][8]) {
    const int tx = tid & 15, ty = tid >> 4;
#pragma unroll
    for (int i = 0; i < 2; i++)
#pragma unroll
        for (int j = 0; j < 8; j++) acc[i][j] = 0.0f;
    for (int kc = 0; kc < 128; kc += 32) {
        __syncthreads();
#pragma unroll
        for (int l = 0; l < 16; l++) {
            int id = tid + l * 256;
            int n = id >> 5, k = id & 31;
            Ws[k * 132 + n] = W[n * 128 + kc + k];
        }
        __syncthreads();
#pragma unroll
        for (int k = 0; k < 32; k++) {
            float a0 = As[(ty * 2) * 132 + kc + k];
            float a1 = As[(ty * 2 + 1) * 132 + kc + k];
            const float* wr = &Ws[k * 132 + tx * 8];
            float4 w0 = *(const float4*)wr;
            float4 w1 = *(const float4*)(wr + 4);
            float wv[8] = {w0.x, w0.y, w0.z, w0.w, w1.x, w1.y, w1.z, w1.w};
#pragma unroll
            for (int j = 0; j < 8; j++) {
                acc[0][j] = fmaf(a0, wv[j], acc[0][j]);
                acc[1][j] = fmaf(a1, wv[j], acc[1][j]);
            }
        }
    }
}

// ps tail + fused hpost: writes h fp32, h2 bf16 [h,l], normh, diag
__global__ void __launch_bounds__(256) ps_tail_kernel(
    const float* __restrict__ tmp, const float* __restrict__ rowsum,
    const float* __restrict__ x,
    const float* __restrict__ W1, const float* __restrict__ b1,
    const float* __restrict__ W2, const float* __restrict__ b2,
    const float* __restrict__ W3, const float* __restrict__ b3,
    const float* __restrict__ Wout, float* __restrict__ h,
    __nv_bfloat16* __restrict__ h2b, float* __restrict__ normh, float* __restrict__ diag,
    float* __restrict__ y) {
    extern __shared__ float sm[];
    float* As = sm;
    float* Ps = sm + 32 * 132;
    float* Ws = sm + 2 * 32 * 132;
    int tid = threadIdx.x;
    int m0 = blockIdx.x * 32;
    const int tx = tid & 15, ty = tid >> 4;
#pragma unroll
    for (int l = 0; l < 4; l++) {
        int id = tid + l * 256;
        int m = id >> 5, c4 = id & 31;
        float inv = 1.0f / rowsum[m0 + m];
        float4 v = *(const float4*)&tmp[(size_t)(m0 + m) * 128 + c4 * 4];
        v.x *= inv; v.y *= inv; v.z *= inv; v.w *= inv;
        *(float4*)&As[m * 132 + c4 * 4] = v;
    }
    float acc[2][8];
    stage_mm(As, W1, Ws, tid, acc);
#pragma unroll
    for (int i = 0; i < 2; i++)
#pragma unroll
        for (int j = 0; j < 8; j++)
            Ps[(ty * 2 + i) * 132 + tx * 8 + j] = acc[i][j] + b1[tx * 8 + j];
    stage_mm(Ps, W2, Ws, tid, acc);
    float ss[2] = {0.0f, 0.0f};
#pragma unroll
    for (int i = 0; i < 2; i++) {
        int m = m0 + ty * 2 + i;
#pragma unroll
        for (int j = 0; j < 8; j++) {
            int n = tx * 8 + j;
            float hv = x[(size_t)m * 128 + n] - (acc[i][j] + b2[n]);
            h[(size_t)m * 128 + n] = hv;
            ss[i] += hv * hv;
            __nv_bfloat16 hb = __float2bfloat16(hv);
            __nv_bfloat16 lb = __float2bfloat16(hv - __bfloat162float(hb));
            size_t base = (size_t)m * 2 * HH + n;
            h2b[base] = hb;
            h2b[base + HH] = lb;
        }
    }
#pragma unroll
    for (int o = 1; o < 16; o <<= 1) {
        ss[0] += __shfl_xor_sync(0xffffffffu, ss[0], o);
        ss[1] += __shfl_xor_sync(0xffffffffu, ss[1], o);
    }
    if (tx == 0) {
#pragma unroll
        for (int i = 0; i < 2; i++) {
            int m = m0 + ty * 2 + i;
            float s = ss[i];
            float n = sqrtf(s);
            normh[m] = n;
            float den = n * n;
            diag[m] = (den == 0.0f) ? 0.0f : s / den;
        }
    }
    stage_mm(Ps, W3, Ws, tid, acc);
    float d0 = 0.0f, d1 = 0.0f;
#pragma unroll
    for (int j = 0; j < 8; j++) {
        int n = tx * 8 + j;
        float z0 = acc[0][j] + b3[n]; z0 = z0 > 0.0f ? z0 : 0.01f * z0;
        float z1 = acc[1][j] + b3[n]; z1 = z1 > 0.0f ? z1 : 0.01f * z1;
        d0 = fmaf(z0, Wout[n], d0);
        d1 = fmaf(z1, Wout[n], d1);
    }
#pragma unroll
    for (int o = 1; o < 16; o <<= 1) {
        d0 += __shfl_xor_sync(0xffffffff, d0, o);
        d1 += __shfl_xor_sync(0xffffffff, d1, o);
    }
    if (tx == 0) {
        atomicAdd(&y[m0 + ty * 2], d0);
        atomicAdd(&y[m0 + ty * 2 + 1], d1);
    }
}

__global__ void __launch_bounds__(256) hs_tail_kernel(
    const float* __restrict__ tmp2, const float* __restrict__ rowsum,
    const float* __restrict__ h,
    const float* __restrict__ W1, const float* __restrict__ b1,
    const float* __restrict__ W2, const float* __restrict__ b2,
    const float* __restrict__ W3, const float* __restrict__ b3,
    const float* __restrict__ W4, const float* __restrict__ b4,
    const float* __restrict__ Wout, float* __restrict__ y) {
    extern __shared__ float sm[];
    float* As = sm;
    float* Hs = sm + 32 * 132;
    float* Is = sm + 2 * 32 * 132;
    float* Ws = sm + 3 * 32 * 132;
    int tid = threadIdx.x;
    int m0 = blockIdx.x * 32;
    const int tx = tid & 15, ty = tid >> 4;
#pragma unroll
    for (int l = 0; l < 4; l++) {
        int id = tid + l * 256;
        int m = id >> 5, c4 = id & 31;
        float inv = 1.0f / rowsum[m0 + m];
        float4 v = *(const float4*)&tmp2[(size_t)(m0 + m) * 128 + c4 * 4];
        v.x *= inv; v.y *= inv; v.z *= inv; v.w *= inv;
        *(float4*)&As[m * 132 + c4 * 4] = v;
    }
    float acc[2][8];
    stage_mm(As, W1, Ws, tid, acc);
#pragma unroll
    for (int i = 0; i < 2; i++)
#pragma unroll
        for (int j = 0; j < 8; j++)
            Hs[(ty * 2 + i) * 132 + tx * 8 + j] = acc[i][j] + b1[tx * 8 + j];
    stage_mm(Hs, W2, Ws, tid, acc);
#pragma unroll
    for (int i = 0; i < 2; i++) {
        int m = m0 + ty * 2 + i;
#pragma unroll
        for (int j = 0; j < 8; j++) {
            int n = tx * 8 + j;
            Is[(ty * 2 + i) * 132 + n] = h[(size_t)m * 128 + n] - (acc[i][j] + b2[n]);
        }
    }
    float d0 = 0.0f, d1 = 0.0f;
    stage_mm(Hs, W3, Ws, tid, acc);
#pragma unroll
    for (int j = 0; j < 8; j++) {
        int n = tx * 8 + j;
        float z0 = acc[0][j] + b3[n]; z0 = z0 > 0.0f ? z0 : 0.01f * z0;
        float z1 = acc[1][j] + b3[n]; z1 = z1 > 0.0f ? z1 : 0.01f * z1;
        d0 = fmaf(z0, Wout[n], d0);
        d1 = fmaf(z1, Wout[n], d1);
    }
    stage_mm(Is, W4, Ws, tid, acc);
#pragma unroll
    for (int j = 0; j < 8; j++) {
        int n = tx * 8 + j;
        float z0 = acc[0][j] + b4[n]; z0 = z0 > 0.0f ? z0 : 0.01f * z0;
        float z1 = acc[1][j] + b4[n]; z1 = z1 > 0.0f ? z1 : 0.01f * z1;
        d0 = fmaf(z0, Wout[n], d0);
        d1 = fmaf(z1, Wout[n], d1);
    }
#pragma unroll
    for (int o = 1; o < 16; o <<= 1) {
        d0 += __shfl_xor_sync(0xffffffff, d0, o);
        d1 += __shfl_xor_sync(0xffffffff, d1, o);
    }
    if (tx == 0) {
        atomicAdd(&y[m0 + ty * 2], d0);
        atomicAdd(&y[m0 + ty * 2 + 1], d1);
    }
}

// ---------------- fused small kernels ----------------
__global__ void zero_all_kernel(float* h2, float* h1, float* hB, float* cs, float* cs2,
                                float* tmp, float* tmp2, float* rsC, float* rsN,
                                float* y, const float* bout) {
    int i = blockIdx.x * blockDim.x + threadIdx.x;
    h2[i] = 0.0f;
    tmp[i] = 0.0f;
    tmp2[i] = 0.0f;
    if (i < CC * HH) { h1[i] = 0.0f; hB[i] = 0.0f; }
    if (i < CC) cs[i] = 0.0f;
    if (i < NN) { cs2[i] = 0.0f; rsC[i] = 0.0f; rsN[i] = 0.0f; y[i] = bout[0]; }
}

// x: norm + [h,l] split2
__global__ void xprep_kernel(const float* __restrict__ X, float* __restrict__ norm,
                             __nv_bfloat16* __restrict__ X2) {
    int m = blockIdx.x, t = threadIdx.x;
    float v = X[(size_t)m * HH + t];
    __shared__ float sh[128];
    sh[t] = v * v;
    __syncthreads();
    for (int o = 64; o > 0; o >>= 1) {
        if (t < o) sh[t] += sh[t + o];
        __syncthreads();
    }
    if (t == 0) norm[m] = sqrtf(sh[0]);
    __nv_bfloat16 h = __float2bfloat16(v);
    __nv_bfloat16 l = __float2bfloat16(v - __bfloat162float(h));
    size_t base = (size_t)m * 2 * HH + t;
    X2[base] = h;
    X2[base + HH] = l;
}

__global__ void hidden1post_kernel(float* __restrict__ X, const float* __restrict__ colsum,
                                   float* __restrict__ validf, __nv_bfloat16* __restrict__ A2) {
    int m = blockIdx.x, t = threadIdx.x;
    float sc = 1.0f / (colsum[m] + 1.0f);
    float v = X[(size_t)m * HH + t] * sc;
    __shared__ float sh[128];
    sh[t] = v;
    __syncthreads();
    for (int o = 64; o > 0; o >>= 1) {
        if (t < o) sh[t] += sh[t + o];
        __syncthreads();
    }
    if (t == 0) validf[m] = (sh[0] != 0.0f) ? 1.0f : 0.0f;
    __nv_bfloat16 h = __float2bfloat16(v);
    __nv_bfloat16 l = __float2bfloat16(v - __bfloat162float(h));
    size_t base = (size_t)m * 2 * HH + t;
    A2[base] = h;
    A2[base + HH] = l;
}

__global__ void hiddenBpost_kernel(float* __restrict__ X, const float* __restrict__ validf,
                                   float* __restrict__ norm, __nv_bfloat16* __restrict__ B2) {
    int m = blockIdx.x, t = threadIdx.x;
    float v = X[(size_t)m * HH + t] * validf[m];
    X[(size_t)m * HH + t] = v;
    __shared__ float sh[128];
    sh[t] = v * v;
    __syncthreads();
    for (int o = 64; o > 0; o >>= 1) {
        if (t < o) sh[t] += sh[t + o];
        __syncthreads();
    }
    if (t == 0) norm[m] = sqrtf(sh[0]);
    __nv_bfloat16 h = __float2bfloat16(v);
    __nv_bfloat16 l = __float2bfloat16(v - __bfloat162float(h));
    size_t base = (size_t)m * 2 * HH + t;
    B2[base] = h;
    B2[base + HH] = l;
}

// softmax (unbounded logits) writing bf16 [h,l] split-2
__global__ void softmax_split2_kernel(const float* __restrict__ buf,
                                      __nv_bfloat16* __restrict__ out2, int L) {
    int r = blockIdx.x;
    const float* row = buf + (size_t)r * L;
    __nv_bfloat16* orow = out2 + (size_t)r * 2 * L;
    int t = threadIdx.x;
    int V = L >> 8;
    float v[16];
    float mx = NEG_INF;
    for (int u = 0; u < V; u++) {
        v[u] = row[t + (u << 8)];
        mx = fmaxf(mx, v[u]);
    }
    __shared__ float sh[256];
    sh[t] = mx;
    __syncthreads();
    for (int o = 128; o > 0; o >>= 1) {
        if (t < o) sh[t] = fmaxf(sh[t], sh[t + o]);
        __syncthreads();
    }
    mx = sh[0];
    __syncthreads();
    float s = 0.0f;
    for (int u = 0; u < V; u++) {
        v[u] = __expf(v[u] - mx);
        s += v[u];
    }
    sh[t] = s;
    __syncthreads();
    for (int o = 128; o > 0; o >>= 1) {
        if (t < o) sh[t] += sh[t + o];
        __syncthreads();
    }
    float inv = 1.0f / sh[0];
    for (int u = 0; u < V; u++) {
        float p = v[u] * inv;
        __nv_bfloat16 h = __float2bfloat16(p);
        __nv_bfloat16 l = __float2bfloat16(p - __bfloat162float(h));
        int c = t + (u << 8);
        orow[c] = h;
        orow[c + L] = l;
    }
}

__global__ void top3_reduce_scatter(const float* __restrict__ cval, const int* __restrict__ cidx,
                                    const float* __restrict__ h, float* __restrict__ hidden2,
                                    float* __restrict__ colsum2) {
    int i = blockIdx.x, t = threadIdx.x;
    size_t off = ((size_t)i * 128 + t) * 3;
    __shared__ float sv[384];
    __shared__ int si[384];
    __shared__ float bv[KTOP];
    __shared__ int bi[KTOP];
    sv[t] = cval[off]; sv[128 + t] = cval[off + 1]; sv[256 + t] = cval[off + 2];
    si[t] = cidx[off]; si[128 + t] = cidx[off + 1]; si[256 + t] = cidx[off + 2];
    __syncthreads();
    if (t == 0) {
        float a0 = NEG_INF, a1 = NEG_INF, a2 = NEG_INF;
        int j0 = 0, j1 = 0, j2 = 0;
        for (int q = 0; q < 384; q++) ins3(sv[q], si[q], a0, a1, a2, j0, j1, j2);
        ins3(0.0f, i, a0, a1, a2, j0, j1, j2);
        bv[0] = a0; bv[1] = a1; bv[2] = a2;
        bi[0] = j0; bi[1] = j1; bi[2] = j2;
    }
    __syncthreads();
    float hv = h[(size_t)i * HH + t];
#pragma unroll
    for (int k = 0; k < KTOP; k++) {
        int j = bi[k];
        float v = bv[k];
        atomicAdd(&hidden2[(size_t)j * HH + t], v * hv);
        if (t == 0) atomicAdd(&colsum2[j], v);
    }
}

__global__ void diag_valid_kernel(const float* __restrict__ colsum2, const float* __restrict__ diag,
                                  const float* __restrict__ h, float* __restrict__ hidden2,
                                  float* __restrict__ valid2f, float* __restrict__ norm2,
                                  __nv_bfloat16* __restrict__ B2) {
    int j = blockIdx.x;
    int t = threadIdx.x;
    float dterm = (colsum2[j] != 0.0f) ? diag[j] : 0.0f;
    float v = hidden2[(size_t)j * HH + t] + dterm * h[(size_t)j * HH + t];
    __shared__ float shs[128];
    __shared__ float shq[128];
    shs[t] = v;
    shq[t] = v * v;
    __syncthreads();
    for (int o = 64; o > 0; o >>= 1) {
        if (t < o) { shs[t] += shs[t + o]; shq[t] += shq[t + o]; }
        __syncthreads();
    }
    float valid = (shs[0] != 0.0f) ? 1.0f : 0.0f;
    v *= valid;
    hidden2[(size_t)j * HH + t] = v;
    if (t == 0) {
        valid2f[j] = valid;
        norm2[j] = valid * sqrtf(shq[0]);
    }
    __nv_bfloat16 hh = __float2bfloat16(v);
    __nv_bfloat16 l = __float2bfloat16(v - __bfloat162float(hh));
    size_t base = (size_t)j * 2 * HH + t;
    B2[base] = hh;
    B2[base + HH] = l;
}

// ---------------- host orchestration ----------------
static EpiParams ep_make(int mode) {
    EpiParams e;
    e.mode = mode;
    e.normA = nullptr; e.normB = nullptr; e.validf = nullptr;
    e.cval = nullptr; e.cidx = nullptr;
    e.out3 = nullptr; e.rowsum = nullptr;
    return e;
}

static void launch_mma(const __nv_bfloat16* A, const __nv_bfloat16* B, float* C,
                       int M, int Nn, int Ktot, int splits, int mapL, int bmapL,
                       const EpiParams& ep) {
    dim3 grid(Nn / 128, M / 128, splits), block(256);
    mma_gemm<<<grid, block>>>(A, B, C, M, Nn, Ktot, Ktot / splits, mapL, bmapL, ep);
}

#define PS_SMEM (3 * 32 * 132 * 4)
#define HS_SMEM (4 * 32 * 132 * 4)

#define SYM(p, s) do { void* _tmp; cudaGetSymbolAddress(&_tmp, s); p = (float*)_tmp; } while (0)
#define SYMB(p, s) do { void* _tmp; cudaGetSymbolAddress(&_tmp, s); p = (__nv_bfloat16*)_tmp; } while (0)

extern "C" void kernel_launch(void* const* d_in, const int* in_sizes, int n_in,
                              void* d_out, int out_size) {
    const float* x = (const float*)d_in[0];
    const float* cm = (const float*)d_in[1];
    const float* mv = (const float*)d_in[2];
    const float* W_ps = (const float*)d_in[3];
    const float* b_ps = (const float*)d_in[4];
    const float* W_psf = (const float*)d_in[5];
    const float* b_psf = (const float*)d_in[6];
    const float* W_psb = (const float*)d_in[7];
    const float* b_psb = (const float*)d_in[8];
    const float* W_hs = (const float*)d_in[9];
    const float* b_hs = (const float*)d_in[10];
    const float* W_hsf = (const float*)d_in[11];
    const float* b_hsf = (const float*)d_in[12];
    const float* W_hsb = (const float*)d_in[13];
    const float* b_hsb = (const float*)d_in[14];
    const float* W_in = (const float*)d_in[15];
    const float* b_in = (const float*)d_in[16];
    const float* W_out = (const float*)d_in[17];
    const float* b_out = (const float*)d_in[18];
    float* y = (float*)d_out;

    cudaFuncSetAttribute(ps_tail_kernel, cudaFuncAttributeMaxDynamicSharedMemorySize, PS_SMEM);
    cudaFuncSetAttribute(hs_tail_kernel, cudaFuncAttributeMaxDynamicSharedMemorySize, HS_SMEM);

    float *p_big, *p_nc, *p_hidden1, *p_hiddenB, *p_tmp, *p_tmp2, *p_h, *p_hidden2,
        *p_colsum, *p_valid1, *p_normx, *p_normB, *p_normh, *p_diag, *p_norm2, *p_valid2,
        *p_colsum2, *p_rowsC, *p_rowsN, *p_cval;
    int* p_cidx;
    __nv_bfloat16 *p_x2, *p_h2b, *p_h1b, *p_hBb, *p_h22b, *p_hBT2, *p_h2T2, *p_xT2,
        *p_xvT2, *p_c2sA2, *p_probsA2, *p_cmT2;
    SYM(p_big, g_big); SYM(p_nc, g_nc); SYM(p_hidden1, g_hidden1); SYM(p_hiddenB, g_hiddenB);
    SYM(p_tmp, g_tmp); SYM(p_tmp2, g_tmp2); SYM(p_h, g_h); SYM(p_hidden2, g_hidden2);
    SYM(p_colsum, g_colsum); SYM(p_valid1, g_valid1); SYM(p_normx, g_normx);
    SYM(p_normB, g_normB); SYM(p_normh, g_normh); SYM(p_diag, g_diag); SYM(p_norm2, g_norm2);
    SYM(p_valid2, g_valid2); SYM(p_colsum2, g_colsum2); SYM(p_rowsC, g_rowsC);
    SYM(p_rowsN, g_rowsN); SYM(p_cval, g_cval);
    { void* t; cudaGetSymbolAddress(&t, g_cidx); p_cidx = (int*)t; }
    SYMB(p_x2, g_x2); SYMB(p_h2b, g_h2b); SYMB(p_h1b, g_h1b); SYMB(p_hBb, g_hBb);
    SYMB(p_h22b, g_h22b); SYMB(p_hBT2, g_hBT2); SYMB(p_h2T2, g_h2T2); SYMB(p_xT2, g_xT2);
    SYMB(p_xvT2, g_xvT2); SYMB(p_c2sA2, g_c2sA2); SYMB(p_probsA2, g_probsA2);
    SYMB(p_cmT2, g_cmT2);
    __nv_bfloat16* p_pT2 = p_probsA2;   // alias [CC, 2*NN] (ps-phase lifetime)

    zero_all_kernel<<<NN * HH / 256, 256>>>(p_hidden2, p_hidden1, p_hiddenB, p_colsum,
                                            p_colsum2, p_tmp, p_tmp2, p_rowsC, p_rowsN,
                                            y, b_out);
    xprep_kernel<<<NN, 128>>>(x, p_normx, p_x2);

    // ---- ps branch ----
    {
        dim3 grid(NN / 32, CC / 32), block(32, 8);
        cm_transpose_kernel<<<grid, block>>>(cm, mv, p_cmT2, p_colsum);
    }
    {
        dim3 grid(NN / 32, HH / 32), block(32, 8);
        xT_kernel<<<grid, block>>>(x, mv, p_xT2, p_xvT2);
    }
    // hidden1 = cm^T @ xv (exact dup-A, exact split-2 B)
    launch_mma(p_cmT2, p_xvT2, p_hidden1, CC, HH, 2 * NN, 32, 0, 0, ep_make(EP_ATOM));
    hidden1post_kernel<<<CC, 128>>>(p_hidden1, p_colsum, p_valid1, p_h1b);
    // logitsT = hidden1 @ x^T
    launch_mma(p_h1b, p_x2, p_nc, CC, NN, 3 * HH, 1, HH, HH, ep_make(EP_NONE));
    softmax_split2_kernel<<<CC, 256>>>(p_nc, p_pT2, NN);
    // hiddenB = probsT @ x
    launch_mma(p_pT2, p_xT2, p_hiddenB, CC, HH, 3 * NN, 32, NN, NN, ep_make(EP_ATOM));
    hiddenBpost_kernel<<<CC, 128>>>(p_hiddenB, p_valid1, p_normB, p_hBb);
    {
        dim3 grid(CC / 32, HH / 32), block(32, 8);
        transpose_split2_kernel<<<grid, block>>>(p_hiddenB, p_hBT2, CC);
    }
    // cos(x,hiddenB) -> exp(cos) [h,l] + rowsums
    {
        EpiParams e = ep_make(EP_EXP3);
        e.normA = p_normx; e.normB = p_normB; e.validf = p_valid1;
        e.out3 = p_c2sA2; e.rowsum = p_rowsC;
        launch_mma(p_x2, p_hBb, p_big, NN, CC, 3 * HH, 1, HH, HH, e);
    }
    launch_mma(p_c2sA2, p_hBT2, p_tmp, NN, HH, 3 * CC, 4, CC, CC, ep_make(EP_ATOM));
    ps_tail_kernel<<<NN / 32, 256, PS_SMEM>>>(p_tmp, p_rowsC, x, W_ps, b_ps, W_psb, b_psb,
                                              W_psf, b_psf, W_out, p_h, p_h2b, p_normh,
                                              p_diag, y);

    // ---- hs branch ----
    // cos(h,h) with fused per-chunk top3
    {
        EpiParams e = ep_make(EP_TOP3);
        e.normA = p_normh; e.normB = p_normh;
        e.cval = p_cval; e.cidx = p_cidx;
        launch_mma(p_h2b, p_h2b, p_big, NN, NN, 3 * HH, 1, HH, HH, e);
    }
    top3_reduce_scatter<<<NN, 128>>>(p_cval, p_cidx, p_h, p_hidden2, p_colsum2);
    diag_valid_kernel<<<NN, 128>>>(p_colsum2, p_diag, p_h, p_hidden2, p_valid2, p_norm2,
                                   p_h22b);
    {
        dim3 grid(NN / 32, HH / 32), block(32, 8);
        transpose_split2_kernel<<<grid, block>>>(p_hidden2, p_h2T2, NN);
    }
    // cos(h,hidden2) -> exp(cos) [h,l] + rowsums
    {
        EpiParams e = ep_make(EP_EXP3);
        e.normA = p_normh; e.normB = p_norm2; e.validf = p_valid2;
        e.out3 = p_probsA2; e.rowsum = p_rowsN;
        launch_mma(p_h2b, p_h22b, p_big, NN, NN, 3 * HH, 1, HH, HH, e);
    }
    launch_mma(p_probsA2, p_h2T2, p_tmp2, NN, HH, 3 * NN, 8, NN, NN, ep_make(EP_ATOM));
    hs_tail_kernel<<<NN / 32, 256, HS_SMEM>>>(p_tmp2, p_rowsN, p_h, W_hs, b_hs, W_hsb, b_hsb,
                                              W_hsf, b_hsf, W_in, b_in, W_out, y);
}

// round 16
// speedup vs baseline: 1.2303x; 1.0647x over previous
#include <cuda_runtime.h>
#include <cuda_bf16.h>
#include <math.h>
#include <stdint.h>

#define NN 4096
#define CC 512
#define HH 128
#define KTOP 3

#define NEG_INF (__int_as_float(0xff800000))

// ---------------- static scratch ----------------
__device__ float g_big[(size_t)NN * NN];
__device__ float g_nc[(size_t)NN * CC];
__device__ float g_hidden1[CC * HH];
__device__ float g_hiddenB[CC * HH];
__device__ float g_tmp[NN * HH];
__device__ float g_tmp2[NN * HH];
__device__ float g_h[NN * HH];
__device__ float g_hidden2[NN * HH];
__device__ float g_colsum[CC];
__device__ float g_valid1[CC];
__device__ float g_normx[NN];
__device__ float g_normB[CC];
__device__ float g_normh[NN];
__device__ float g_diag[NN];
__device__ float g_norm2[NN];
__device__ float g_valid2[NN];
__device__ float g_colsum2[NN];
__device__ float g_rowsC[NN];
__device__ float g_rowsN[NN];
__device__ float g_cval[(size_t)NN * 32 * 3];
__device__ int   g_cidx[(size_t)NN * 32 * 3];

// all split operands stored [h,l] (split-2), consumed via A-map [h,h,l] / B-map [h,l,h]
__device__ __nv_bfloat16 g_x2[(size_t)NN * 2 * HH];
__device__ __nv_bfloat16 g_h2b[(size_t)NN * 2 * HH];
__device__ __nv_bfloat16 g_h1b[(size_t)CC * 2 * HH];
__device__ __nv_bfloat16 g_hBb[(size_t)CC * 2 * HH];
__device__ __nv_bfloat16 g_h22b[(size_t)NN * 2 * HH];
__device__ __nv_bfloat16 g_hBT2[(size_t)HH * 2 * CC];
__device__ __nv_bfloat16 g_h2T2[(size_t)HH * 2 * NN];
__device__ __nv_bfloat16 g_xT2[(size_t)HH * 2 * NN];
__device__ __nv_bfloat16 g_xvT2[(size_t)HH * 2 * NN];
__device__ __nv_bfloat16 g_c2sA2[(size_t)NN * 2 * CC];
__device__ __nv_bfloat16 g_probsA2[(size_t)NN * 2 * NN];
__device__ __nv_bfloat16 g_cmT2[(size_t)CC * 2 * NN];

enum { EP_NONE = 0, EP_ATOM = 6, EP_TOP3 = 7, EP_EXP3 = 8 };

struct EpiParams {
    int mode;
    const float* normA;
    const float* normB;
    const float* validf;
    float* cval;
    int* cidx;
    __nv_bfloat16* out3;
    float* rowsum;
};

__device__ __forceinline__ void ins3(float v, int j, float& b0, float& b1, float& b2,
                                     int& j0, int& j1, int& j2) {
    if (v > b0) { b2 = b1; j2 = j1; b1 = b0; j1 = j0; b0 = v; j0 = j; }
    else if (v > b1) { b2 = b1; j2 = j1; b1 = v; j1 = j; }
    else if (v > b2) { b2 = v; j2 = j; }
}

// ---------------- mma.sync bf16 GEMM (8 warps, 64x32 warp tile, 2-stage) ----------------
#define SMEM_ROW 80

__device__ __forceinline__ void mma16816(float* c, const uint32_t* a, const uint32_t* b) {
    asm volatile(
        "mma.sync.aligned.m16n8k16.row.col.f32.bf16.bf16.f32 "
        "{%0,%1,%2,%3}, {%4,%5,%6,%7}, {%8,%9}, {%0,%1,%2,%3};"
        : "+f"(c[0]), "+f"(c[1]), "+f"(c[2]), "+f"(c[3])
        : "r"(a[0]), "r"(a[1]), "r"(a[2]), "r"(a[3]), "r"(b[0]), "r"(b[1]));
}

__device__ __forceinline__ void cp_async16(uint32_t smem_addr, const void* gptr) {
    asm volatile("cp.async.cg.shared.global [%0], [%1], 16;" :: "r"(smem_addr), "l"(gptr));
}

__device__ __forceinline__ void ldmatrix_x4(uint32_t* r, uint32_t addr) {
    asm volatile("ldmatrix.sync.aligned.m8n8.x4.shared.b16 {%0,%1,%2,%3}, [%4];"
                 : "=r"(r[0]), "=r"(r[1]), "=r"(r[2]), "=r"(r[3]) : "r"(addr));
}

__global__ void __launch_bounds__(256)
mma_gemm(const __nv_bfloat16* __restrict__ A, const __nv_bfloat16* __restrict__ B,
         float* __restrict__ C, int M, int Nn, int Ktot, int kchunk, int mapL, int bmapL,
         EpiParams ep) {
    __shared__ __align__(16) char As_[2][128 * SMEM_ROW];
    __shared__ __align__(16) char Bs_[2][128 * SMEM_ROW];

    const int tid = threadIdx.x;
    const int lane = tid & 31;
    const int wid = tid >> 5;
    const int warp_m = (wid >> 2) * 64;
    const int warp_n = (wid & 3) * 32;
    const int m0 = blockIdx.y * 128;
    const int n0 = blockIdx.x * 128;
    const int kbase = blockIdx.z * kchunk;
    const int niter = kchunk >> 5;

    const size_t rowbA = (size_t)(mapL ? 2 * mapL : Ktot) * 2;
    const size_t rowbB = (size_t)(bmapL ? 2 * bmapL : Ktot) * 2;
    const char* Ag = (const char*)A + (size_t)m0 * rowbA;
    const char* Bg = (const char*)B + (size_t)n0 * rowbB;
    const uint32_t LbA = (uint32_t)mapL * 2;
    const uint32_t LbB2 = (uint32_t)bmapL * 4;

    uint32_t asb = (uint32_t)__cvta_generic_to_shared(&As_[0][0]);
    uint32_t bsb = (uint32_t)__cvta_generic_to_shared(&Bs_[0][0]);

    float acc[4][4][4];
#pragma unroll
    for (int i = 0; i < 4; i++)
#pragma unroll
        for (int j = 0; j < 4; j++)
#pragma unroll
            for (int q = 0; q < 4; q++) acc[i][j][q] = 0.0f;

    const int lm0 = tid >> 2;
    const int lc = tid & 3;

    const int lj = lane >> 3;
    const int lr = lane & 7;
    const uint32_t a_row_off = (uint32_t)(warp_m + (lj & 1) * 8 + lr) * SMEM_ROW +
                               (uint32_t)(lj >> 1) * 16;
    const uint32_t b_row_off = (uint32_t)(warp_n + (lj >> 1) * 8 + lr) * SMEM_ROW +
                               (uint32_t)(lj & 1) * 16;

#define LOAD_TILE(s, it) do { \
    uint32_t lkB = (uint32_t)kbase * 2 + (uint32_t)(it) * 64; \
    uint32_t pA = (mapL && lkB >= LbA) ? lkB - LbA : lkB; \
    uint32_t pB = (bmapL && lkB >= LbB2) ? lkB - LbB2 : lkB; \
    uint32_t soff = (uint32_t)((s) * 128 * SMEM_ROW + lc * 16); \
    cp_async16(asb + soff + lm0 * SMEM_ROW, \
               Ag + (size_t)lm0 * rowbA + pA + lc * 16); \
    cp_async16(asb + soff + (lm0 + 64) * SMEM_ROW, \
               Ag + (size_t)(lm0 + 64) * rowbA + pA + lc * 16); \
    cp_async16(bsb + soff + lm0 * SMEM_ROW, \
               Bg + (size_t)lm0 * rowbB + pB + lc * 16); \
    cp_async16(bsb + soff + (lm0 + 64) * SMEM_ROW, \
               Bg + (size_t)(lm0 + 64) * rowbB + pB + lc * 16); \
    asm volatile("cp.async.commit_group;"); \
} while (0)

    LOAD_TILE(0, 0);

    for (int it = 0; it < niter; it++) {
        int s = it & 1;
        if (it + 1 < niter) {
            LOAD_TILE(s ^ 1, it + 1);
            asm volatile("cp.async.wait_group 1;");
        } else {
            asm volatile("cp.async.wait_group 0;");
        }
        __syncthreads();

        uint32_t abase = asb + (uint32_t)s * (128 * SMEM_ROW) + a_row_off;
        uint32_t bbase = bsb + (uint32_t)s * (128 * SMEM_ROW) + b_row_off;
#pragma unroll
        for (int ks = 0; ks < 32; ks += 16) {
            uint32_t a[4][4], b[4][2];
#pragma unroll
            for (int mi = 0; mi < 4; mi++)
                ldmatrix_x4(a[mi], abase + mi * 16 * SMEM_ROW + ks * 2);
#pragma unroll
            for (int p = 0; p < 2; p++) {
                uint32_t t[4];
                ldmatrix_x4(t, bbase + p * 16 * SMEM_ROW + ks * 2);
                b[p * 2][0] = t[0]; b[p * 2][1] = t[1];
                b[p * 2 + 1][0] = t[2]; b[p * 2 + 1][1] = t[3];
            }
#pragma unroll
            for (int mi = 0; mi < 4; mi++)
#pragma unroll
                for (int ni = 0; ni < 4; ni++) mma16816(acc[mi][ni], a[mi], b[ni]);
        }
        __syncthreads();
    }

    if (ep.mode == EP_TOP3) {
        // per-warp chunk top3 -> block-level merge through (now free) A-stage smem
        float* sv = (float*)&As_[0][0];             // [128 rows][4 chunks][3]
        int* si = (int*)(&As_[0][0] + 8192);
#pragma unroll
        for (int mi = 0; mi < 4; mi++) {
#pragma unroll
            for (int half = 0; half < 2; half++) {
                int rl = warp_m + mi * 16 + (lane >> 2) + half * 8;
                int m = m0 + rl;
                float na = ep.normA[m];
                float b0 = NEG_INF, b1 = NEG_INF, b2 = NEG_INF;
                int j0 = 0, j1 = 0, j2 = 0;
#pragma unroll
                for (int ni = 0; ni < 4; ni++) {
#pragma unroll
                    for (int q = 0; q < 2; q++) {
                        int c = n0 + warp_n + ni * 8 + (lane & 3) * 2 + q;
                        float v = acc[mi][ni][half * 2 + q];
                        float den = na * ep.normB[c];
                        v = v / (den == 0.0f ? 1.0f : den);
                        if (c == m) v = NEG_INF;
                        ins3(v, c, b0, b1, b2, j0, j1, j2);
                    }
                }
#pragma unroll
                for (int msk = 1; msk <= 2; msk <<= 1) {
                    float o0 = __shfl_xor_sync(0xffffffff, b0, msk);
                    int p0 = __shfl_xor_sync(0xffffffff, j0, msk);
                    float o1 = __shfl_xor_sync(0xffffffff, b1, msk);
                    int p1 = __shfl_xor_sync(0xffffffff, j1, msk);
                    float o2 = __shfl_xor_sync(0xffffffff, b2, msk);
                    int p2 = __shfl_xor_sync(0xffffffff, j2, msk);
                    ins3(o0, p0, b0, b1, b2, j0, j1, j2);
                    ins3(o1, p1, b0, b1, b2, j0, j1, j2);
                    ins3(o2, p2, b0, b1, b2, j0, j1, j2);
                }
                if ((lane & 3) == 0) {
                    int slot = (rl * 4 + (warp_n >> 5)) * 3;
                    sv[slot] = b0; sv[slot + 1] = b1; sv[slot + 2] = b2;
                    si[slot] = j0; si[slot + 1] = j1; si[slot + 2] = j2;
                }
            }
        }
        __syncthreads();
        if (tid < 128) {
            float a0 = NEG_INF, a1 = NEG_INF, a2 = NEG_INF;
            int j0 = 0, j1 = 0, j2 = 0;
#pragma unroll
            for (int q = 0; q < 12; q++) {
                int slot = tid * 12 + q;
                ins3(sv[slot], si[slot], a0, a1, a2, j0, j1, j2);
            }
            size_t off = ((size_t)(m0 + tid) * 32 + blockIdx.x) * 3;
            ep.cval[off] = a0; ep.cval[off + 1] = a1; ep.cval[off + 2] = a2;
            ep.cidx[off] = j0; ep.cidx[off + 1] = j1; ep.cidx[off + 2] = j2;
        }
        return;
    }

    if (ep.mode == EP_EXP3) {
#pragma unroll
        for (int mi = 0; mi < 4; mi++) {
#pragma unroll
            for (int half = 0; half < 2; half++) {
                int m = m0 + warp_m + mi * 16 + (lane >> 2) + half * 8;
                float na = ep.normA[m];
                float rs = 0.0f;
#pragma unroll
                for (int ni = 0; ni < 4; ni++) {
                    int c = n0 + warp_n + ni * 8 + (lane & 3) * 2;
                    float v0 = acc[mi][ni][half * 2];
                    float v1 = acc[mi][ni][half * 2 + 1];
                    float d0 = na * ep.normB[c];
                    float d1 = na * ep.normB[c + 1];
                    v0 = v0 / (d0 == 0.0f ? 1.0f : d0);
                    v1 = v1 / (d1 == 0.0f ? 1.0f : d1);
                    float e0 = (ep.validf && ep.validf[c] == 0.0f) ? 0.0f : __expf(v0);
                    float e1 = (ep.validf && ep.validf[c + 1] == 0.0f) ? 0.0f : __expf(v1);
                    rs += e0 + e1;
                    __nv_bfloat16 h0 = __float2bfloat16(e0);
                    __nv_bfloat16 h1 = __float2bfloat16(e1);
                    __nv_bfloat16 l0 = __float2bfloat16(e0 - __bfloat162float(h0));
                    __nv_bfloat16 l1 = __float2bfloat16(e1 - __bfloat162float(h1));
                    __nv_bfloat162 hv; hv.x = h0; hv.y = h1;
                    __nv_bfloat162 lv; lv.x = l0; lv.y = l1;
                    size_t base = (size_t)m * 2 * Nn + c;
                    *(__nv_bfloat162*)&ep.out3[base] = hv;
                    *(__nv_bfloat162*)&ep.out3[base + Nn] = lv;
                }
                rs += __shfl_xor_sync(0xffffffffu, rs, 1);
                rs += __shfl_xor_sync(0xffffffffu, rs, 2);
                if ((lane & 3) == 0) atomicAdd(&ep.rowsum[m], rs);
            }
        }
        return;
    }

#pragma unroll
    for (int mi = 0; mi < 4; mi++) {
        int r0 = m0 + warp_m + mi * 16 + (lane >> 2);
#pragma unroll
        for (int ni = 0; ni < 4; ni++) {
            int c = n0 + warp_n + ni * 8 + (lane & 3) * 2;
#pragma unroll
            for (int half = 0; half < 2; half++) {
                int m = r0 + half * 8;
                float v0 = acc[mi][ni][half * 2];
                float v1 = acc[mi][ni][half * 2 + 1];
                size_t o = (size_t)m * Nn + c;
                if (ep.mode == EP_ATOM) {
                    atomicAdd(&C[o], v0);
                    atomicAdd(&C[o + 1], v1);
                } else {
                    *(float2*)&C[o] = make_float2(v0, v1);
                }
            }
        }
    }
}

// ---------------- transpose kernels ----------------
__global__ void transpose_split2_kernel(const float* __restrict__ X,
                                        __nv_bfloat16* __restrict__ Y, int K) {
    __shared__ float tile[32][33];
    int k0 = blockIdx.x * 32, h0 = blockIdx.y * 32;
    int tx = threadIdx.x, ty = threadIdx.y;
    for (int r = ty; r < 32; r += 8)
        tile[r][tx] = X[(size_t)(k0 + r) * HH + h0 + tx];
    __syncthreads();
    for (int r = ty; r < 32; r += 8) {
        int hcol = h0 + r;
        int k = k0 + tx;
        float v = tile[tx][r];
        __nv_bfloat16 h = __float2bfloat16(v);
        __nv_bfloat16 l = __float2bfloat16(v - __bfloat162float(h));
        size_t base = (size_t)hcol * 2 * K + k;
        Y[base] = h;
        Y[base + K] = l;
    }
}

__global__ void xT_kernel(const float* __restrict__ X, const float* __restrict__ mv,
                          __nv_bfloat16* __restrict__ T2, __nv_bfloat16* __restrict__ V2) {
    __shared__ float tile[32][33];
    int k0 = blockIdx.x * 32, h0 = blockIdx.y * 32;
    int tx = threadIdx.x, ty = threadIdx.y;
    for (int r = ty; r < 32; r += 8)
        tile[r][tx] = X[(size_t)(k0 + r) * HH + h0 + tx];
    __syncthreads();
    float mvk = mv[k0 + tx];
    for (int r = ty; r < 32; r += 8) {
        int hcol = h0 + r;
        int k = k0 + tx;
        float v = tile[tx][r];
        __nv_bfloat16 h = __float2bfloat16(v);
        __nv_bfloat16 l = __float2bfloat16(v - __bfloat162float(h));
        size_t base = (size_t)hcol * 2 * NN + k;
        T2[base] = h;
        T2[base + NN] = l;
        float w = v * mvk;
        __nv_bfloat16 hw = __float2bfloat16(w);
        __nv_bfloat16 lw = __float2bfloat16(w - __bfloat162float(hw));
        V2[base] = hw;
        V2[base + NN] = lw;
    }
}

__global__ void cm_transpose_kernel(const float* __restrict__ cm, const float* __restrict__ mv,
                                    __nv_bfloat16* __restrict__ Y, float* __restrict__ colsum) {
    __shared__ float tile[32][33];
    int k0 = blockIdx.x * 32, c0 = blockIdx.y * 32;
    int tx = threadIdx.x, ty = threadIdx.y;
    for (int r = ty; r < 32; r += 8)
        tile[r][tx] = cm[(size_t)(k0 + r) * CC + c0 + tx];
    __syncthreads();
    float mvk = mv[k0 + tx];
    for (int r = ty; r < 32; r += 8) {
        int c = c0 + r;
        int k = k0 + tx;
        float fv = tile[tx][r];
        __nv_bfloat16 v = __float2bfloat16(fv);
        size_t base = (size_t)c * 2 * NN + k;
        Y[base] = v;
        Y[base + NN] = v;
        float s = fv * mvk;
#pragma unroll
        for (int o = 16; o > 0; o >>= 1) s += __shfl_xor_sync(0xffffffffu, s, o);
        if (tx == 0) atomicAdd(&colsum[c], s);
    }
}

// ---------------- fused tail kernels ----------------
__device__ __forceinline__ void stage_mm(const float* __restrict__ As,
                                         const float* __restrict__ W, float* Ws,
                                         int tid, float acc[2][8]) {
    const int tx = tid & 15, ty = tid >> 4;
#pragma unroll
    for (int i = 0; i < 2; i++)
#pragma unroll
        for (int j = 0; j < 8; j++) acc[i][j] = 0.0f;
    for (int kc = 0; kc < 128; kc += 32) {
        __syncthreads();
#pragma unroll
        for (int l = 0; l < 16; l++) {
            int id = tid + l * 256;
            int n = id >> 5, k = id & 31;
            Ws[k * 132 + n] = W[n * 128 + kc + k];
        }
        __syncthreads();
#pragma unroll
        for (int k = 0; k < 32; k++) {
            float a0 = As[(ty * 2) * 132 + kc + k];
            float a1 = As[(ty * 2 + 1) * 132 + kc + k];
            const float* wr = &Ws[k * 132 + tx * 8];
            float4 w0 = *(const float4*)wr;
            float4 w1 = *(const float4*)(wr + 4);
            float wv[8] = {w0.x, w0.y, w0.z, w0.w, w1.x, w1.y, w1.z, w1.w};
#pragma unroll
            for (int j = 0; j < 8; j++) {
                acc[0][j] = fmaf(a0, wv[j], acc[0][j]);
                acc[1][j] = fmaf(a1, wv[j], acc[1][j]);
            }
        }
    }
}

__global__ void __launch_bounds__(256) ps_tail_kernel(
    const float* __restrict__ tmp, const float* __restrict__ rowsum,
    const float* __restrict__ x,
    const float* __restrict__ W1, const float* __restrict__ b1,
    const float* __restrict__ W2, const float* __restrict__ b2,
    const float* __restrict__ W3, const float* __restrict__ b3,
    const float* __restrict__ Wout, float* __restrict__ h,
    __nv_bfloat16* __restrict__ h2b, float* __restrict__ normh, float* __restrict__ diag,
    float* __restrict__ y) {
    extern __shared__ float sm[];
    float* As = sm;
    float* Ps = sm + 32 * 132;
    float* Ws = sm + 2 * 32 * 132;
    int tid = threadIdx.x;
    int m0 = blockIdx.x * 32;
    const int tx = tid & 15, ty = tid >> 4;
#pragma unroll
    for (int l = 0; l < 4; l++) {
        int id = tid + l * 256;
        int m = id >> 5, c4 = id & 31;
        float inv = 1.0f / rowsum[m0 + m];
        float4 v = *(const float4*)&tmp[(size_t)(m0 + m) * 128 + c4 * 4];
        v.x *= inv; v.y *= inv; v.z *= inv; v.w *= inv;
        *(float4*)&As[m * 132 + c4 * 4] = v;
    }
    float acc[2][8];
    stage_mm(As, W1, Ws, tid, acc);
#pragma unroll
    for (int i = 0; i < 2; i++)
#pragma unroll
        for (int j = 0; j < 8; j++)
            Ps[(ty * 2 + i) * 132 + tx * 8 + j] = acc[i][j] + b1[tx * 8 + j];
    stage_mm(Ps, W2, Ws, tid, acc);
    float ss[2] = {0.0f, 0.0f};
#pragma unroll
    for (int i = 0; i < 2; i++) {
        int m = m0 + ty * 2 + i;
#pragma unroll
        for (int j = 0; j < 8; j++) {
            int n = tx * 8 + j;
            float hv = x[(size_t)m * 128 + n] - (acc[i][j] + b2[n]);
            h[(size_t)m * 128 + n] = hv;
            ss[i] += hv * hv;
            __nv_bfloat16 hb = __float2bfloat16(hv);
            __nv_bfloat16 lb = __float2bfloat16(hv - __bfloat162float(hb));
            size_t base = (size_t)m * 2 * HH + n;
            h2b[base] = hb;
            h2b[base + HH] = lb;
        }
    }
#pragma unroll
    for (int o = 1; o < 16; o <<= 1) {
        ss[0] += __shfl_xor_sync(0xffffffffu, ss[0], o);
        ss[1] += __shfl_xor_sync(0xffffffffu, ss[1], o);
    }
    if (tx == 0) {
#pragma unroll
        for (int i = 0; i < 2; i++) {
            int m = m0 + ty * 2 + i;
            float s = ss[i];
            float n = sqrtf(s);
            normh[m] = n;
            float den = n * n;
            diag[m] = (den == 0.0f) ? 0.0f : s / den;
        }
    }
    stage_mm(Ps, W3, Ws, tid, acc);
    float d0 = 0.0f, d1 = 0.0f;
#pragma unroll
    for (int j = 0; j < 8; j++) {
        int n = tx * 8 + j;
        float z0 = acc[0][j] + b3[n]; z0 = z0 > 0.0f ? z0 : 0.01f * z0;
        float z1 = acc[1][j] + b3[n]; z1 = z1 > 0.0f ? z1 : 0.01f * z1;
        d0 = fmaf(z0, Wout[n], d0);
        d1 = fmaf(z1, Wout[n], d1);
    }
#pragma unroll
    for (int o = 1; o < 16; o <<= 1) {
        d0 += __shfl_xor_sync(0xffffffff, d0, o);
        d1 += __shfl_xor_sync(0xffffffff, d1, o);
    }
    if (tx == 0) {
        atomicAdd(&y[m0 + ty * 2], d0);
        atomicAdd(&y[m0 + ty * 2 + 1], d1);
    }
}

__global__ void __launch_bounds__(256) hs_tail_kernel(
    const float* __restrict__ tmp2, const float* __restrict__ rowsum,
    const float* __restrict__ h,
    const float* __restrict__ W1, const float* __restrict__ b1,
    const float* __restrict__ W2, const float* __restrict__ b2,
    const float* __restrict__ W3, const float* __restrict__ b3,
    const float* __restrict__ W4, const float* __restrict__ b4,
    const float* __restrict__ Wout, float* __restrict__ y) {
    extern __shared__ float sm[];
    float* As = sm;
    float* Hs = sm + 32 * 132;
    float* Is = sm + 2 * 32 * 132;
    float* Ws = sm + 3 * 32 * 132;
    int tid = threadIdx.x;
    int m0 = blockIdx.x * 32;
    const int tx = tid & 15, ty = tid >> 4;
#pragma unroll
    for (int l = 0; l < 4; l++) {
        int id = tid + l * 256;
        int m = id >> 5, c4 = id & 31;
        float inv = 1.0f / rowsum[m0 + m];
        float4 v = *(const float4*)&tmp2[(size_t)(m0 + m) * 128 + c4 * 4];
        v.x *= inv; v.y *= inv; v.z *= inv; v.w *= inv;
        *(float4*)&As[m * 132 + c4 * 4] = v;
    }
    float acc[2][8];
    stage_mm(As, W1, Ws, tid, acc);
#pragma unroll
    for (int i = 0; i < 2; i++)
#pragma unroll
        for (int j = 0; j < 8; j++)
            Hs[(ty * 2 + i) * 132 + tx * 8 + j] = acc[i][j] + b1[tx * 8 + j];
    stage_mm(Hs, W2, Ws, tid, acc);
#pragma unroll
    for (int i = 0; i < 2; i++) {
        int m = m0 + ty * 2 + i;
#pragma unroll
        for (int j = 0; j < 8; j++) {
            int n = tx * 8 + j;
            Is[(ty * 2 + i) * 132 + n] = h[(size_t)m * 128 + n] - (acc[i][j] + b2[n]);
        }
    }
    float d0 = 0.0f, d1 = 0.0f;
    stage_mm(Hs, W3, Ws, tid, acc);
#pragma unroll
    for (int j = 0; j < 8; j++) {
        int n = tx * 8 + j;
        float z0 = acc[0][j] + b3[n]; z0 = z0 > 0.0f ? z0 : 0.01f * z0;
        float z1 = acc[1][j] + b3[n]; z1 = z1 > 0.0f ? z1 : 0.01f * z1;
        d0 = fmaf(z0, Wout[n], d0);
        d1 = fmaf(z1, Wout[n], d1);
    }
    stage_mm(Is, W4, Ws, tid, acc);
#pragma unroll
    for (int j = 0; j < 8; j++) {
        int n = tx * 8 + j;
        float z0 = acc[0][j] + b4[n]; z0 = z0 > 0.0f ? z0 : 0.01f * z0;
        float z1 = acc[1][j] + b4[n]; z1 = z1 > 0.0f ? z1 : 0.01f * z1;
        d0 = fmaf(z0, Wout[n], d0);
        d1 = fmaf(z1, Wout[n], d1);
    }
#pragma unroll
    for (int o = 1; o < 16; o <<= 1) {
        d0 += __shfl_xor_sync(0xffffffff, d0, o);
        d1 += __shfl_xor_sync(0xffffffff, d1, o);
    }
    if (tx == 0) {
        atomicAdd(&y[m0 + ty * 2], d0);
        atomicAdd(&y[m0 + ty * 2 + 1], d1);
    }
}

// ---------------- fused small kernels ----------------
__global__ void zero_all_kernel(float* h2, float* h1, float* hB, float* cs, float* cs2,
                                float* tmp, float* tmp2, float* rsC, float* rsN,
                                float* y, const float* bout) {
    int i = blockIdx.x * blockDim.x + threadIdx.x;
    h2[i] = 0.0f;
    tmp[i] = 0.0f;
    tmp2[i] = 0.0f;
    if (i < CC * HH) { h1[i] = 0.0f; hB[i] = 0.0f; }
    if (i < CC) cs[i] = 0.0f;
    if (i < NN) { cs2[i] = 0.0f; rsC[i] = 0.0f; rsN[i] = 0.0f; y[i] = bout[0]; }
}

__global__ void xprep_kernel(const float* __restrict__ X, float* __restrict__ norm,
                             __nv_bfloat16* __restrict__ X2) {
    int m = blockIdx.x, t = threadIdx.x;
    float v = X[(size_t)m * HH + t];
    __shared__ float sh[128];
    sh[t] = v * v;
    __syncthreads();
    for (int o = 64; o > 0; o >>= 1) {
        if (t < o) sh[t] += sh[t + o];
        __syncthreads();
    }
    if (t == 0) norm[m] = sqrtf(sh[0]);
    __nv_bfloat16 h = __float2bfloat16(v);
    __nv_bfloat16 l = __float2bfloat16(v - __bfloat162float(h));
    size_t base = (size_t)m * 2 * HH + t;
    X2[base] = h;
    X2[base + HH] = l;
}

__global__ void hidden1post_kernel(float* __restrict__ X, const float* __restrict__ colsum,
                                   float* __restrict__ validf, __nv_bfloat16* __restrict__ A2) {
    int m = blockIdx.x, t = threadIdx.x;
    float sc = 1.0f / (colsum[m] + 1.0f);
    float v = X[(size_t)m * HH + t] * sc;
    __shared__ float sh[128];
    sh[t] = v;
    __syncthreads();
    for (int o = 64; o > 0; o >>= 1) {
        if (t < o) sh[t] += sh[t + o];
        __syncthreads();
    }
    if (t == 0) validf[m] = (sh[0] != 0.0f) ? 1.0f : 0.0f;
    __nv_bfloat16 h = __float2bfloat16(v);
    __nv_bfloat16 l = __float2bfloat16(v - __bfloat162float(h));
    size_t base = (size_t)m * 2 * HH + t;
    A2[base] = h;
    A2[base + HH] = l;
}

__global__ void hiddenBpost_kernel(float* __restrict__ X, const float* __restrict__ validf,
                                   float* __restrict__ norm, __nv_bfloat16* __restrict__ B2) {
    int m = blockIdx.x, t = threadIdx.x;
    float v = X[(size_t)m * HH + t] * validf[m];
    X[(size_t)m * HH + t] = v;
    __shared__ float sh[128];
    sh[t] = v * v;
    __syncthreads();
    for (int o = 64; o > 0; o >>= 1) {
        if (t < o) sh[t] += sh[t + o];
        __syncthreads();
    }
    if (t == 0) norm[m] = sqrtf(sh[0]);
    __nv_bfloat16 h = __float2bfloat16(v);
    __nv_bfloat16 l = __float2bfloat16(v - __bfloat162float(h));
    size_t base = (size_t)m * 2 * HH + t;
    B2[base] = h;
    B2[base + HH] = l;
}

__global__ void softmax_split2_kernel(const float* __restrict__ buf,
                                      __nv_bfloat16* __restrict__ out2, int L) {
    int r = blockIdx.x;
    const float* row = buf + (size_t)r * L;
    __nv_bfloat16* orow = out2 + (size_t)r * 2 * L;
    int t = threadIdx.x;
    int V = L >> 8;
    float v[16];
    float mx = NEG_INF;
    for (int u = 0; u < V; u++) {
        v[u] = row[t + (u << 8)];
        mx = fmaxf(mx, v[u]);
    }
    __shared__ float sh[256];
    sh[t] = mx;
    __syncthreads();
    for (int o = 128; o > 0; o >>= 1) {
        if (t < o) sh[t] = fmaxf(sh[t], sh[t + o]);
        __syncthreads();
    }
    mx = sh[0];
    __syncthreads();
    float s = 0.0f;
    for (int u = 0; u < V; u++) {
        v[u] = __expf(v[u] - mx);
        s += v[u];
    }
    sh[t] = s;
    __syncthreads();
    for (int o = 128; o > 0; o >>= 1) {
        if (t < o) sh[t] += sh[t + o];
        __syncthreads();
    }
    float inv = 1.0f / sh[0];
    for (int u = 0; u < V; u++) {
        float p = v[u] * inv;
        __nv_bfloat16 h = __float2bfloat16(p);
        __nv_bfloat16 l = __float2bfloat16(p - __bfloat162float(h));
        int c = t + (u << 8);
        orow[c] = h;
        orow[c + L] = l;
    }
}

__global__ void top3_reduce_scatter(const float* __restrict__ cval, const int* __restrict__ cidx,
                                    const float* __restrict__ h, float* __restrict__ hidden2,
                                    float* __restrict__ colsum2) {
    int i = blockIdx.x, t = threadIdx.x;
    __shared__ float sv[96];
    __shared__ int si[96];
    __shared__ float bv[KTOP];
    __shared__ int bi[KTOP];
    if (t < 96) {
        sv[t] = cval[(size_t)i * 96 + t];
        si[t] = cidx[(size_t)i * 96 + t];
    }
    __syncthreads();
    if (t == 0) {
        float a0 = NEG_INF, a1 = NEG_INF, a2 = NEG_INF;
        int j0 = 0, j1 = 0, j2 = 0;
        for (int q = 0; q < 96; q++) ins3(sv[q], si[q], a0, a1, a2, j0, j1, j2);
        ins3(0.0f, i, a0, a1, a2, j0, j1, j2);
        bv[0] = a0; bv[1] = a1; bv[2] = a2;
        bi[0] = j0; bi[1] = j1; bi[2] = j2;
    }
    __syncthreads();
    float hv = h[(size_t)i * HH + t];
#pragma unroll
    for (int k = 0; k < KTOP; k++) {
        int j = bi[k];
        float v = bv[k];
        atomicAdd(&hidden2[(size_t)j * HH + t], v * hv);
        if (t == 0) atomicAdd(&colsum2[j], v);
    }
}

__global__ void diag_valid_kernel(const float* __restrict__ colsum2, const float* __restrict__ diag,
                                  const float* __restrict__ h, float* __restrict__ hidden2,
                                  float* __restrict__ valid2f, float* __restrict__ norm2,
                                  __nv_bfloat16* __restrict__ B2) {
    int j = blockIdx.x;
    int t = threadIdx.x;
    float dterm = (colsum2[j] != 0.0f) ? diag[j] : 0.0f;
    float v = hidden2[(size_t)j * HH + t] + dterm * h[(size_t)j * HH + t];
    __shared__ float shs[128];
    __shared__ float shq[128];
    shs[t] = v;
    shq[t] = v * v;
    __syncthreads();
    for (int o = 64; o > 0; o >>= 1) {
        if (t < o) { shs[t] += shs[t + o]; shq[t] += shq[t + o]; }
        __syncthreads();
    }
    float valid = (shs[0] != 0.0f) ? 1.0f : 0.0f;
    v *= valid;
    hidden2[(size_t)j * HH + t] = v;
    if (t == 0) {
        valid2f[j] = valid;
        norm2[j] = valid * sqrtf(shq[0]);
    }
    __nv_bfloat16 hh = __float2bfloat16(v);
    __nv_bfloat16 l = __float2bfloat16(v - __bfloat162float(hh));
    size_t base = (size_t)j * 2 * HH + t;
    B2[base] = hh;
    B2[base + HH] = l;
}

// ---------------- host orchestration ----------------
static EpiParams ep_make(int mode) {
    EpiParams e;
    e.mode = mode;
    e.normA = nullptr; e.normB = nullptr; e.validf = nullptr;
    e.cval = nullptr; e.cidx = nullptr;
    e.out3 = nullptr; e.rowsum = nullptr;
    return e;
}

static void launch_mma(const __nv_bfloat16* A, const __nv_bfloat16* B, float* C,
                       int M, int Nn, int Ktot, int splits, int mapL, int bmapL,
                       const EpiParams& ep) {
    dim3 grid(Nn / 128, M / 128, splits), block(256);
    mma_gemm<<<grid, block>>>(A, B, C, M, Nn, Ktot, Ktot / splits, mapL, bmapL, ep);
}

#define PS_SMEM (3 * 32 * 132 * 4)
#define HS_SMEM (4 * 32 * 132 * 4)

#define SYM(p, s) do { void* _tmp; cudaGetSymbolAddress(&_tmp, s); p = (float*)_tmp; } while (0)
#define SYMB(p, s) do { void* _tmp; cudaGetSymbolAddress(&_tmp, s); p = (__nv_bfloat16*)_tmp; } while (0)

extern "C" void kernel_launch(void* const* d_in, const int* in_sizes, int n_in,
                              void* d_out, int out_size) {
    const float* x = (const float*)d_in[0];
    const float* cm = (const float*)d_in[1];
    const float* mv = (const float*)d_in[2];
    const float* W_ps = (const float*)d_in[3];
    const float* b_ps = (const float*)d_in[4];
    const float* W_psf = (const float*)d_in[5];
    const float* b_psf = (const float*)d_in[6];
    const float* W_psb = (const float*)d_in[7];
    const float* b_psb = (const float*)d_in[8];
    const float* W_hs = (const float*)d_in[9];
    const float* b_hs = (const float*)d_in[10];
    const float* W_hsf = (const float*)d_in[11];
    const float* b_hsf = (const float*)d_in[12];
    const float* W_hsb = (const float*)d_in[13];
    const float* b_hsb = (const float*)d_in[14];
    const float* W_in = (const float*)d_in[15];
    const float* b_in = (const float*)d_in[16];
    const float* W_out = (const float*)d_in[17];
    const float* b_out = (const float*)d_in[18];
    float* y = (float*)d_out;

    cudaFuncSetAttribute(ps_tail_kernel, cudaFuncAttributeMaxDynamicSharedMemorySize, PS_SMEM);
    cudaFuncSetAttribute(hs_tail_kernel, cudaFuncAttributeMaxDynamicSharedMemorySize, HS_SMEM);

    float *p_big, *p_nc, *p_hidden1, *p_hiddenB, *p_tmp, *p_tmp2, *p_h, *p_hidden2,
        *p_colsum, *p_valid1, *p_normx, *p_normB, *p_normh, *p_diag, *p_norm2, *p_valid2,
        *p_colsum2, *p_rowsC, *p_rowsN, *p_cval;
    int* p_cidx;
    __nv_bfloat16 *p_x2, *p_h2b, *p_h1b, *p_hBb, *p_h22b, *p_hBT2, *p_h2T2, *p_xT2,
        *p_xvT2, *p_c2sA2, *p_probsA2, *p_cmT2;
    SYM(p_big, g_big); SYM(p_nc, g_nc); SYM(p_hidden1, g_hidden1); SYM(p_hiddenB, g_hiddenB);
    SYM(p_tmp, g_tmp); SYM(p_tmp2, g_tmp2); SYM(p_h, g_h); SYM(p_hidden2, g_hidden2);
    SYM(p_colsum, g_colsum); SYM(p_valid1, g_valid1); SYM(p_normx, g_normx);
    SYM(p_normB, g_normB); SYM(p_normh, g_normh); SYM(p_diag, g_diag); SYM(p_norm2, g_norm2);
    SYM(p_valid2, g_valid2); SYM(p_colsum2, g_colsum2); SYM(p_rowsC, g_rowsC);
    SYM(p_rowsN, g_rowsN); SYM(p_cval, g_cval);
    { void* t; cudaGetSymbolAddress(&t, g_cidx); p_cidx = (int*)t; }
    SYMB(p_x2, g_x2); SYMB(p_h2b, g_h2b); SYMB(p_h1b, g_h1b); SYMB(p_hBb, g_hBb);
    SYMB(p_h22b, g_h22b); SYMB(p_hBT2, g_hBT2); SYMB(p_h2T2, g_h2T2); SYMB(p_xT2, g_xT2);
    SYMB(p_xvT2, g_xvT2); SYMB(p_c2sA2, g_c2sA2); SYMB(p_probsA2, g_probsA2);
    SYMB(p_cmT2, g_cmT2);
    __nv_bfloat16* p_pT2 = p_probsA2;   // alias [CC, 2*NN] (ps-phase lifetime)

    zero_all_kernel<<<NN * HH / 256, 256>>>(p_hidden2, p_hidden1, p_hiddenB, p_colsum,
                                            p_colsum2, p_tmp, p_tmp2, p_rowsC, p_rowsN,
                                            y, b_out);
    xprep_kernel<<<NN, 128>>>(x, p_normx, p_x2);

    // ---- ps branch ----
    {
        dim3 grid(NN / 32, CC / 32), block(32, 8);
        cm_transpose_kernel<<<grid, block>>>(cm, mv, p_cmT2, p_colsum);
    }
    {
        dim3 grid(NN / 32, HH / 32), block(32, 8);
        xT_kernel<<<grid, block>>>(x, mv, p_xT2, p_xvT2);
    }
    launch_mma(p_cmT2, p_xvT2, p_hidden1, CC, HH, 2 * NN, 32, 0, 0, ep_make(EP_ATOM));
    hidden1post_kernel<<<CC, 128>>>(p_hidden1, p_colsum, p_valid1, p_h1b);
    launch_mma(p_h1b, p_x2, p_nc, CC, NN, 3 * HH, 1, HH, HH, ep_make(EP_NONE));
    softmax_split2_kernel<<<CC, 256>>>(p_nc, p_pT2, NN);
    launch_mma(p_pT2, p_xT2, p_hiddenB, CC, HH, 3 * NN, 32, NN, NN, ep_make(EP_ATOM));
    hiddenBpost_kernel<<<CC, 128>>>(p_hiddenB, p_valid1, p_normB, p_hBb);
    {
        dim3 grid(CC / 32, HH / 32), block(32, 8);
        transpose_split2_kernel<<<grid, block>>>(p_hiddenB, p_hBT2, CC);
    }
    {
        EpiParams e = ep_make(EP_EXP3);
        e.normA = p_normx; e.normB = p_normB; e.validf = p_valid1;
        e.out3 = p_c2sA2; e.rowsum = p_rowsC;
        launch_mma(p_x2, p_hBb, p_big, NN, CC, 3 * HH, 1, HH, HH, e);
    }
    launch_mma(p_c2sA2, p_hBT2, p_tmp, NN, HH, 3 * CC, 4, CC, CC, ep_make(EP_ATOM));
    ps_tail_kernel<<<NN / 32, 256, PS_SMEM>>>(p_tmp, p_rowsC, x, W_ps, b_ps, W_psb, b_psb,
                                              W_psf, b_psf, W_out, p_h, p_h2b, p_normh,
                                              p_diag, y);

    // ---- hs branch ----
    {
        EpiParams e = ep_make(EP_TOP3);
        e.normA = p_normh; e.normB = p_normh;
        e.cval = p_cval; e.cidx = p_cidx;
        launch_mma(p_h2b, p_h2b, p_big, NN, NN, 3 * HH, 1, HH, HH, e);
    }
    top3_reduce_scatter<<<NN, 128>>>(p_cval, p_cidx, p_h, p_hidden2, p_colsum2);
    diag_valid_kernel<<<NN, 128>>>(p_colsum2, p_diag, p_h, p_hidden2, p_valid2, p_norm2,
                                   p_h22b);
    {
        dim3 grid(NN / 32, HH / 32), block(32, 8);
        transpose_split2_kernel<<<grid, block>>>(p_hidden2, p_h2T2, NN);
    }
    {
        EpiParams e = ep_make(EP_EXP3);
        e.normA = p_normh; e.normB = p_norm2; e.validf = p_valid2;
        e.out3 = p_probsA2; e.rowsum = p_rowsN;
        launch_mma(p_h2b, p_h22b, p_big, NN, NN, 3 * HH, 1, HH, HH, e);
    }
    launch_mma(p_probsA2, p_h2T2, p_tmp2, NN, HH, 3 * NN, 8, NN, NN, ep_make(EP_ATOM));
    hs_tail_kernel<<<NN / 32, 256, HS_SMEM>>>(p_tmp2, p_rowsN, p_h, W_hs, b_hs, W_hsb, b_hsb,
                                              W_hsf, b_hsf, W_in, b_in, W_out, y);
}